// round 2
// baseline (speedup 1.0000x reference)
#include <cuda_runtime.h>
#include <cstdint>

// ---------------- problem dims ----------------
#define B_   2048
#define F_   267
#define L_   32
#define H_   256
#define E_   8
#define G_   64

// padded K dims (multiples of 16)
#define KP_FC1 544            // 534 -> 544
#define KP_FC2 528            // 523 -> 528
#define KP_ZC  304            // 299 -> 304
#define K_D0   (E_*KP_ZC)     // 2432
#define IN1_   288            // 32 + 256, already /16
#define K_D12  (E_*IN1_)      // 2304
#define NP_W2  320            // 267 -> 320 (N-padded, 5 tiles of 64)

// ---------------- device scratch ----------------
__device__ __align__(16) float g_enc  [B_*KP_FC1];
__device__ __align__(16) float g_h1   [B_*H_];
__device__ __align__(16) float g_h2   [B_*H_];
__device__ __align__(16) float g_mulv [B_*64];
__device__ __align__(16) float g_z    [B_*L_];
__device__ __align__(16) float g_zc   [B_*KP_ZC];
__device__ __align__(16) float g_g0o  [B_*G_];
__device__ __align__(16) float g_g1o  [B_*G_];
__device__ __align__(16) float g_coef [B_*E_];
__device__ __align__(16) float g_aext [B_*K_D0];
__device__ __align__(16) float g_d0   [B_*H_];
__device__ __align__(16) float g_d1   [B_*H_];
// packed weights
__device__ __align__(16) float g_wfc1 [KP_FC1*H_];
__device__ __align__(16) float g_wfc2 [KP_FC2*H_];
__device__ __align__(16) float g_wmulv[KP_FC2*64];
__device__ __align__(16) float g_bmulv[64];
__device__ __align__(16) float g_wg0  [KP_ZC*G_];
__device__ __align__(16) float g_wg1  [G_*G_];
__device__ __align__(16) float g_w0p  [K_D0*H_];
__device__ __align__(16) float g_w2p  [K_D12*NP_W2];

// ---------------- small helpers ----------------
__device__ __forceinline__ float elu1(float v) { return v > 0.f ? v : expm1f(v); }

// ---------------- pack kernels ----------------
// transpose-pack: src is [N,K] row-major (out,in); dst is [Kp,Np] row-major, zero padded
__global__ void packT(float* __restrict__ dst, const float* __restrict__ src,
                      int K, int N, int Kp, int Np) {
    int idx = blockIdx.x * blockDim.x + threadIdx.x;
    if (idx >= Kp * Np) return;
    int k = idx / Np, n = idx % Np;
    dst[idx] = (k < K && n < N) ? src[n * K + k] : 0.f;
}

// mu_w [32,523], lv_w [32,523] -> [528,64]
__global__ void pack_mulvw(float* __restrict__ dst, const float* __restrict__ mu_w,
                           const float* __restrict__ lv_w) {
    int idx = blockIdx.x * blockDim.x + threadIdx.x;
    if (idx >= KP_FC2 * 64) return;
    int k = idx / 64, n = idx % 64;
    float v = 0.f;
    if (k < 523) v = (n < 32) ? mu_w[n * 523 + k] : lv_w[(n - 32) * 523 + k];
    dst[idx] = v;
}
__global__ void pack_bmulv(float* __restrict__ dst, const float* __restrict__ mu_b,
                           const float* __restrict__ lv_b) {
    int n = threadIdx.x;
    if (n < 64) dst[n] = (n < 32) ? mu_b[n] : lv_b[n - 32];
}

// w0 [8,299,256] -> [2432,256] with per-expert K padding 299->304
__global__ void pack_w0(float* __restrict__ dst, const float* __restrict__ w0) {
    int idx = blockIdx.x * blockDim.x + threadIdx.x;
    if (idx >= K_D0 * H_) return;
    int kk = idx / H_, n = idx % H_;
    int e = kk / KP_ZC, i = kk % KP_ZC;
    dst[idx] = (i < 299) ? w0[(e * 299 + i) * H_ + n] : 0.f;
}

// w2 [2304,267] -> [2304,320] N-padded
__global__ void pack_w2(float* __restrict__ dst, const float* __restrict__ w2) {
    int idx = blockIdx.x * blockDim.x + threadIdx.x;
    if (idx >= K_D12 * NP_W2) return;
    int k = idx / NP_W2, n = idx % NP_W2;
    dst[idx] = (n < 267) ? w2[k * 267 + n] : 0.f;
}

// ---------------- concat kernels ----------------
__global__ void cat2(float* __restrict__ dst, int Kp,
                     const float* __restrict__ s1, int l1,
                     const float* __restrict__ s2, int l2) {
    int idx = blockIdx.x * blockDim.x + threadIdx.x;
    if (idx >= B_ * Kp) return;
    int b = idx / Kp, k = idx % Kp;
    float v = 0.f;
    if (k < l1)           v = s1[b * l1 + k];
    else if (k < l1 + l2) v = s2[b * l2 + (k - l1)];
    dst[idx] = v;
}

// ---------------- A_ext builders ----------------
__global__ void build0(float* __restrict__ dst, const float* __restrict__ zc,
                       const float* __restrict__ coeff) {
    int idx = blockIdx.x * blockDim.x + threadIdx.x;
    if (idx >= B_ * K_D0) return;
    int b = idx / K_D0, kk = idx % K_D0;
    int e = kk / KP_ZC, i = kk % KP_ZC;
    dst[idx] = coeff[b * E_ + e] * zc[b * KP_ZC + i];   // zc pad cols are already 0
}

__global__ void build12(float* __restrict__ dst, const float* __restrict__ dsrc,
                        const float* __restrict__ z, const float* __restrict__ coeff) {
    int idx = blockIdx.x * blockDim.x + threadIdx.x;
    if (idx >= B_ * K_D12) return;
    int b = idx / K_D12, kk = idx % K_D12;
    int e = kk / IN1_, i = kk % IN1_;
    float v = (i < L_) ? z[b * L_ + i] : dsrc[b * H_ + (i - L_)];
    dst[idx] = coeff[b * E_ + e] * v;
}

// ---------------- threefry (partitionable) + XLA erfinv ----------------
__device__ __forceinline__ uint32_t rotl32(uint32_t v, int d) { return (v << d) | (v >> (32 - d)); }
__device__ __forceinline__ void tf4(uint32_t& x0, uint32_t& x1, int r0, int r1, int r2, int r3) {
    x0 += x1; x1 = rotl32(x1, r0); x1 ^= x0;
    x0 += x1; x1 = rotl32(x1, r1); x1 ^= x0;
    x0 += x1; x1 = rotl32(x1, r2); x1 ^= x0;
    x0 += x1; x1 = rotl32(x1, r3); x1 ^= x0;
}
__device__ __forceinline__ void threefry2x32(uint32_t k0, uint32_t k1, uint32_t& x0, uint32_t& x1) {
    uint32_t k2 = k0 ^ k1 ^ 0x1BD11BDAu;
    x0 += k0; x1 += k1;
    tf4(x0, x1, 13, 15, 26, 6);  x0 += k1; x1 += k2 + 1u;
    tf4(x0, x1, 17, 29, 16, 24); x0 += k2; x1 += k0 + 2u;
    tf4(x0, x1, 13, 15, 26, 6);  x0 += k0; x1 += k1 + 3u;
    tf4(x0, x1, 17, 29, 16, 24); x0 += k1; x1 += k2 + 4u;
    tf4(x0, x1, 13, 15, 26, 6);  x0 += k2; x1 += k0 + 5u;
}
// XLA f32 ErfInv polynomial
__device__ __forceinline__ float erfinv_xla(float x) {
    float w = -log1pf(-x * x);
    float p;
    if (w < 5.0f) {
        w -= 2.5f;
        p = 2.81022636e-08f;
        p = fmaf(p, w, 3.43273939e-07f);
        p = fmaf(p, w, -3.5233877e-06f);
        p = fmaf(p, w, -4.39150654e-06f);
        p = fmaf(p, w, 0.00021858087f);
        p = fmaf(p, w, -0.00125372503f);
        p = fmaf(p, w, -0.00417768164f);
        p = fmaf(p, w, 0.246640727f);
        p = fmaf(p, w, 1.50140941f);
    } else {
        w = sqrtf(w) - 3.0f;
        p = -0.000200214257f;
        p = fmaf(p, w, 0.000100950558f);
        p = fmaf(p, w, 0.00134934322f);
        p = fmaf(p, w, -0.00367342844f);
        p = fmaf(p, w, 0.00573950773f);
        p = fmaf(p, w, -0.0076224613f);
        p = fmaf(p, w, 0.00943887047f);
        p = fmaf(p, w, 1.00167406f);
        p = fmaf(p, w, 2.83297682f);
    }
    return p * x;
}

// Partitionable threefry (jax_threefry_partitionable=True, default since jax 0.4.36):
// per element i: (x0,x1) = threefry2x32(key, hi(i)=0, lo(i)=i); bits = x0 ^ x1.
__global__ void z_eps_kernel(float* __restrict__ zout, const float* __restrict__ mulv,
                             float* __restrict__ out_mu, float* __restrict__ out_lv) {
    int i = blockIdx.x * blockDim.x + threadIdx.x;
    if (i >= B_ * L_) return;
    uint32_t x0 = 0u, x1 = (uint32_t)i;
    threefry2x32(0u, 42u, x0, x1);    // key(42) -> (0, 42)
    uint32_t bits = x0 ^ x1;
    float f = __uint_as_float((bits >> 9) | 0x3f800000u) - 1.0f;      // [0,1)
    const float lo = -0.99999994f;                                     // nextafter(-1,0)
    float u = fmaxf(lo, fmaf(f, 2.0f, lo));                            // (hi-lo) rounds to 2.0f
    float eps = 1.41421354f * erfinv_xla(u);                           // f32(sqrt(2)) * erfinv
    int b = i >> 5, l = i & 31;
    float mu = mulv[b * 64 + l];
    float lv = mulv[b * 64 + 32 + l];
    zout[i]   = fmaf(eps, expf(0.5f * lv), mu);
    out_mu[i] = mu;
    out_lv[i] = lv;
}

// ---------------- gate final (g2 + softmax) ----------------
__global__ void gate_final(const float* __restrict__ g1o, const float* __restrict__ g2w,
                           const float* __restrict__ g2b, float* __restrict__ coeff) {
    int gtid = blockIdx.x * blockDim.x + threadIdx.x;
    int row = gtid >> 5, lane = gtid & 31;
    if (row >= B_) return;
    float logit = 0.f;
    if (lane < E_) {
        logit = g2b[lane];
        const float* r = g1o + row * G_;
        const float* w = g2w + lane * G_;
        #pragma unroll 8
        for (int k = 0; k < G_; k++) logit = fmaf(r[k], w[k], logit);
    }
    float m = logit;
    for (int d = 4; d > 0; d >>= 1) m = fmaxf(m, __shfl_xor_sync(0xffffffffu, m, d));
    float ex = (lane < E_) ? expf(logit - m) : 0.f;
    float s = ex;
    for (int d = 4; d > 0; d >>= 1) s += __shfl_xor_sync(0xffffffffu, s, d);
    if (lane < E_) coeff[row * E_ + lane] = ex / s;
}

// ---------------- SGEMM: C = act( A[M,K] @ W[K,N] + bias / mixed-bias ) ----------------
// BM=BN=64, BK=16, 256 threads, 4x4 per thread, register prefetch.
__global__ void __launch_bounds__(256) sgemm(
    const float* __restrict__ A, int lda,
    const float* __restrict__ W, int ldw,
    float* __restrict__ C, int ldc, int Nout, int K,
    const float* __restrict__ bias,
    const float* __restrict__ coeff, const float* __restrict__ ebias, int ebld,
    int act)
{
    __shared__ float As[16][68];
    __shared__ float Bs[16][64];
    int tid = threadIdx.x;
    int m0 = blockIdx.y * 64;
    int n0 = blockIdx.x * 64;
    int tx = tid & 15, ty = tid >> 4;
    int arow = tid >> 2, acol = (tid & 3) << 2;
    int brow = tid >> 4, bcol = (tid & 15) << 2;

    const float* Ap = A + (m0 + arow) * lda + acol;
    const float* Wp = W + brow * ldw + n0 + bcol;

    float acc[4][4];
    #pragma unroll
    for (int i = 0; i < 4; i++)
        #pragma unroll
        for (int j = 0; j < 4; j++) acc[i][j] = 0.f;

    float4 av = *(const float4*)Ap;
    float4 bv = *(const float4*)Wp;

    for (int k0 = 0; k0 < K; k0 += 16) {
        As[acol + 0][arow] = av.x;
        As[acol + 1][arow] = av.y;
        As[acol + 2][arow] = av.z;
        As[acol + 3][arow] = av.w;
        *(float4*)&Bs[brow][bcol] = bv;
        __syncthreads();
        if (k0 + 16 < K) {
            av = *(const float4*)(Ap + k0 + 16);
            bv = *(const float4*)(Wp + (k0 + 16) * ldw);
        }
        #pragma unroll
        for (int k = 0; k < 16; k++) {
            float a[4], b[4];
            *(float4*)a = *(const float4*)&As[k][ty << 2];
            *(float4*)b = *(const float4*)&Bs[k][tx << 2];
            #pragma unroll
            for (int i = 0; i < 4; i++)
                #pragma unroll
                for (int j = 0; j < 4; j++)
                    acc[i][j] = fmaf(a[i], b[j], acc[i][j]);
        }
        __syncthreads();
    }

    #pragma unroll
    for (int i = 0; i < 4; i++) {
        int m = m0 + (ty << 2) + i;
        const float* cf = coeff ? (coeff + m * E_) : nullptr;
        #pragma unroll
        for (int j = 0; j < 4; j++) {
            int n = n0 + (tx << 2) + j;
            if (n < Nout) {
                float v = acc[i][j];
                if (bias) v += bias[n];
                if (cf) {
                    float bm = 0.f;
                    #pragma unroll
                    for (int e = 0; e < E_; e++) bm = fmaf(cf[e], ebias[e * ebld + n], bm);
                    v += bm;
                }
                if (act) v = elu1(v);
                C[m * ldc + n] = v;
            }
        }
    }
}

// ---------------- host launch ----------------
static inline void* sym(const void* s) { void* p = nullptr; cudaGetSymbolAddress(&p, s); return p; }

extern "C" void kernel_launch(void* const* d_in, const int* in_sizes, int n_in,
                              void* d_out, int out_size) {
    (void)in_sizes; (void)n_in; (void)out_size;
    const float* x     = (const float*)d_in[0];
    const float* c     = (const float*)d_in[1];
    const float* fc1_w = (const float*)d_in[2];
    const float* fc1_b = (const float*)d_in[3];
    const float* fc2_w = (const float*)d_in[4];
    const float* fc2_b = (const float*)d_in[5];
    const float* mu_w  = (const float*)d_in[6];
    const float* mu_b  = (const float*)d_in[7];
    const float* lv_w  = (const float*)d_in[8];
    const float* lv_b  = (const float*)d_in[9];
    const float* g0_w  = (const float*)d_in[10];
    const float* g0_b  = (const float*)d_in[11];
    const float* g1_w  = (const float*)d_in[12];
    const float* g1_b  = (const float*)d_in[13];
    const float* g2_w  = (const float*)d_in[14];
    const float* g2_b  = (const float*)d_in[15];
    const float* w0    = (const float*)d_in[16];
    const float* b0    = (const float*)d_in[17];
    const float* w1    = (const float*)d_in[18];
    const float* b1    = (const float*)d_in[19];
    const float* w2    = (const float*)d_in[20];
    const float* b2    = (const float*)d_in[21];

    float* out       = (float*)d_out;
    float* out_layer = out;                        // [B, 267]
    float* out_mu    = out + B_ * F_;              // [B, 32]
    float* out_lv    = out + B_ * F_ + B_ * L_;    // [B, 32]

    float* enc   = (float*)sym(g_enc);
    float* h1    = (float*)sym(g_h1);
    float* h2    = (float*)sym(g_h2);
    float* mulv  = (float*)sym(g_mulv);
    float* z     = (float*)sym(g_z);
    float* zc    = (float*)sym(g_zc);
    float* g0o   = (float*)sym(g_g0o);
    float* g1o   = (float*)sym(g_g1o);
    float* coef  = (float*)sym(g_coef);
    float* aext  = (float*)sym(g_aext);
    float* d0    = (float*)sym(g_d0);
    float* d1    = (float*)sym(g_d1);
    float* wfc1  = (float*)sym(g_wfc1);
    float* wfc2  = (float*)sym(g_wfc2);
    float* wmulv = (float*)sym(g_wmulv);
    float* bmulv = (float*)sym(g_bmulv);
    float* wg0   = (float*)sym(g_wg0);
    float* wg1   = (float*)sym(g_wg1);
    float* w0p   = (float*)sym(g_w0p);
    float* w2p   = (float*)sym(g_w2p);

    const int T = 256;
    auto gr = [](int n) { return (n + 255) / 256; };

    // weight packing (independent)
    packT<<<gr(KP_FC1 * H_), T>>>(wfc1, fc1_w, 534, 256, KP_FC1, H_);
    packT<<<gr(KP_FC2 * H_), T>>>(wfc2, fc2_w, 523, 256, KP_FC2, H_);
    pack_mulvw<<<gr(KP_FC2 * 64), T>>>(wmulv, mu_w, lv_w);
    pack_bmulv<<<1, 64>>>(bmulv, mu_b, lv_b);
    packT<<<gr(KP_ZC * G_), T>>>(wg0, g0_w, 299, 64, KP_ZC, G_);
    packT<<<gr(G_ * G_), T>>>(wg1, g1_w, 64, 64, G_, G_);
    pack_w0<<<gr(K_D0 * H_), T>>>(w0p, w0);
    pack_w2<<<gr(K_D12 * NP_W2), T>>>(w2p, w2);

    // encoder
    cat2<<<gr(B_ * KP_FC1), T>>>(enc, KP_FC1, x, 267, c, 267);
    sgemm<<<dim3(4, 32), T>>>(enc, KP_FC1, wfc1, H_, h1, H_, H_, KP_FC1,
                              fc1_b, nullptr, nullptr, 0, 1);
    cat2<<<gr(B_ * KP_FC2), T>>>(enc, KP_FC2, x, 267, h1, 256);
    sgemm<<<dim3(4, 32), T>>>(enc, KP_FC2, wfc2, H_, h2, H_, H_, KP_FC2,
                              fc2_b, nullptr, nullptr, 0, 1);
    cat2<<<gr(B_ * KP_FC2), T>>>(enc, KP_FC2, x, 267, h2, 256);
    sgemm<<<dim3(1, 32), T>>>(enc, KP_FC2, wmulv, 64, mulv, 64, 64, KP_FC2,
                              bmulv, nullptr, nullptr, 0, 0);

    // z = mu + eps * exp(0.5*lv); also emit mu/logvar to output
    z_eps_kernel<<<gr(B_ * L_), T>>>(z, mulv, out_mu, out_lv);

    // gate
    cat2<<<gr(B_ * KP_ZC), T>>>(zc, KP_ZC, z, 32, c, 267);
    sgemm<<<dim3(1, 32), T>>>(zc, KP_ZC, wg0, G_, g0o, G_, G_, KP_ZC,
                              g0_b, nullptr, nullptr, 0, 1);
    sgemm<<<dim3(1, 32), T>>>(g0o, G_, wg1, G_, g1o, G_, G_, G_,
                              g1_b, nullptr, nullptr, 0, 1);
    gate_final<<<gr(B_ * 32), T>>>(g1o, g2_w, g2_b, coef);

    // decoder layer 0
    build0<<<gr(B_ * K_D0), T>>>(aext, zc, coef);
    sgemm<<<dim3(4, 32), T>>>(aext, K_D0, w0p, H_, d0, H_, H_, K_D0,
                              nullptr, coef, b0, 256, 1);
    // decoder layer 1
    build12<<<gr(B_ * K_D12), T>>>(aext, d0, z, coef);
    sgemm<<<dim3(4, 32), T>>>(aext, K_D12, w1, H_, d1, H_, H_, K_D12,
                              nullptr, coef, b1, 256, 1);
    // decoder layer 2 (no activation, ragged N=267)
    build12<<<gr(B_ * K_D12), T>>>(aext, d1, z, coef);
    sgemm<<<dim3(5, 32), T>>>(aext, K_D12, w2p, NP_W2, out_layer, 267, 267, K_D12,
                              nullptr, coef, b2, 267, 0);
}

// round 3
// speedup vs baseline: 1.2539x; 1.2539x over previous
#include <cuda_runtime.h>
#include <cstdint>

// ---------------- problem dims ----------------
#define B_   2048
#define F_   267
#define L_   32
#define H_   256
#define E_   8
#define G_   64

#define KP_FC1 544            // 534 -> 544
#define KP_FC2 528            // 523 -> 528
#define KP_ZC  304            // 299 -> 304
#define K_D0   (E_*KP_ZC)     // 2432
#define IN1_   288            // 32 + 256
#define K_D12  (E_*IN1_)      // 2304
#define NP_W2  320            // 267 -> 320

// ---------------- device scratch ----------------
__device__ __align__(16) float g_enc  [B_*KP_FC1];
__device__ __align__(16) float g_h1   [B_*H_];
__device__ __align__(16) float g_h2   [B_*H_];
__device__ __align__(16) float g_mulv [B_*64];
__device__ __align__(16) float g_z    [B_*L_];
__device__ __align__(16) float g_zc   [B_*KP_ZC];
__device__ __align__(16) float g_g0o  [B_*G_];
__device__ __align__(16) float g_g1o  [B_*G_];
__device__ __align__(16) float g_coef [B_*E_];
__device__ __align__(16) float g_d0   [B_*H_];
__device__ __align__(16) float g_d1   [B_*H_];
// packed weights
__device__ __align__(16) float g_wfc1 [KP_FC1*H_];
__device__ __align__(16) float g_wfc2 [KP_FC2*H_];
__device__ __align__(16) float g_wmulv[KP_FC2*64];
__device__ __align__(16) float g_bmulv[64];
__device__ __align__(16) float g_wg0  [KP_ZC*G_];
__device__ __align__(16) float g_wg1  [G_*G_];
__device__ __align__(16) float g_w0p  [K_D0*H_];
__device__ __align__(16) float g_w2p  [K_D12*NP_W2];

__device__ __forceinline__ float elu1(float v) { return v > 0.f ? v : expm1f(v); }

// ---------------- f32x2 helpers ----------------
__device__ __forceinline__ unsigned long long ff2(unsigned long long a,
                                                  unsigned long long b,
                                                  unsigned long long c) {
    unsigned long long d;
    asm("fma.rn.f32x2 %0, %1, %2, %3;" : "=l"(d) : "l"(a), "l"(b), "l"(c));
    return d;
}
__device__ __forceinline__ unsigned long long dup2(float x) {
    unsigned long long d;
    asm("mov.b64 %0, {%1, %1};" : "=l"(d) : "f"(x));
    return d;
}

// ---------------- single mega-pack kernel ----------------
#define PK0 (KP_FC1*H_)          // wfc1
#define PK1 (KP_FC2*H_)          // wfc2
#define PK2 (KP_FC2*64)          // wmulv
#define PK3 64                   // bmulv
#define PK4 (KP_ZC*G_)           // wg0
#define PK5 (G_*G_)              // wg1
#define PK6 (K_D0*H_)            // w0p
#define PK7 (K_D12*NP_W2)        // w2p
#define PKTOT (PK0+PK1+PK2+PK3+PK4+PK5+PK6+PK7)

__global__ void pack_all(const float* __restrict__ fc1_w, const float* __restrict__ fc2_w,
                         const float* __restrict__ mu_w, const float* __restrict__ mu_b,
                         const float* __restrict__ lv_w, const float* __restrict__ lv_b,
                         const float* __restrict__ g0_w, const float* __restrict__ g1_w,
                         const float* __restrict__ w0,   const float* __restrict__ w2,
                         float* __restrict__ wfc1, float* __restrict__ wfc2,
                         float* __restrict__ wmulv, float* __restrict__ bmulv,
                         float* __restrict__ wg0, float* __restrict__ wg1,
                         float* __restrict__ w0p, float* __restrict__ w2p) {
    int idx = blockIdx.x * blockDim.x + threadIdx.x;
    if (idx >= PKTOT) return;
    if (idx < PK0) {                                    // fc1_w [256,534] -> [544,256]
        int k = idx / H_, n = idx % H_;
        wfc1[idx] = (k < 534) ? fc1_w[n * 534 + k] : 0.f;
        return;
    } idx -= PK0;
    if (idx < PK1) {                                    // fc2_w [256,523] -> [528,256]
        int k = idx / H_, n = idx % H_;
        wfc2[idx] = (k < 523) ? fc2_w[n * 523 + k] : 0.f;
        return;
    } idx -= PK1;
    if (idx < PK2) {                                    // mu/lv [32,523] -> [528,64]
        int k = idx / 64, n = idx % 64;
        float v = 0.f;
        if (k < 523) v = (n < 32) ? mu_w[n * 523 + k] : lv_w[(n - 32) * 523 + k];
        wmulv[idx] = v;
        return;
    } idx -= PK2;
    if (idx < PK3) {
        bmulv[idx] = (idx < 32) ? mu_b[idx] : lv_b[idx - 32];
        return;
    } idx -= PK3;
    if (idx < PK4) {                                    // g0_w [64,299] -> [304,64]
        int k = idx / G_, n = idx % G_;
        wg0[idx] = (k < 299) ? g0_w[n * 299 + k] : 0.f;
        return;
    } idx -= PK4;
    if (idx < PK5) {                                    // g1_w [64,64] -> T
        int k = idx / G_, n = idx % G_;
        wg1[idx] = g1_w[n * G_ + k];
        return;
    } idx -= PK5;
    if (idx < PK6) {                                    // w0 [8,299,256] -> [2432,256]
        int kk = idx / H_, n = idx % H_;
        int e = kk / KP_ZC, i = kk % KP_ZC;
        w0p[idx] = (i < 299) ? w0[(e * 299 + i) * H_ + n] : 0.f;
        return;
    } idx -= PK6;
    {                                                   // w2 [2304,267] -> [2304,320]
        int k = idx / NP_W2, n = idx % NP_W2;
        w2p[idx] = (n < 267) ? w2[k * 267 + n] : 0.f;
    }
}

// ---------------- concat / fill kernels ----------------
__global__ void cat2(float* __restrict__ dst, int Kp,
                     const float* __restrict__ s1, int l1,
                     const float* __restrict__ s2, int l2) {
    int idx = blockIdx.x * blockDim.x + threadIdx.x;
    if (idx >= B_ * Kp) return;
    int b = idx / Kp, k = idx % Kp;
    float v = 0.f;
    if (k < l1)           v = s1[b * l1 + k];
    else if (k < l1 + l2) v = s2[b * l2 + (k - l1)];
    dst[idx] = v;
}

// fill zc[:, 32:304] from c (independent of z) with zero pad cols 299..303
__global__ void zc_fill_c(float* __restrict__ zc, const float* __restrict__ c) {
    int idx = blockIdx.x * blockDim.x + threadIdx.x;
    if (idx >= B_ * 272) return;
    int b = idx / 272, k = 32 + idx % 272;
    zc[b * KP_ZC + k] = (k < 299) ? c[b * 267 + (k - 32)] : 0.f;
}

// ---------------- threefry (partitionable) + XLA erfinv ----------------
__device__ __forceinline__ uint32_t rotl32(uint32_t v, int d) { return (v << d) | (v >> (32 - d)); }
__device__ __forceinline__ void tf4(uint32_t& x0, uint32_t& x1, int r0, int r1, int r2, int r3) {
    x0 += x1; x1 = rotl32(x1, r0); x1 ^= x0;
    x0 += x1; x1 = rotl32(x1, r1); x1 ^= x0;
    x0 += x1; x1 = rotl32(x1, r2); x1 ^= x0;
    x0 += x1; x1 = rotl32(x1, r3); x1 ^= x0;
}
__device__ __forceinline__ void threefry2x32(uint32_t k0, uint32_t k1, uint32_t& x0, uint32_t& x1) {
    uint32_t k2 = k0 ^ k1 ^ 0x1BD11BDAu;
    x0 += k0; x1 += k1;
    tf4(x0, x1, 13, 15, 26, 6);  x0 += k1; x1 += k2 + 1u;
    tf4(x0, x1, 17, 29, 16, 24); x0 += k2; x1 += k0 + 2u;
    tf4(x0, x1, 13, 15, 26, 6);  x0 += k0; x1 += k1 + 3u;
    tf4(x0, x1, 17, 29, 16, 24); x0 += k1; x1 += k2 + 4u;
    tf4(x0, x1, 13, 15, 26, 6);  x0 += k2; x1 += k0 + 5u;
}
__device__ __forceinline__ float erfinv_xla(float x) {
    float w = -log1pf(-x * x);
    float p;
    if (w < 5.0f) {
        w -= 2.5f;
        p = 2.81022636e-08f;
        p = fmaf(p, w, 3.43273939e-07f);
        p = fmaf(p, w, -3.5233877e-06f);
        p = fmaf(p, w, -4.39150654e-06f);
        p = fmaf(p, w, 0.00021858087f);
        p = fmaf(p, w, -0.00125372503f);
        p = fmaf(p, w, -0.00417768164f);
        p = fmaf(p, w, 0.246640727f);
        p = fmaf(p, w, 1.50140941f);
    } else {
        w = sqrtf(w) - 3.0f;
        p = -0.000200214257f;
        p = fmaf(p, w, 0.000100950558f);
        p = fmaf(p, w, 0.00134934322f);
        p = fmaf(p, w, -0.00367342844f);
        p = fmaf(p, w, 0.00573950773f);
        p = fmaf(p, w, -0.0076224613f);
        p = fmaf(p, w, 0.00943887047f);
        p = fmaf(p, w, 1.00167406f);
        p = fmaf(p, w, 2.83297682f);
    }
    return p * x;
}

// partitionable threefry; writes z, zc[:, :32], mu, logvar
__global__ void z_eps_kernel(float* __restrict__ zout, float* __restrict__ zc,
                             const float* __restrict__ mulv,
                             float* __restrict__ out_mu, float* __restrict__ out_lv) {
    int i = blockIdx.x * blockDim.x + threadIdx.x;
    if (i >= B_ * L_) return;
    uint32_t x0 = 0u, x1 = (uint32_t)i;
    threefry2x32(0u, 42u, x0, x1);
    uint32_t bits = x0 ^ x1;
    float f = __uint_as_float((bits >> 9) | 0x3f800000u) - 1.0f;
    const float lo = -0.99999994f;
    float u = fmaxf(lo, fmaf(f, 2.0f, lo));
    float eps = 1.41421354f * erfinv_xla(u);
    int b = i >> 5, l = i & 31;
    float mu = mulv[b * 64 + l];
    float lv = mulv[b * 64 + 32 + l];
    float zv = fmaf(eps, expf(0.5f * lv), mu);
    zout[i] = zv;
    zc[b * KP_ZC + l] = zv;
    out_mu[i] = mu;
    out_lv[i] = lv;
}

// ---------------- gate final (g2 + softmax) ----------------
__global__ void gate_final(const float* __restrict__ g1o, const float* __restrict__ g2w,
                           const float* __restrict__ g2b, float* __restrict__ coeff) {
    int gtid = blockIdx.x * blockDim.x + threadIdx.x;
    int row = gtid >> 5, lane = gtid & 31;
    if (row >= B_) return;
    float logit = 0.f;
    if (lane < E_) {
        logit = g2b[lane];
        const float* r = g1o + row * G_;
        const float* w = g2w + lane * G_;
        #pragma unroll 8
        for (int k = 0; k < G_; k++) logit = fmaf(r[k], w[k], logit);
    }
    float m = logit;
    for (int d = 4; d > 0; d >>= 1) m = fmaxf(m, __shfl_xor_sync(0xffffffffu, m, d));
    float ex = (lane < E_) ? expf(logit - m) : 0.f;
    float s = ex;
    for (int d = 4; d > 0; d >>= 1) s += __shfl_xor_sync(0xffffffffu, s, d);
    if (lane < E_) coeff[row * E_ + lane] = ex / s;
}

// ---------------- A loaders (MODE) ----------------
// MODE 0: plain A[m, kk] (lda)
// MODE 1: coeff[m,e] * zc[m, kk%304]       (e = kk/304)   decoder layer 0
// MODE 2: coeff[m,e] * (z|d)[m, kk%288]    (e = kk/288)   decoder layers 1,2
template <int MODE>
__device__ __forceinline__ float4 loadA(const float* __restrict__ A, int lda,
                                        const float* __restrict__ z,
                                        const float* __restrict__ coeff,
                                        int m, int kk) {
    if (MODE == 0) {
        return *(const float4*)(A + (size_t)m * lda + kk);
    } else if (MODE == 1) {
        int e = kk / KP_ZC, i = kk - e * KP_ZC;
        float s = coeff[m * E_ + e];
        float4 v = *(const float4*)(A + m * KP_ZC + i);
        v.x *= s; v.y *= s; v.z *= s; v.w *= s;
        return v;
    } else {
        int e = kk / IN1_, i = kk - e * IN1_;
        float s = coeff[m * E_ + e];
        float4 v = (i < L_) ? *(const float4*)(z + m * L_ + i)
                            : *(const float4*)(A + m * H_ + (i - L_));
        v.x *= s; v.y *= s; v.z *= s; v.w *= s;
        return v;
    }
}

// ---------------- SGEMM with f32x2 FMA, double-buffered smem ----------------
// BM=BN=64, BK=16, 256 threads, 4x4 microtile (acc paired over m).
template <int MODE>
__global__ void __launch_bounds__(256) gemm2(
    const float* __restrict__ A, int lda,
    const float* __restrict__ z,
    const float* __restrict__ coeff,
    const float* __restrict__ W, int ldw,
    float* __restrict__ C, int ldc, int Nout, int K,
    const float* __restrict__ bias,
    const float* __restrict__ ebias, int ebld,
    int act)
{
    __shared__ __align__(16) float As[2][16][68];
    __shared__ __align__(16) float Bs[2][16][64];

    int tid = threadIdx.x;
    int m0 = blockIdx.y * 64;
    int n0 = blockIdx.x * 64;
    int tx = tid & 15, ty = tid >> 4;
    int arow = tid >> 2, acol = (tid & 3) << 2;
    int brow = tid >> 4, bcol = (tid & 15) << 2;

    const float* Wp = W + (size_t)brow * ldw + n0 + bcol;
    int am = m0 + arow;

    unsigned long long acc[2][4];
    #pragma unroll
    for (int p = 0; p < 2; p++)
        #pragma unroll
        for (int j = 0; j < 4; j++) acc[p][j] = 0ull;

    int ntiles = K >> 4;
    float4 av = loadA<MODE>(A, lda, z, coeff, am, acol);
    float4 bv = *(const float4*)Wp;

    // store tile 0 into buf 0
    As[0][acol + 0][arow] = av.x;
    As[0][acol + 1][arow] = av.y;
    As[0][acol + 2][arow] = av.z;
    As[0][acol + 3][arow] = av.w;
    *(float4*)&Bs[0][brow][bcol] = bv;
    __syncthreads();

    for (int t = 0; t < ntiles; t++) {
        int buf = t & 1;
        bool more = (t + 1) < ntiles;
        if (more) {
            int kk = ((t + 1) << 4) + acol;
            av = loadA<MODE>(A, lda, z, coeff, am, kk);
            bv = *(const float4*)(Wp + (size_t)((t + 1) << 4) * ldw);
        }
        #pragma unroll
        for (int k = 0; k < 16; k++) {
            ulonglong2 ap = *(const ulonglong2*)&As[buf][k][ty << 2];
            float4 b4 = *(const float4*)&Bs[buf][k][tx << 2];
            unsigned long long bd0 = dup2(b4.x);
            unsigned long long bd1 = dup2(b4.y);
            unsigned long long bd2 = dup2(b4.z);
            unsigned long long bd3 = dup2(b4.w);
            acc[0][0] = ff2(ap.x, bd0, acc[0][0]);
            acc[0][1] = ff2(ap.x, bd1, acc[0][1]);
            acc[0][2] = ff2(ap.x, bd2, acc[0][2]);
            acc[0][3] = ff2(ap.x, bd3, acc[0][3]);
            acc[1][0] = ff2(ap.y, bd0, acc[1][0]);
            acc[1][1] = ff2(ap.y, bd1, acc[1][1]);
            acc[1][2] = ff2(ap.y, bd2, acc[1][2]);
            acc[1][3] = ff2(ap.y, bd3, acc[1][3]);
        }
        if (more) {
            int nb = buf ^ 1;
            As[nb][acol + 0][arow] = av.x;
            As[nb][acol + 1][arow] = av.y;
            As[nb][acol + 2][arow] = av.z;
            As[nb][acol + 3][arow] = av.w;
            *(float4*)&Bs[nb][brow][bcol] = bv;
        }
        __syncthreads();
    }

    // unpack: pair p covers rows (ty*4 + 2p, ty*4 + 2p + 1)
    float cres[4][4];
    #pragma unroll
    for (int p = 0; p < 2; p++)
        #pragma unroll
        for (int j = 0; j < 4; j++) {
            float lo, hi;
            asm("mov.b64 {%0, %1}, %2;" : "=f"(lo), "=f"(hi) : "l"(acc[p][j]));
            cres[2 * p][j] = lo;
            cres[2 * p + 1][j] = hi;
        }

    #pragma unroll
    for (int i = 0; i < 4; i++) {
        int m = m0 + (ty << 2) + i;
        const float* cf = ebias ? (coeff + m * E_) : nullptr;
        #pragma unroll
        for (int j = 0; j < 4; j++) {
            int n = n0 + (tx << 2) + j;
            if (n < Nout) {
                float v = cres[i][j];
                if (bias) v += bias[n];
                if (cf) {
                    float bm = 0.f;
                    #pragma unroll
                    for (int e = 0; e < E_; e++) bm = fmaf(cf[e], ebias[e * ebld + n], bm);
                    v += bm;
                }
                if (act) v = elu1(v);
                C[(size_t)m * ldc + n] = v;
            }
        }
    }
}

// ---------------- host launch ----------------
static inline void* sym(const void* s) { void* p = nullptr; cudaGetSymbolAddress(&p, s); return p; }

extern "C" void kernel_launch(void* const* d_in, const int* in_sizes, int n_in,
                              void* d_out, int out_size) {
    (void)in_sizes; (void)n_in; (void)out_size;
    const float* x     = (const float*)d_in[0];
    const float* c     = (const float*)d_in[1];
    const float* fc1_w = (const float*)d_in[2];
    const float* fc1_b = (const float*)d_in[3];
    const float* fc2_w = (const float*)d_in[4];
    const float* fc2_b = (const float*)d_in[5];
    const float* mu_w  = (const float*)d_in[6];
    const float* mu_b  = (const float*)d_in[7];
    const float* lv_w  = (const float*)d_in[8];
    const float* lv_b  = (const float*)d_in[9];
    const float* g0_w  = (const float*)d_in[10];
    const float* g0_b  = (const float*)d_in[11];
    const float* g1_w  = (const float*)d_in[12];
    const float* g1_b  = (const float*)d_in[13];
    const float* g2_w  = (const float*)d_in[14];
    const float* g2_b  = (const float*)d_in[15];
    const float* w0    = (const float*)d_in[16];
    const float* b0    = (const float*)d_in[17];
    const float* w1    = (const float*)d_in[18];
    const float* b1    = (const float*)d_in[19];
    const float* w2    = (const float*)d_in[20];
    const float* b2    = (const float*)d_in[21];

    float* out       = (float*)d_out;
    float* out_layer = out;
    float* out_mu    = out + B_ * F_;
    float* out_lv    = out + B_ * F_ + B_ * L_;

    float* enc   = (float*)sym(g_enc);
    float* h1    = (float*)sym(g_h1);
    float* h2    = (float*)sym(g_h2);
    float* mulv  = (float*)sym(g_mulv);
    float* z     = (float*)sym(g_z);
    float* zc    = (float*)sym(g_zc);
    float* g0o   = (float*)sym(g_g0o);
    float* g1o   = (float*)sym(g_g1o);
    float* coef  = (float*)sym(g_coef);
    float* d0    = (float*)sym(g_d0);
    float* d1    = (float*)sym(g_d1);
    float* wfc1  = (float*)sym(g_wfc1);
    float* wfc2  = (float*)sym(g_wfc2);
    float* wmulv = (float*)sym(g_wmulv);
    float* bmulv = (float*)sym(g_bmulv);
    float* wg0   = (float*)sym(g_wg0);
    float* wg1   = (float*)sym(g_wg1);
    float* w0p   = (float*)sym(g_w0p);
    float* w2p   = (float*)sym(g_w2p);

    const int T = 256;
    auto gr = [](int n) { return (n + 255) / 256; };

    // all weight packing in one launch; zc's c-half early (both independent)
    pack_all<<<gr(PKTOT), T>>>(fc1_w, fc2_w, mu_w, mu_b, lv_w, lv_b, g0_w, g1_w, w0, w2,
                               wfc1, wfc2, wmulv, bmulv, wg0, wg1, w0p, w2p);
    zc_fill_c<<<gr(B_ * 272), T>>>(zc, c);

    // encoder
    cat2<<<gr(B_ * KP_FC1), T>>>(enc, KP_FC1, x, 267, c, 267);
    gemm2<0><<<dim3(4, 32), T>>>(enc, KP_FC1, nullptr, nullptr, wfc1, H_,
                                 h1, H_, H_, KP_FC1, fc1_b, nullptr, 0, 1);
    cat2<<<gr(B_ * KP_FC2), T>>>(enc, KP_FC2, x, 267, h1, 256);
    gemm2<0><<<dim3(4, 32), T>>>(enc, KP_FC2, nullptr, nullptr, wfc2, H_,
                                 h2, H_, H_, KP_FC2, fc2_b, nullptr, 0, 1);
    cat2<<<gr(B_ * KP_FC2), T>>>(enc, KP_FC2, x, 267, h2, 256);
    gemm2<0><<<dim3(1, 32), T>>>(enc, KP_FC2, nullptr, nullptr, wmulv, 64,
                                 mulv, 64, 64, KP_FC2, bmulv, nullptr, 0, 0);

    // z (also fills zc[:, :32]), mu/logvar outputs
    z_eps_kernel<<<gr(B_ * L_), T>>>(z, zc, mulv, out_mu, out_lv);

    // gate
    gemm2<0><<<dim3(1, 32), T>>>(zc, KP_ZC, nullptr, nullptr, wg0, G_,
                                 g0o, G_, G_, KP_ZC, g0_b, nullptr, 0, 1);
    gemm2<0><<<dim3(1, 32), T>>>(g0o, G_, nullptr, nullptr, wg1, G_,
                                 g1o, G_, G_, G_, g1_b, nullptr, 0, 1);
    gate_final<<<gr(B_ * 32), T>>>(g1o, g2_w, g2_b, coef);

    // decoder: A built on-the-fly inside the GEMM (coeff * src)
    gemm2<1><<<dim3(4, 32), T>>>(zc, KP_ZC, nullptr, coef, w0p, H_,
                                 d0, H_, H_, K_D0, nullptr, b0, 256, 1);
    gemm2<2><<<dim3(4, 32), T>>>(d0, H_, z, coef, w1, H_,
                                 d1, H_, H_, K_D12, nullptr, b1, 256, 1);
    gemm2<2><<<dim3(5, 32), T>>>(d1, H_, z, coef, w2p, NP_W2,
                                 out_layer, 267, 267, K_D12, nullptr, b2, 267, 0);
}

// round 4
// speedup vs baseline: 1.7252x; 1.3759x over previous
#include <cuda_runtime.h>
#include <cstdint>

// ---------------- problem dims ----------------
#define B_   2048
#define F_   267
#define L_   32
#define H_   256
#define E_   8
#define G_   64

#define KP_FC1 544            // 534 -> 544 (34 tiles)
#define KP_FC2 528            // 523 -> 528 (33 tiles)
#define KP_ZC  304            // 299 -> 304 (19 tiles)
#define K_D0   (E_*KP_ZC)     // 2432 (152 tiles)
#define IN1_   288            // 32 + 256
#define K_D12  (E_*IN1_)      // 2304 (144 tiles)
#define NP_W2  320            // 267 -> 320

// ---------------- device scratch ----------------
__device__ __align__(16) float g_enc  [B_*KP_FC1];
__device__ __align__(16) float g_h1   [B_*H_];
__device__ __align__(16) float g_h2   [B_*H_];
__device__ __align__(16) float g_mulv [B_*64];
__device__ __align__(16) float g_z    [B_*L_];
__device__ __align__(16) float g_zc   [B_*KP_ZC];
__device__ __align__(16) float g_g0o  [B_*G_];
__device__ __align__(16) float g_g1o  [B_*G_];
__device__ __align__(16) float g_coef [B_*E_];
__device__ __align__(16) float g_d0   [B_*H_];
__device__ __align__(16) float g_d1   [B_*H_];
__device__ __align__(16) float g_part [4*B_*NP_W2];     // split-K partials (10.5 MB)
// packed weights
__device__ __align__(16) float g_wfc1 [KP_FC1*H_];
__device__ __align__(16) float g_wfc2 [KP_FC2*H_];
__device__ __align__(16) float g_wmulv[KP_FC2*64];
__device__ __align__(16) float g_bmulv[64];
__device__ __align__(16) float g_wg0  [KP_ZC*G_];
__device__ __align__(16) float g_wg1  [G_*G_];
__device__ __align__(16) float g_w0p  [K_D0*H_];
__device__ __align__(16) float g_w2p  [K_D12*NP_W2];

__device__ __forceinline__ float elu1(float v) { return v > 0.f ? v : expm1f(v); }

// ---------------- f32x2 helpers ----------------
__device__ __forceinline__ unsigned long long ff2(unsigned long long a,
                                                  unsigned long long b,
                                                  unsigned long long c) {
    unsigned long long d;
    asm("fma.rn.f32x2 %0, %1, %2, %3;" : "=l"(d) : "l"(a), "l"(b), "l"(c));
    return d;
}
__device__ __forceinline__ unsigned long long dup2(float x) {
    unsigned long long d;
    asm("mov.b64 %0, {%1, %1};" : "=l"(d) : "f"(x));
    return d;
}

// ---------------- single mega-pack kernel ----------------
#define PK0 (KP_FC1*H_)
#define PK1 (KP_FC2*H_)
#define PK2 (KP_FC2*64)
#define PK3 64
#define PK4 (KP_ZC*G_)
#define PK5 (G_*G_)
#define PK6 (K_D0*H_)
#define PK7 (K_D12*NP_W2)
#define PKTOT (PK0+PK1+PK2+PK3+PK4+PK5+PK6+PK7)

__global__ void pack_all(const float* __restrict__ fc1_w, const float* __restrict__ fc2_w,
                         const float* __restrict__ mu_w, const float* __restrict__ mu_b,
                         const float* __restrict__ lv_w, const float* __restrict__ lv_b,
                         const float* __restrict__ g0_w, const float* __restrict__ g1_w,
                         const float* __restrict__ w0,   const float* __restrict__ w2,
                         float* __restrict__ wfc1, float* __restrict__ wfc2,
                         float* __restrict__ wmulv, float* __restrict__ bmulv,
                         float* __restrict__ wg0, float* __restrict__ wg1,
                         float* __restrict__ w0p, float* __restrict__ w2p) {
    int idx = blockIdx.x * blockDim.x + threadIdx.x;
    if (idx >= PKTOT) return;
    if (idx < PK0) {
        int k = idx / H_, n = idx % H_;
        wfc1[idx] = (k < 534) ? fc1_w[n * 534 + k] : 0.f;
        return;
    } idx -= PK0;
    if (idx < PK1) {
        int k = idx / H_, n = idx % H_;
        wfc2[idx] = (k < 523) ? fc2_w[n * 523 + k] : 0.f;
        return;
    } idx -= PK1;
    if (idx < PK2) {
        int k = idx / 64, n = idx % 64;
        float v = 0.f;
        if (k < 523) v = (n < 32) ? mu_w[n * 523 + k] : lv_w[(n - 32) * 523 + k];
        wmulv[idx] = v;
        return;
    } idx -= PK2;
    if (idx < PK3) {
        bmulv[idx] = (idx < 32) ? mu_b[idx] : lv_b[idx - 32];
        return;
    } idx -= PK3;
    if (idx < PK4) {
        int k = idx / G_, n = idx % G_;
        wg0[idx] = (k < 299) ? g0_w[n * 299 + k] : 0.f;
        return;
    } idx -= PK4;
    if (idx < PK5) {
        int k = idx / G_, n = idx % G_;
        wg1[idx] = g1_w[n * G_ + k];
        return;
    } idx -= PK5;
    if (idx < PK6) {
        int kk = idx / H_, n = idx % H_;
        int e = kk / KP_ZC, i = kk % KP_ZC;
        w0p[idx] = (i < 299) ? w0[(e * 299 + i) * H_ + n] : 0.f;
        return;
    } idx -= PK6;
    {
        int k = idx / NP_W2, n = idx % NP_W2;
        w2p[idx] = (n < 267) ? w2[k * 267 + n] : 0.f;
    }
}

// ---------------- concat / fill kernels ----------------
__global__ void cat2(float* __restrict__ dst, int Kp,
                     const float* __restrict__ s1, int l1,
                     const float* __restrict__ s2, int l2) {
    int idx = blockIdx.x * blockDim.x + threadIdx.x;
    if (idx >= B_ * Kp) return;
    int b = idx / Kp, k = idx % Kp;
    float v = 0.f;
    if (k < l1)           v = s1[b * l1 + k];
    else if (k < l1 + l2) v = s2[b * l2 + (k - l1)];
    dst[idx] = v;
}

__global__ void zc_fill_c(float* __restrict__ zc, const float* __restrict__ c) {
    int idx = blockIdx.x * blockDim.x + threadIdx.x;
    if (idx >= B_ * 272) return;
    int b = idx / 272, k = 32 + idx % 272;
    zc[b * KP_ZC + k] = (k < 299) ? c[b * 267 + (k - 32)] : 0.f;
}

// ---------------- threefry (partitionable) + XLA erfinv ----------------
__device__ __forceinline__ uint32_t rotl32(uint32_t v, int d) { return (v << d) | (v >> (32 - d)); }
__device__ __forceinline__ void tf4(uint32_t& x0, uint32_t& x1, int r0, int r1, int r2, int r3) {
    x0 += x1; x1 = rotl32(x1, r0); x1 ^= x0;
    x0 += x1; x1 = rotl32(x1, r1); x1 ^= x0;
    x0 += x1; x1 = rotl32(x1, r2); x1 ^= x0;
    x0 += x1; x1 = rotl32(x1, r3); x1 ^= x0;
}
__device__ __forceinline__ void threefry2x32(uint32_t k0, uint32_t k1, uint32_t& x0, uint32_t& x1) {
    uint32_t k2 = k0 ^ k1 ^ 0x1BD11BDAu;
    x0 += k0; x1 += k1;
    tf4(x0, x1, 13, 15, 26, 6);  x0 += k1; x1 += k2 + 1u;
    tf4(x0, x1, 17, 29, 16, 24); x0 += k2; x1 += k0 + 2u;
    tf4(x0, x1, 13, 15, 26, 6);  x0 += k0; x1 += k1 + 3u;
    tf4(x0, x1, 17, 29, 16, 24); x0 += k1; x1 += k2 + 4u;
    tf4(x0, x1, 13, 15, 26, 6);  x0 += k2; x1 += k0 + 5u;
}
__device__ __forceinline__ float erfinv_xla(float x) {
    float w = -log1pf(-x * x);
    float p;
    if (w < 5.0f) {
        w -= 2.5f;
        p = 2.81022636e-08f;
        p = fmaf(p, w, 3.43273939e-07f);
        p = fmaf(p, w, -3.5233877e-06f);
        p = fmaf(p, w, -4.39150654e-06f);
        p = fmaf(p, w, 0.00021858087f);
        p = fmaf(p, w, -0.00125372503f);
        p = fmaf(p, w, -0.00417768164f);
        p = fmaf(p, w, 0.246640727f);
        p = fmaf(p, w, 1.50140941f);
    } else {
        w = sqrtf(w) - 3.0f;
        p = -0.000200214257f;
        p = fmaf(p, w, 0.000100950558f);
        p = fmaf(p, w, 0.00134934322f);
        p = fmaf(p, w, -0.00367342844f);
        p = fmaf(p, w, 0.00573950773f);
        p = fmaf(p, w, -0.0076224613f);
        p = fmaf(p, w, 0.00943887047f);
        p = fmaf(p, w, 1.00167406f);
        p = fmaf(p, w, 2.83297682f);
    }
    return p * x;
}

__global__ void z_eps_kernel(float* __restrict__ zout, float* __restrict__ zc,
                             const float* __restrict__ mulv,
                             float* __restrict__ out_mu, float* __restrict__ out_lv) {
    int i = blockIdx.x * blockDim.x + threadIdx.x;
    if (i >= B_ * L_) return;
    uint32_t x0 = 0u, x1 = (uint32_t)i;
    threefry2x32(0u, 42u, x0, x1);
    uint32_t bits = x0 ^ x1;
    float f = __uint_as_float((bits >> 9) | 0x3f800000u) - 1.0f;
    const float lo = -0.99999994f;
    float u = fmaxf(lo, fmaf(f, 2.0f, lo));
    float eps = 1.41421354f * erfinv_xla(u);
    int b = i >> 5, l = i & 31;
    float mu = mulv[b * 64 + l];
    float lv = mulv[b * 64 + 32 + l];
    float zv = fmaf(eps, expf(0.5f * lv), mu);
    zout[i] = zv;
    zc[b * KP_ZC + l] = zv;
    out_mu[i] = mu;
    out_lv[i] = lv;
}

// ---------------- gate final (g2 + softmax) ----------------
__global__ void gate_final(const float* __restrict__ g1o, const float* __restrict__ g2w,
                           const float* __restrict__ g2b, float* __restrict__ coeff) {
    int gtid = blockIdx.x * blockDim.x + threadIdx.x;
    int row = gtid >> 5, lane = gtid & 31;
    if (row >= B_) return;
    float logit = 0.f;
    if (lane < E_) {
        logit = g2b[lane];
        const float* r = g1o + row * G_;
        const float* w = g2w + lane * G_;
        #pragma unroll 8
        for (int k = 0; k < G_; k++) logit = fmaf(r[k], w[k], logit);
    }
    float m = logit;
    for (int d = 4; d > 0; d >>= 1) m = fmaxf(m, __shfl_xor_sync(0xffffffffu, m, d));
    float ex = (lane < E_) ? expf(logit - m) : 0.f;
    float s = ex;
    for (int d = 4; d > 0; d >>= 1) s += __shfl_xor_sync(0xffffffffu, s, d);
    if (lane < E_) coeff[row * E_ + lane] = ex / s;
}

// ---------------- A loaders (MODE) ----------------
template <int MODE>
__device__ __forceinline__ float4 loadA(const float* __restrict__ A, int lda,
                                        const float* __restrict__ z,
                                        const float* __restrict__ coeff,
                                        int m, int kk) {
    if (MODE == 0) {
        return *(const float4*)(A + (size_t)m * lda + kk);
    } else if (MODE == 1) {
        int e = kk / KP_ZC, i = kk - e * KP_ZC;
        float s = coeff[m * E_ + e];
        float4 v = *(const float4*)(A + m * KP_ZC + i);
        v.x *= s; v.y *= s; v.z *= s; v.w *= s;
        return v;
    } else {
        int e = kk / IN1_, i = kk - e * IN1_;
        float s = coeff[m * E_ + e];
        float4 v = (i < L_) ? *(const float4*)(z + m * L_ + i)
                            : *(const float4*)(A + m * H_ + (i - L_));
        v.x *= s; v.y *= s; v.z *= s; v.w *= s;
        return v;
    }
}

// ---------------- SGEMM with f32x2 FMA, double-buffered smem, split-K ----------------
// grid = (nTiles, mTiles, S); CTA z handles k-tiles [z*ktPer, min(ktTot, (z+1)*ktPer))
// and writes to C + z*sliceStride.
template <int MODE>
__global__ void __launch_bounds__(256) gemm2(
    const float* __restrict__ A, int lda,
    const float* __restrict__ z,
    const float* __restrict__ coeff,
    const float* __restrict__ W, int ldw,
    float* __restrict__ C, int ldc, long sliceStride, int Nout,
    int ktTot, int ktPer,
    const float* __restrict__ bias,
    const float* __restrict__ ebias, int ebld,
    int act)
{
    __shared__ __align__(16) float As[2][16][68];
    __shared__ __align__(16) float Bs[2][16][64];

    int tid = threadIdx.x;
    int m0 = blockIdx.y * 64;
    int n0 = blockIdx.x * 64;
    int kt0 = blockIdx.z * ktPer;
    int ktn = min(ktPer, ktTot - kt0);
    float* Cp = C + (long)blockIdx.z * sliceStride;

    int tx = tid & 15, ty = tid >> 4;
    int arow = tid >> 2, acol = (tid & 3) << 2;
    int brow = tid >> 4, bcol = (tid & 15) << 2;

    const float* Wp = W + (size_t)brow * ldw + n0 + bcol;
    int am = m0 + arow;

    unsigned long long acc[2][4];
    #pragma unroll
    for (int p = 0; p < 2; p++)
        #pragma unroll
        for (int j = 0; j < 4; j++) acc[p][j] = 0ull;

    float4 av = loadA<MODE>(A, lda, z, coeff, am, (kt0 << 4) + acol);
    float4 bv = *(const float4*)(Wp + (size_t)(kt0 << 4) * ldw);

    As[0][acol + 0][arow] = av.x;
    As[0][acol + 1][arow] = av.y;
    As[0][acol + 2][arow] = av.z;
    As[0][acol + 3][arow] = av.w;
    *(float4*)&Bs[0][brow][bcol] = bv;
    __syncthreads();

    for (int t = 0; t < ktn; t++) {
        int buf = t & 1;
        bool more = (t + 1) < ktn;
        if (more) {
            int kk = ((kt0 + t + 1) << 4);
            av = loadA<MODE>(A, lda, z, coeff, am, kk + acol);
            bv = *(const float4*)(Wp + (size_t)kk * ldw);
        }
        #pragma unroll
        for (int k = 0; k < 16; k++) {
            ulonglong2 ap = *(const ulonglong2*)&As[buf][k][ty << 2];
            float4 b4 = *(const float4*)&Bs[buf][k][tx << 2];
            unsigned long long bd0 = dup2(b4.x);
            unsigned long long bd1 = dup2(b4.y);
            unsigned long long bd2 = dup2(b4.z);
            unsigned long long bd3 = dup2(b4.w);
            acc[0][0] = ff2(ap.x, bd0, acc[0][0]);
            acc[0][1] = ff2(ap.x, bd1, acc[0][1]);
            acc[0][2] = ff2(ap.x, bd2, acc[0][2]);
            acc[0][3] = ff2(ap.x, bd3, acc[0][3]);
            acc[1][0] = ff2(ap.y, bd0, acc[1][0]);
            acc[1][1] = ff2(ap.y, bd1, acc[1][1]);
            acc[1][2] = ff2(ap.y, bd2, acc[1][2]);
            acc[1][3] = ff2(ap.y, bd3, acc[1][3]);
        }
        if (more) {
            int nb = buf ^ 1;
            As[nb][acol + 0][arow] = av.x;
            As[nb][acol + 1][arow] = av.y;
            As[nb][acol + 2][arow] = av.z;
            As[nb][acol + 3][arow] = av.w;
            *(float4*)&Bs[nb][brow][bcol] = bv;
        }
        __syncthreads();
    }

    float cres[4][4];
    #pragma unroll
    for (int p = 0; p < 2; p++)
        #pragma unroll
        for (int j = 0; j < 4; j++) {
            float lo, hi;
            asm("mov.b64 {%0, %1}, %2;" : "=f"(lo), "=f"(hi) : "l"(acc[p][j]));
            cres[2 * p][j] = lo;
            cres[2 * p + 1][j] = hi;
        }

    #pragma unroll
    for (int i = 0; i < 4; i++) {
        int m = m0 + (ty << 2) + i;
        const float* cf = ebias ? (coeff + m * E_) : nullptr;
        #pragma unroll
        for (int j = 0; j < 4; j++) {
            int n = n0 + (tx << 2) + j;
            if (n < Nout) {
                float v = cres[i][j];
                if (bias) v += bias[n];
                if (cf) {
                    float bm = 0.f;
                    #pragma unroll
                    for (int e = 0; e < E_; e++) bm = fmaf(cf[e], ebias[e * ebld + n], bm);
                    v += bm;
                }
                if (act) v = elu1(v);
                Cp[(size_t)m * ldc + n] = v;
            }
        }
    }
}

// ---------------- split-K combine with epilogue ----------------
__global__ void combine(const float* __restrict__ part, int S, int ldp,
                        float* __restrict__ C, int ldc, int Nout,
                        const float* __restrict__ bias,
                        const float* __restrict__ coeff,
                        const float* __restrict__ ebias, int ebld,
                        int act)
{
    int idx = blockIdx.x * blockDim.x + threadIdx.x;
    if (idx >= B_ * Nout) return;
    int m = idx / Nout, n = idx % Nout;
    float v = 0.f;
    for (int s = 0; s < S; s++) v += part[(size_t)s * B_ * ldp + (size_t)m * ldp + n];
    if (bias) v += bias[n];
    if (ebias) {
        const float* cf = coeff + m * E_;
        float bm = 0.f;
        #pragma unroll
        for (int e = 0; e < E_; e++) bm = fmaf(cf[e], ebias[e * ebld + n], bm);
        v += bm;
    }
    if (act) v = elu1(v);
    C[(size_t)m * ldc + n] = v;
}

// ---------------- host launch ----------------
static inline void* sym(const void* s) { void* p = nullptr; cudaGetSymbolAddress(&p, s); return p; }

extern "C" void kernel_launch(void* const* d_in, const int* in_sizes, int n_in,
                              void* d_out, int out_size) {
    (void)in_sizes; (void)n_in; (void)out_size;
    const float* x     = (const float*)d_in[0];
    const float* c     = (const float*)d_in[1];
    const float* fc1_w = (const float*)d_in[2];
    const float* fc1_b = (const float*)d_in[3];
    const float* fc2_w = (const float*)d_in[4];
    const float* fc2_b = (const float*)d_in[5];
    const float* mu_w  = (const float*)d_in[6];
    const float* mu_b  = (const float*)d_in[7];
    const float* lv_w  = (const float*)d_in[8];
    const float* lv_b  = (const float*)d_in[9];
    const float* g0_w  = (const float*)d_in[10];
    const float* g0_b  = (const float*)d_in[11];
    const float* g1_w  = (const float*)d_in[12];
    const float* g1_b  = (const float*)d_in[13];
    const float* g2_w  = (const float*)d_in[14];
    const float* g2_b  = (const float*)d_in[15];
    const float* w0    = (const float*)d_in[16];
    const float* b0    = (const float*)d_in[17];
    const float* w1    = (const float*)d_in[18];
    const float* b1    = (const float*)d_in[19];
    const float* w2    = (const float*)d_in[20];
    const float* b2    = (const float*)d_in[21];

    float* out       = (float*)d_out;
    float* out_layer = out;
    float* out_mu    = out + B_ * F_;
    float* out_lv    = out + B_ * F_ + B_ * L_;

    float* enc   = (float*)sym(g_enc);
    float* h1    = (float*)sym(g_h1);
    float* h2    = (float*)sym(g_h2);
    float* mulv  = (float*)sym(g_mulv);
    float* z     = (float*)sym(g_z);
    float* zc    = (float*)sym(g_zc);
    float* g0o   = (float*)sym(g_g0o);
    float* g1o   = (float*)sym(g_g1o);
    float* coef  = (float*)sym(g_coef);
    float* d0    = (float*)sym(g_d0);
    float* d1    = (float*)sym(g_d1);
    float* part  = (float*)sym(g_part);
    float* wfc1  = (float*)sym(g_wfc1);
    float* wfc2  = (float*)sym(g_wfc2);
    float* wmulv = (float*)sym(g_wmulv);
    float* bmulv = (float*)sym(g_bmulv);
    float* wg0   = (float*)sym(g_wg0);
    float* wg1   = (float*)sym(g_wg1);
    float* w0p   = (float*)sym(g_w0p);
    float* w2p   = (float*)sym(g_w2p);

    const int T = 256;
    auto gr = [](int n) { return (n + 255) / 256; };

    pack_all<<<gr(PKTOT), T>>>(fc1_w, fc2_w, mu_w, mu_b, lv_w, lv_b, g0_w, g1_w, w0, w2,
                               wfc1, wfc2, wmulv, bmulv, wg0, wg1, w0p, w2p);
    zc_fill_c<<<gr(B_ * 272), T>>>(zc, c);

    // ---- encoder (split-K 2) ----
    cat2<<<gr(B_ * KP_FC1), T>>>(enc, KP_FC1, x, 267, c, 267);
    gemm2<0><<<dim3(4, 32, 2), T>>>(enc, KP_FC1, nullptr, nullptr, wfc1, H_,
                                    part, H_, (long)B_ * H_, H_, 34, 17,
                                    nullptr, nullptr, 0, 0);
    combine<<<gr(B_ * H_), T>>>(part, 2, H_, h1, H_, H_, fc1_b, nullptr, nullptr, 0, 1);

    cat2<<<gr(B_ * KP_FC2), T>>>(enc, KP_FC2, x, 267, h1, 256);
    gemm2<0><<<dim3(4, 32, 2), T>>>(enc, KP_FC2, nullptr, nullptr, wfc2, H_,
                                    part, H_, (long)B_ * H_, H_, 33, 17,
                                    nullptr, nullptr, 0, 0);
    combine<<<gr(B_ * H_), T>>>(part, 2, H_, h2, H_, H_, fc2_b, nullptr, nullptr, 0, 1);

    cat2<<<gr(B_ * KP_FC2), T>>>(enc, KP_FC2, x, 267, h2, 256);
    gemm2<0><<<dim3(1, 32, 4), T>>>(enc, KP_FC2, nullptr, nullptr, wmulv, 64,
                                    part, 64, (long)B_ * 64, 64, 33, 9,
                                    nullptr, nullptr, 0, 0);
    combine<<<gr(B_ * 64), T>>>(part, 4, 64, mulv, 64, 64, bmulv, nullptr, nullptr, 0, 0);

    // z (also fills zc[:, :32]), mu/logvar outputs
    z_eps_kernel<<<gr(B_ * L_), T>>>(z, zc, mulv, out_mu, out_lv);

    // ---- gate ----
    gemm2<0><<<dim3(1, 32, 2), T>>>(zc, KP_ZC, nullptr, nullptr, wg0, G_,
                                    part, G_, (long)B_ * G_, G_, 19, 10,
                                    nullptr, nullptr, 0, 0);
    combine<<<gr(B_ * G_), T>>>(part, 2, G_, g0o, G_, G_, g0_b, nullptr, nullptr, 0, 1);
    gemm2<0><<<dim3(1, 32, 1), T>>>(g0o, G_, nullptr, nullptr, wg1, G_,
                                    g1o, G_, 0, G_, 4, 4,
                                    g1_b, nullptr, 0, 1);
    gate_final<<<gr(B_ * 32), T>>>(g1o, g2_w, g2_b, coef);

    // ---- decoder (split-K 4, A built on-the-fly) ----
    gemm2<1><<<dim3(4, 32, 4), T>>>(zc, KP_ZC, nullptr, coef, w0p, H_,
                                    part, H_, (long)B_ * H_, H_, 152, 38,
                                    nullptr, nullptr, 0, 0);
    combine<<<gr(B_ * H_), T>>>(part, 4, H_, d0, H_, H_, nullptr, coef, b0, 256, 1);

    gemm2<2><<<dim3(4, 32, 4), T>>>(d0, H_, z, coef, w1, H_,
                                    part, H_, (long)B_ * H_, H_, 144, 36,
                                    nullptr, nullptr, 0, 0);
    combine<<<gr(B_ * H_), T>>>(part, 4, H_, d1, H_, H_, nullptr, coef, b1, 256, 1);

    gemm2<2><<<dim3(5, 32, 4), T>>>(d1, H_, z, coef, w2p, NP_W2,
                                    part, NP_W2, (long)B_ * NP_W2, NP_W2, 144, 36,
                                    nullptr, nullptr, 0, 0);
    combine<<<gr(B_ * 267), T>>>(part, 4, NP_W2, out_layer, 267, 267, nullptr, coef, b2, 267, 0);
}

// round 5
// speedup vs baseline: 1.8503x; 1.0725x over previous
#include <cuda_runtime.h>
#include <cstdint>

// ---------------- problem dims ----------------
#define B_   2048
#define F_   267
#define L_   32
#define H_   256
#define E_   8
#define G_   64

#define KP_FC1 544            // 534 -> 544 (34 tiles)
#define KP_FC2 528            // 523 -> 528 (33 tiles)
#define KP_ZC  304            // 299 -> 304 (19 tiles)
#define K_D0   (E_*KP_ZC)     // 2432 (152 tiles)
#define IN1_   288            // 32 + 256
#define K_D12  (E_*IN1_)      // 2304 (144 tiles)
#define NP_W2  320            // 267 -> 320

#define SPLIT_MAX 8

// ---------------- device scratch ----------------
__device__ __align__(16) float g_enc  [B_*KP_FC1];
__device__ __align__(16) float g_h1   [B_*H_];
__device__ __align__(16) float g_h2   [B_*H_];
__device__ __align__(16) float g_mulv [B_*64];
__device__ __align__(16) float g_z    [B_*L_];
__device__ __align__(16) float g_zc   [B_*KP_ZC];
__device__ __align__(16) float g_g0o  [B_*G_];
__device__ __align__(16) float g_g1o  [B_*G_];
__device__ __align__(16) float g_coef [B_*E_];
__device__ __align__(16) float g_d0   [B_*H_];
__device__ __align__(16) float g_d1   [B_*H_];
__device__ __align__(16) float g_part [SPLIT_MAX*B_*NP_W2];   // split-K partials (21 MB)
// packed weights
__device__ __align__(16) float g_wfc1 [KP_FC1*H_];
__device__ __align__(16) float g_wfc2 [KP_FC2*H_];
__device__ __align__(16) float g_wmulv[KP_FC2*64];
__device__ __align__(16) float g_bmulv[64];
__device__ __align__(16) float g_wg0  [KP_ZC*G_];
__device__ __align__(16) float g_wg1  [G_*G_];
__device__ __align__(16) float g_w0p  [K_D0*H_];
__device__ __align__(16) float g_w2p  [K_D12*NP_W2];

__device__ __forceinline__ float elu1(float v) { return v > 0.f ? v : expm1f(v); }

// ---------------- f32x2 helpers ----------------
__device__ __forceinline__ unsigned long long ff2(unsigned long long a,
                                                  unsigned long long b,
                                                  unsigned long long c) {
    unsigned long long d;
    asm("fma.rn.f32x2 %0, %1, %2, %3;" : "=l"(d) : "l"(a), "l"(b), "l"(c));
    return d;
}
__device__ __forceinline__ unsigned long long dup2(float x) {
    unsigned long long d;
    asm("mov.b64 %0, {%1, %1};" : "=l"(d) : "f"(x));
    return d;
}

// ---------------- single mega-pack kernel ----------------
#define PK0 (KP_FC1*H_)
#define PK1 (KP_FC2*H_)
#define PK2 (KP_FC2*64)
#define PK3 64
#define PK4 (KP_ZC*G_)
#define PK5 (G_*G_)
#define PK6 (K_D0*H_)
#define PK7 (K_D12*NP_W2)
#define PKTOT (PK0+PK1+PK2+PK3+PK4+PK5+PK6+PK7)

__global__ void pack_all(const float* __restrict__ fc1_w, const float* __restrict__ fc2_w,
                         const float* __restrict__ mu_w, const float* __restrict__ mu_b,
                         const float* __restrict__ lv_w, const float* __restrict__ lv_b,
                         const float* __restrict__ g0_w, const float* __restrict__ g1_w,
                         const float* __restrict__ w0,   const float* __restrict__ w2,
                         float* __restrict__ wfc1, float* __restrict__ wfc2,
                         float* __restrict__ wmulv, float* __restrict__ bmulv,
                         float* __restrict__ wg0, float* __restrict__ wg1,
                         float* __restrict__ w0p, float* __restrict__ w2p) {
    int idx = blockIdx.x * blockDim.x + threadIdx.x;
    if (idx >= PKTOT) return;
    if (idx < PK0) {
        int k = idx / H_, n = idx % H_;
        wfc1[idx] = (k < 534) ? fc1_w[n * 534 + k] : 0.f;
        return;
    } idx -= PK0;
    if (idx < PK1) {
        int k = idx / H_, n = idx % H_;
        wfc2[idx] = (k < 523) ? fc2_w[n * 523 + k] : 0.f;
        return;
    } idx -= PK1;
    if (idx < PK2) {
        int k = idx / 64, n = idx % 64;
        float v = 0.f;
        if (k < 523) v = (n < 32) ? mu_w[n * 523 + k] : lv_w[(n - 32) * 523 + k];
        wmulv[idx] = v;
        return;
    } idx -= PK2;
    if (idx < PK3) {
        bmulv[idx] = (idx < 32) ? mu_b[idx] : lv_b[idx - 32];
        return;
    } idx -= PK3;
    if (idx < PK4) {
        int k = idx / G_, n = idx % G_;
        wg0[idx] = (k < 299) ? g0_w[n * 299 + k] : 0.f;
        return;
    } idx -= PK4;
    if (idx < PK5) {
        int k = idx / G_, n = idx % G_;
        wg1[idx] = g1_w[n * G_ + k];
        return;
    } idx -= PK5;
    if (idx < PK6) {
        int kk = idx / H_, n = idx % H_;
        int e = kk / KP_ZC, i = kk % KP_ZC;
        w0p[idx] = (i < 299) ? w0[(e * 299 + i) * H_ + n] : 0.f;
        return;
    } idx -= PK6;
    {
        int k = idx / NP_W2, n = idx % NP_W2;
        w2p[idx] = (n < 267) ? w2[k * 267 + n] : 0.f;
    }
}

// ---------------- concat / fill kernels ----------------
__global__ void cat2(float* __restrict__ dst, int Kp,
                     const float* __restrict__ s1, int l1,
                     const float* __restrict__ s2, int l2) {
    int idx = blockIdx.x * blockDim.x + threadIdx.x;
    if (idx >= B_ * Kp) return;
    int b = idx / Kp, k = idx % Kp;
    float v = 0.f;
    if (k < l1)           v = s1[b * l1 + k];
    else if (k < l1 + l2) v = s2[b * l2 + (k - l1)];
    dst[idx] = v;
}

__global__ void zc_fill_c(float* __restrict__ zc, const float* __restrict__ c) {
    int idx = blockIdx.x * blockDim.x + threadIdx.x;
    if (idx >= B_ * 272) return;
    int b = idx / 272, k = 32 + idx % 272;
    zc[b * KP_ZC + k] = (k < 299) ? c[b * 267 + (k - 32)] : 0.f;
}

// ---------------- threefry (partitionable) + XLA erfinv ----------------
__device__ __forceinline__ uint32_t rotl32(uint32_t v, int d) { return (v << d) | (v >> (32 - d)); }
__device__ __forceinline__ void tf4(uint32_t& x0, uint32_t& x1, int r0, int r1, int r2, int r3) {
    x0 += x1; x1 = rotl32(x1, r0); x1 ^= x0;
    x0 += x1; x1 = rotl32(x1, r1); x1 ^= x0;
    x0 += x1; x1 = rotl32(x1, r2); x1 ^= x0;
    x0 += x1; x1 = rotl32(x1, r3); x1 ^= x0;
}
__device__ __forceinline__ void threefry2x32(uint32_t k0, uint32_t k1, uint32_t& x0, uint32_t& x1) {
    uint32_t k2 = k0 ^ k1 ^ 0x1BD11BDAu;
    x0 += k0; x1 += k1;
    tf4(x0, x1, 13, 15, 26, 6);  x0 += k1; x1 += k2 + 1u;
    tf4(x0, x1, 17, 29, 16, 24); x0 += k2; x1 += k0 + 2u;
    tf4(x0, x1, 13, 15, 26, 6);  x0 += k0; x1 += k1 + 3u;
    tf4(x0, x1, 17, 29, 16, 24); x0 += k1; x1 += k2 + 4u;
    tf4(x0, x1, 13, 15, 26, 6);  x0 += k2; x1 += k0 + 5u;
}
__device__ __forceinline__ float erfinv_xla(float x) {
    float w = -log1pf(-x * x);
    float p;
    if (w < 5.0f) {
        w -= 2.5f;
        p = 2.81022636e-08f;
        p = fmaf(p, w, 3.43273939e-07f);
        p = fmaf(p, w, -3.5233877e-06f);
        p = fmaf(p, w, -4.39150654e-06f);
        p = fmaf(p, w, 0.00021858087f);
        p = fmaf(p, w, -0.00125372503f);
        p = fmaf(p, w, -0.00417768164f);
        p = fmaf(p, w, 0.246640727f);
        p = fmaf(p, w, 1.50140941f);
    } else {
        w = sqrtf(w) - 3.0f;
        p = -0.000200214257f;
        p = fmaf(p, w, 0.000100950558f);
        p = fmaf(p, w, 0.00134934322f);
        p = fmaf(p, w, -0.00367342844f);
        p = fmaf(p, w, 0.00573950773f);
        p = fmaf(p, w, -0.0076224613f);
        p = fmaf(p, w, 0.00943887047f);
        p = fmaf(p, w, 1.00167406f);
        p = fmaf(p, w, 2.83297682f);
    }
    return p * x;
}

__global__ void z_eps_kernel(float* __restrict__ zout, float* __restrict__ zc,
                             const float* __restrict__ mulv,
                             float* __restrict__ out_mu, float* __restrict__ out_lv) {
    int i = blockIdx.x * blockDim.x + threadIdx.x;
    if (i >= B_ * L_) return;
    uint32_t x0 = 0u, x1 = (uint32_t)i;
    threefry2x32(0u, 42u, x0, x1);
    uint32_t bits = x0 ^ x1;
    float f = __uint_as_float((bits >> 9) | 0x3f800000u) - 1.0f;
    const float lo = -0.99999994f;
    float u = fmaxf(lo, fmaf(f, 2.0f, lo));
    float eps = 1.41421354f * erfinv_xla(u);
    int b = i >> 5, l = i & 31;
    float mu = mulv[b * 64 + l];
    float lv = mulv[b * 64 + 32 + l];
    float zv = fmaf(eps, expf(0.5f * lv), mu);
    zout[i] = zv;
    zc[b * KP_ZC + l] = zv;
    out_mu[i] = mu;
    out_lv[i] = lv;
}

// ---------------- gate final (g2 + softmax) ----------------
__global__ void gate_final(const float* __restrict__ g1o, const float* __restrict__ g2w,
                           const float* __restrict__ g2b, float* __restrict__ coeff) {
    int gtid = blockIdx.x * blockDim.x + threadIdx.x;
    int row = gtid >> 5, lane = gtid & 31;
    if (row >= B_) return;
    float logit = 0.f;
    if (lane < E_) {
        logit = g2b[lane];
        const float* r = g1o + row * G_;
        const float* w = g2w + lane * G_;
        #pragma unroll 8
        for (int k = 0; k < G_; k++) logit = fmaf(r[k], w[k], logit);
    }
    float m = logit;
    for (int d = 4; d > 0; d >>= 1) m = fmaxf(m, __shfl_xor_sync(0xffffffffu, m, d));
    float ex = (lane < E_) ? expf(logit - m) : 0.f;
    float s = ex;
    for (int d = 4; d > 0; d >>= 1) s += __shfl_xor_sync(0xffffffffu, s, d);
    if (lane < E_) coeff[row * E_ + lane] = ex / s;
}

// ---------------- A loaders (MODE) ----------------
template <int MODE>
__device__ __forceinline__ float4 loadA(const float* __restrict__ A, int lda,
                                        const float* __restrict__ z,
                                        const float* __restrict__ coeff,
                                        int m, int kk) {
    if (MODE == 0) {
        return *(const float4*)(A + (size_t)m * lda + kk);
    } else if (MODE == 1) {
        int e = kk / KP_ZC, i = kk - e * KP_ZC;
        float s = coeff[m * E_ + e];
        float4 v = *(const float4*)(A + m * KP_ZC + i);
        v.x *= s; v.y *= s; v.z *= s; v.w *= s;
        return v;
    } else {
        int e = kk / IN1_, i = kk - e * IN1_;
        float s = coeff[m * E_ + e];
        float4 v = (i < L_) ? *(const float4*)(z + m * L_ + i)
                            : *(const float4*)(A + m * H_ + (i - L_));
        v.x *= s; v.y *= s; v.z *= s; v.w *= s;
        return v;
    }
}

// ---------------- SGEMM with f32x2 FMA, double-buffered smem, split-K ----------------
template <int MODE>
__global__ void __launch_bounds__(256) gemm2(
    const float* __restrict__ A, int lda,
    const float* __restrict__ z,
    const float* __restrict__ coeff,
    const float* __restrict__ W, int ldw,
    float* __restrict__ C, int ldc, long sliceStride, int Nout,
    int ktTot, int ktPer,
    const float* __restrict__ bias,
    const float* __restrict__ ebias, int ebld,
    int act)
{
    __shared__ __align__(16) float As[2][16][68];
    __shared__ __align__(16) float Bs[2][16][64];

    int tid = threadIdx.x;
    int m0 = blockIdx.y * 64;
    int n0 = blockIdx.x * 64;
    int kt0 = blockIdx.z * ktPer;
    int ktn = min(ktPer, ktTot - kt0);
    float* Cp = C + (long)blockIdx.z * sliceStride;

    int tx = tid & 15, ty = tid >> 4;
    int arow = tid >> 2, acol = (tid & 3) << 2;
    int brow = tid >> 4, bcol = (tid & 15) << 2;

    const float* Wp = W + (size_t)brow * ldw + n0 + bcol;
    int am = m0 + arow;

    unsigned long long acc[2][4];
    #pragma unroll
    for (int p = 0; p < 2; p++)
        #pragma unroll
        for (int j = 0; j < 4; j++) acc[p][j] = 0ull;

    float4 av = loadA<MODE>(A, lda, z, coeff, am, (kt0 << 4) + acol);
    float4 bv = *(const float4*)(Wp + (size_t)(kt0 << 4) * ldw);

    As[0][acol + 0][arow] = av.x;
    As[0][acol + 1][arow] = av.y;
    As[0][acol + 2][arow] = av.z;
    As[0][acol + 3][arow] = av.w;
    *(float4*)&Bs[0][brow][bcol] = bv;
    __syncthreads();

    for (int t = 0; t < ktn; t++) {
        int buf = t & 1;
        bool more = (t + 1) < ktn;
        if (more) {
            int kk = ((kt0 + t + 1) << 4);
            av = loadA<MODE>(A, lda, z, coeff, am, kk + acol);
            bv = *(const float4*)(Wp + (size_t)kk * ldw);
        }
        #pragma unroll
        for (int k = 0; k < 16; k++) {
            ulonglong2 ap = *(const ulonglong2*)&As[buf][k][ty << 2];
            float4 b4 = *(const float4*)&Bs[buf][k][tx << 2];
            unsigned long long bd0 = dup2(b4.x);
            unsigned long long bd1 = dup2(b4.y);
            unsigned long long bd2 = dup2(b4.z);
            unsigned long long bd3 = dup2(b4.w);
            acc[0][0] = ff2(ap.x, bd0, acc[0][0]);
            acc[0][1] = ff2(ap.x, bd1, acc[0][1]);
            acc[0][2] = ff2(ap.x, bd2, acc[0][2]);
            acc[0][3] = ff2(ap.x, bd3, acc[0][3]);
            acc[1][0] = ff2(ap.y, bd0, acc[1][0]);
            acc[1][1] = ff2(ap.y, bd1, acc[1][1]);
            acc[1][2] = ff2(ap.y, bd2, acc[1][2]);
            acc[1][3] = ff2(ap.y, bd3, acc[1][3]);
        }
        if (more) {
            int nb = buf ^ 1;
            As[nb][acol + 0][arow] = av.x;
            As[nb][acol + 1][arow] = av.y;
            As[nb][acol + 2][arow] = av.z;
            As[nb][acol + 3][arow] = av.w;
            *(float4*)&Bs[nb][brow][bcol] = bv;
        }
        __syncthreads();
    }

    float cres[4][4];
    #pragma unroll
    for (int p = 0; p < 2; p++)
        #pragma unroll
        for (int j = 0; j < 4; j++) {
            float lo, hi;
            asm("mov.b64 {%0, %1}, %2;" : "=f"(lo), "=f"(hi) : "l"(acc[p][j]));
            cres[2 * p][j] = lo;
            cres[2 * p + 1][j] = hi;
        }

    #pragma unroll
    for (int i = 0; i < 4; i++) {
        int m = m0 + (ty << 2) + i;
        const float* cf = ebias ? (coeff + m * E_) : nullptr;
        #pragma unroll
        for (int j = 0; j < 4; j++) {
            int n = n0 + (tx << 2) + j;
            if (n < Nout) {
                float v = cres[i][j];
                if (bias) v += bias[n];
                if (cf) {
                    float bm = 0.f;
                    #pragma unroll
                    for (int e = 0; e < E_; e++) bm = fmaf(cf[e], ebias[e * ebld + n], bm);
                    v += bm;
                }
                if (act) v = elu1(v);
                Cp[(size_t)m * ldc + n] = v;
            }
        }
    }
}

// ---------------- split-K combine with epilogue ----------------
__global__ void combine(const float* __restrict__ part, int S, int ldp,
                        float* __restrict__ C, int ldc, int Nout,
                        const float* __restrict__ bias,
                        const float* __restrict__ coeff,
                        const float* __restrict__ ebias, int ebld,
                        int act)
{
    int idx = blockIdx.x * blockDim.x + threadIdx.x;
    if (idx >= B_ * Nout) return;
    int m = idx / Nout, n = idx % Nout;
    float v = 0.f;
    for (int s = 0; s < S; s++) v += part[(size_t)s * B_ * ldp + (size_t)m * ldp + n];
    if (bias) v += bias[n];
    if (ebias) {
        const float* cf = coeff + m * E_;
        float bm = 0.f;
        #pragma unroll
        for (int e = 0; e < E_; e++) bm = fmaf(cf[e], ebias[e * ebld + n], bm);
        v += bm;
    }
    if (act) v = elu1(v);
    C[(size_t)m * ldc + n] = v;
}

// ---------------- host launch ----------------
static inline void* sym(const void* s) { void* p = nullptr; cudaGetSymbolAddress(&p, s); return p; }

extern "C" void kernel_launch(void* const* d_in, const int* in_sizes, int n_in,
                              void* d_out, int out_size) {
    (void)in_sizes; (void)n_in; (void)out_size;
    const float* x     = (const float*)d_in[0];
    const float* c     = (const float*)d_in[1];
    const float* fc1_w = (const float*)d_in[2];
    const float* fc1_b = (const float*)d_in[3];
    const float* fc2_w = (const float*)d_in[4];
    const float* fc2_b = (const float*)d_in[5];
    const float* mu_w  = (const float*)d_in[6];
    const float* mu_b  = (const float*)d_in[7];
    const float* lv_w  = (const float*)d_in[8];
    const float* lv_b  = (const float*)d_in[9];
    const float* g0_w  = (const float*)d_in[10];
    const float* g0_b  = (const float*)d_in[11];
    const float* g1_w  = (const float*)d_in[12];
    const float* g1_b  = (const float*)d_in[13];
    const float* g2_w  = (const float*)d_in[14];
    const float* g2_b  = (const float*)d_in[15];
    const float* w0    = (const float*)d_in[16];
    const float* b0    = (const float*)d_in[17];
    const float* w1    = (const float*)d_in[18];
    const float* b1    = (const float*)d_in[19];
    const float* w2    = (const float*)d_in[20];
    const float* b2    = (const float*)d_in[21];

    float* out       = (float*)d_out;
    float* out_layer = out;
    float* out_mu    = out + B_ * F_;
    float* out_lv    = out + B_ * F_ + B_ * L_;

    float* enc   = (float*)sym(g_enc);
    float* h1    = (float*)sym(g_h1);
    float* h2    = (float*)sym(g_h2);
    float* mulv  = (float*)sym(g_mulv);
    float* z     = (float*)sym(g_z);
    float* zc    = (float*)sym(g_zc);
    float* g0o   = (float*)sym(g_g0o);
    float* g1o   = (float*)sym(g_g1o);
    float* coef  = (float*)sym(g_coef);
    float* d0    = (float*)sym(g_d0);
    float* d1    = (float*)sym(g_d1);
    float* part  = (float*)sym(g_part);
    float* wfc1  = (float*)sym(g_wfc1);
    float* wfc2  = (float*)sym(g_wfc2);
    float* wmulv = (float*)sym(g_wmulv);
    float* bmulv = (float*)sym(g_bmulv);
    float* wg0   = (float*)sym(g_wg0);
    float* wg1   = (float*)sym(g_wg1);
    float* w0p   = (float*)sym(g_w0p);
    float* w2p   = (float*)sym(g_w2p);

    const int T = 256;
    auto gr = [](int n) { return (n + 255) / 256; };

    pack_all<<<gr(PKTOT), T>>>(fc1_w, fc2_w, mu_w, mu_b, lv_w, lv_b, g0_w, g1_w, w0, w2,
                               wfc1, wfc2, wmulv, bmulv, wg0, wg1, w0p, w2p);
    zc_fill_c<<<gr(B_ * 272), T>>>(zc, c);

    // ---- encoder fc1: split-K 4, grid 512 ----
    cat2<<<gr(B_ * KP_FC1), T>>>(enc, KP_FC1, x, 267, c, 267);
    gemm2<0><<<dim3(4, 32, 4), T>>>(enc, KP_FC1, nullptr, nullptr, wfc1, H_,
                                    part, H_, (long)B_ * H_, H_, 34, 9,
                                    nullptr, nullptr, 0, 0);
    combine<<<gr(B_ * H_), T>>>(part, 4, H_, h1, H_, H_, fc1_b, nullptr, nullptr, 0, 1);

    // ---- encoder fc2: split-K 4, grid 512 ----
    cat2<<<gr(B_ * KP_FC2), T>>>(enc, KP_FC2, x, 267, h1, 256);
    gemm2<0><<<dim3(4, 32, 4), T>>>(enc, KP_FC2, nullptr, nullptr, wfc2, H_,
                                    part, H_, (long)B_ * H_, H_, 33, 9,
                                    nullptr, nullptr, 0, 0);
    combine<<<gr(B_ * H_), T>>>(part, 4, H_, h2, H_, H_, fc2_b, nullptr, nullptr, 0, 1);

    // ---- mu/lv: split-K 8, grid 256 ----
    cat2<<<gr(B_ * KP_FC2), T>>>(enc, KP_FC2, x, 267, h2, 256);
    gemm2<0><<<dim3(1, 32, 8), T>>>(enc, KP_FC2, nullptr, nullptr, wmulv, 64,
                                    part, 64, (long)B_ * 64, 64, 33, 5,
                                    nullptr, nullptr, 0, 0);
    combine<<<gr(B_ * 64), T>>>(part, 8, 64, mulv, 64, 64, bmulv, nullptr, nullptr, 0, 0);

    // z (also fills zc[:, :32]), mu/logvar outputs
    z_eps_kernel<<<gr(B_ * L_), T>>>(z, zc, mulv, out_mu, out_lv);

    // ---- gate ----
    gemm2<0><<<dim3(1, 32, 4), T>>>(zc, KP_ZC, nullptr, nullptr, wg0, G_,
                                    part, G_, (long)B_ * G_, G_, 19, 5,
                                    nullptr, nullptr, 0, 0);
    combine<<<gr(B_ * G_), T>>>(part, 4, G_, g0o, G_, G_, g0_b, nullptr, nullptr, 0, 1);
    gemm2<0><<<dim3(1, 32, 1), T>>>(g0o, G_, nullptr, nullptr, wg1, G_,
                                    g1o, G_, 0, G_, 4, 4,
                                    g1_b, nullptr, 0, 1);
    gate_final<<<gr(B_ * 32), T>>>(g1o, g2_w, g2_b, coef);

    // ---- decoder (split-K 8, A built on-the-fly) ----
    gemm2<1><<<dim3(4, 32, 8), T>>>(zc, KP_ZC, nullptr, coef, w0p, H_,
                                    part, H_, (long)B_ * H_, H_, 152, 19,
                                    nullptr, nullptr, 0, 0);
    combine<<<gr(B_ * H_), T>>>(part, 8, H_, d0, H_, H_, nullptr, coef, b0, 256, 1);

    gemm2<2><<<dim3(4, 32, 8), T>>>(d0, H_, z, coef, w1, H_,
                                    part, H_, (long)B_ * H_, H_, 144, 18,
                                    nullptr, nullptr, 0, 0);
    combine<<<gr(B_ * H_), T>>>(part, 8, H_, d1, H_, H_, nullptr, coef, b1, 256, 1);

    gemm2<2><<<dim3(5, 32, 8), T>>>(d1, H_, z, coef, w2p, NP_W2,
                                    part, NP_W2, (long)B_ * NP_W2, NP_W2, 144, 18,
                                    nullptr, nullptr, 0, 0);
    combine<<<gr(B_ * 267), T>>>(part, 8, NP_W2, out_layer, 267, 267, nullptr, coef, b2, 267, 0);
}

// round 6
// speedup vs baseline: 2.1183x; 1.1448x over previous
#include <cuda_runtime.h>
#include <cstdint>

// ---------------- problem dims ----------------
#define B_   2048
#define F_   267
#define L_   32
#define H_   256
#define E_   8
#define G_   64

#define KP_FC1 544            // 534 -> 544 (34 tiles)
#define KP_FC2 528            // 523 -> 528 (33 tiles)
#define KP_ZC  304            // 299 -> 304 (19 tiles)
#define K_D0   (E_*KP_ZC)     // 2432 (152 tiles)
#define IN1_   288            // 32 + 256
#define K_D12  (E_*IN1_)      // 2304 (144 tiles)
#define NP_W2  320            // 267 -> 320

#define SPLIT_MAX 8

// ---------------- device scratch ----------------
__device__ __align__(16) float g_enc  [B_*KP_FC1];
__device__ __align__(16) float g_h1   [B_*H_];
__device__ __align__(16) float g_h2   [B_*H_];
__device__ __align__(16) float g_mulv [B_*64];
__device__ __align__(16) float g_z    [B_*L_];
__device__ __align__(16) float g_zc   [B_*KP_ZC];
__device__ __align__(16) float g_g0o  [B_*G_];
__device__ __align__(16) float g_g1o  [B_*G_];
__device__ __align__(16) float g_coef [B_*E_];
__device__ __align__(16) float g_d0   [B_*H_];
__device__ __align__(16) float g_d1   [B_*H_];
__device__ __align__(16) float g_part [SPLIT_MAX*B_*NP_W2];   // split-K partials (21 MB)
// packed weights
__device__ __align__(16) float g_wfc1 [KP_FC1*H_];
__device__ __align__(16) float g_wfc2 [KP_FC2*H_];
__device__ __align__(16) float g_wmulv[KP_FC2*64];
__device__ __align__(16) float g_bmulv[64];
__device__ __align__(16) float g_wg0  [KP_ZC*G_];
__device__ __align__(16) float g_wg1  [G_*G_];
__device__ __align__(16) float g_w0p  [K_D0*H_];
__device__ __align__(16) float g_w2p  [K_D12*NP_W2];

__device__ __forceinline__ float elu1(float v) { return v > 0.f ? v : expm1f(v); }

// ---------------- f32x2 helpers ----------------
__device__ __forceinline__ unsigned long long ff2(unsigned long long a,
                                                  unsigned long long b,
                                                  unsigned long long c) {
    unsigned long long d;
    asm("fma.rn.f32x2 %0, %1, %2, %3;" : "=l"(d) : "l"(a), "l"(b), "l"(c));
    return d;
}
__device__ __forceinline__ unsigned long long dup2(float x) {
    unsigned long long d;
    asm("mov.b64 %0, {%1, %1};" : "=l"(d) : "f"(x));
    return d;
}

// ---------------- single mega-pack kernel ----------------
#define PK0 (KP_FC1*H_)
#define PK1 (KP_FC2*H_)
#define PK2 (KP_FC2*64)
#define PK3 64
#define PK4 (KP_ZC*G_)
#define PK5 (G_*G_)
#define PK6 (K_D0*H_)
#define PK7 (K_D12*NP_W2)
#define PKTOT (PK0+PK1+PK2+PK3+PK4+PK5+PK6+PK7)

__global__ void pack_all(const float* __restrict__ fc1_w, const float* __restrict__ fc2_w,
                         const float* __restrict__ mu_w, const float* __restrict__ mu_b,
                         const float* __restrict__ lv_w, const float* __restrict__ lv_b,
                         const float* __restrict__ g0_w, const float* __restrict__ g1_w,
                         const float* __restrict__ w0,   const float* __restrict__ w2,
                         float* __restrict__ wfc1, float* __restrict__ wfc2,
                         float* __restrict__ wmulv, float* __restrict__ bmulv,
                         float* __restrict__ wg0, float* __restrict__ wg1,
                         float* __restrict__ w0p, float* __restrict__ w2p) {
    int idx = blockIdx.x * blockDim.x + threadIdx.x;
    if (idx >= PKTOT) return;
    if (idx < PK0) {
        int k = idx / H_, n = idx % H_;
        wfc1[idx] = (k < 534) ? fc1_w[n * 534 + k] : 0.f;
        return;
    } idx -= PK0;
    if (idx < PK1) {
        int k = idx / H_, n = idx % H_;
        wfc2[idx] = (k < 523) ? fc2_w[n * 523 + k] : 0.f;
        return;
    } idx -= PK1;
    if (idx < PK2) {
        int k = idx / 64, n = idx % 64;
        float v = 0.f;
        if (k < 523) v = (n < 32) ? mu_w[n * 523 + k] : lv_w[(n - 32) * 523 + k];
        wmulv[idx] = v;
        return;
    } idx -= PK2;
    if (idx < PK3) {
        bmulv[idx] = (idx < 32) ? mu_b[idx] : lv_b[idx - 32];
        return;
    } idx -= PK3;
    if (idx < PK4) {
        int k = idx / G_, n = idx % G_;
        wg0[idx] = (k < 299) ? g0_w[n * 299 + k] : 0.f;
        return;
    } idx -= PK4;
    if (idx < PK5) {
        int k = idx / G_, n = idx % G_;
        wg1[idx] = g1_w[n * G_ + k];
        return;
    } idx -= PK5;
    if (idx < PK6) {
        int kk = idx / H_, n = idx % H_;
        int e = kk / KP_ZC, i = kk % KP_ZC;
        w0p[idx] = (i < 299) ? w0[(e * 299 + i) * H_ + n] : 0.f;
        return;
    } idx -= PK6;
    {
        int k = idx / NP_W2, n = idx % NP_W2;
        w2p[idx] = (n < 267) ? w2[k * 267 + n] : 0.f;
    }
}

// ---------------- concat / fill kernels ----------------
__global__ void cat2(float* __restrict__ dst, int Kp,
                     const float* __restrict__ s1, int l1,
                     const float* __restrict__ s2, int l2) {
    int idx = blockIdx.x * blockDim.x + threadIdx.x;
    if (idx >= B_ * Kp) return;
    int b = idx / Kp, k = idx % Kp;
    float v = 0.f;
    if (k < l1)           v = s1[b * l1 + k];
    else if (k < l1 + l2) v = s2[b * l2 + (k - l1)];
    dst[idx] = v;
}

__global__ void zc_fill_c(float* __restrict__ zc, const float* __restrict__ c) {
    int idx = blockIdx.x * blockDim.x + threadIdx.x;
    if (idx >= B_ * 272) return;
    int b = idx / 272, k = 32 + idx % 272;
    zc[b * KP_ZC + k] = (k < 299) ? c[b * 267 + (k - 32)] : 0.f;
}

// ---------------- threefry (partitionable) + XLA erfinv ----------------
__device__ __forceinline__ uint32_t rotl32(uint32_t v, int d) { return (v << d) | (v >> (32 - d)); }
__device__ __forceinline__ void tf4(uint32_t& x0, uint32_t& x1, int r0, int r1, int r2, int r3) {
    x0 += x1; x1 = rotl32(x1, r0); x1 ^= x0;
    x0 += x1; x1 = rotl32(x1, r1); x1 ^= x0;
    x0 += x1; x1 = rotl32(x1, r2); x1 ^= x0;
    x0 += x1; x1 = rotl32(x1, r3); x1 ^= x0;
}
__device__ __forceinline__ void threefry2x32(uint32_t k0, uint32_t k1, uint32_t& x0, uint32_t& x1) {
    uint32_t k2 = k0 ^ k1 ^ 0x1BD11BDAu;
    x0 += k0; x1 += k1;
    tf4(x0, x1, 13, 15, 26, 6);  x0 += k1; x1 += k2 + 1u;
    tf4(x0, x1, 17, 29, 16, 24); x0 += k2; x1 += k0 + 2u;
    tf4(x0, x1, 13, 15, 26, 6);  x0 += k0; x1 += k1 + 3u;
    tf4(x0, x1, 17, 29, 16, 24); x0 += k1; x1 += k2 + 4u;
    tf4(x0, x1, 13, 15, 26, 6);  x0 += k2; x1 += k0 + 5u;
}
__device__ __forceinline__ float erfinv_xla(float x) {
    float w = -log1pf(-x * x);
    float p;
    if (w < 5.0f) {
        w -= 2.5f;
        p = 2.81022636e-08f;
        p = fmaf(p, w, 3.43273939e-07f);
        p = fmaf(p, w, -3.5233877e-06f);
        p = fmaf(p, w, -4.39150654e-06f);
        p = fmaf(p, w, 0.00021858087f);
        p = fmaf(p, w, -0.00125372503f);
        p = fmaf(p, w, -0.00417768164f);
        p = fmaf(p, w, 0.246640727f);
        p = fmaf(p, w, 1.50140941f);
    } else {
        w = sqrtf(w) - 3.0f;
        p = -0.000200214257f;
        p = fmaf(p, w, 0.000100950558f);
        p = fmaf(p, w, 0.00134934322f);
        p = fmaf(p, w, -0.00367342844f);
        p = fmaf(p, w, 0.00573950773f);
        p = fmaf(p, w, -0.0076224613f);
        p = fmaf(p, w, 0.00943887047f);
        p = fmaf(p, w, 1.00167406f);
        p = fmaf(p, w, 2.83297682f);
    }
    return p * x;
}

__global__ void z_eps_kernel(float* __restrict__ zout, float* __restrict__ zc,
                             const float* __restrict__ mulv,
                             float* __restrict__ out_mu, float* __restrict__ out_lv) {
    int i = blockIdx.x * blockDim.x + threadIdx.x;
    if (i >= B_ * L_) return;
    uint32_t x0 = 0u, x1 = (uint32_t)i;
    threefry2x32(0u, 42u, x0, x1);
    uint32_t bits = x0 ^ x1;
    float f = __uint_as_float((bits >> 9) | 0x3f800000u) - 1.0f;
    const float lo = -0.99999994f;
    float u = fmaxf(lo, fmaf(f, 2.0f, lo));
    float eps = 1.41421354f * erfinv_xla(u);
    int b = i >> 5, l = i & 31;
    float mu = mulv[b * 64 + l];
    float lv = mulv[b * 64 + 32 + l];
    float zv = fmaf(eps, expf(0.5f * lv), mu);
    zout[i] = zv;
    zc[b * KP_ZC + l] = zv;
    out_mu[i] = mu;
    out_lv[i] = lv;
}

// ---------------- gate final (g2 + softmax) ----------------
__global__ void gate_final(const float* __restrict__ g1o, const float* __restrict__ g2w,
                           const float* __restrict__ g2b, float* __restrict__ coeff) {
    int gtid = blockIdx.x * blockDim.x + threadIdx.x;
    int row = gtid >> 5, lane = gtid & 31;
    if (row >= B_) return;
    float logit = 0.f;
    if (lane < E_) {
        logit = g2b[lane];
        const float* r = g1o + row * G_;
        const float* w = g2w + lane * G_;
        #pragma unroll 8
        for (int k = 0; k < G_; k++) logit = fmaf(r[k], w[k], logit);
    }
    float m = logit;
    for (int d = 4; d > 0; d >>= 1) m = fmaxf(m, __shfl_xor_sync(0xffffffffu, m, d));
    float ex = (lane < E_) ? expf(logit - m) : 0.f;
    float s = ex;
    for (int d = 4; d > 0; d >>= 1) s += __shfl_xor_sync(0xffffffffu, s, d);
    if (lane < E_) coeff[row * E_ + lane] = ex / s;
}

// ---------------- A loaders (MODE) ----------------
template <int MODE>
__device__ __forceinline__ float4 loadA(const float* __restrict__ A, int lda,
                                        const float* __restrict__ z,
                                        const float* __restrict__ coeff,
                                        int m, int kk) {
    if (MODE == 0) {
        return *(const float4*)(A + (size_t)m * lda + kk);
    } else if (MODE == 1) {
        int e = kk / KP_ZC, i = kk - e * KP_ZC;
        float s = coeff[m * E_ + e];
        float4 v = *(const float4*)(A + m * KP_ZC + i);
        v.x *= s; v.y *= s; v.z *= s; v.w *= s;
        return v;
    } else {
        int e = kk / IN1_, i = kk - e * IN1_;
        float s = coeff[m * E_ + e];
        float4 v = (i < L_) ? *(const float4*)(z + m * L_ + i)
                            : *(const float4*)(A + m * H_ + (i - L_));
        v.x *= s; v.y *= s; v.z *= s; v.w *= s;
        return v;
    }
}

// ---------------- SGEMM: BM=128, BN=64, BK=16, 8x4 microtile (f32x2 pairs over m) ----------------
template <int MODE>
__global__ void __launch_bounds__(256) gemm3(
    const float* __restrict__ A, int lda,
    const float* __restrict__ z,
    const float* __restrict__ coeff,
    const float* __restrict__ W, int ldw,
    float* __restrict__ C, int ldc, long sliceStride, int Nout,
    int ktTot, int ktPer,
    const float* __restrict__ bias, int act)
{
    __shared__ __align__(16) float As[2][16][132];
    __shared__ __align__(16) float Bs[2][16][68];

    int tid = threadIdx.x;
    int m0 = blockIdx.y * 128;
    int n0 = blockIdx.x * 64;
    int kt0 = blockIdx.z * ktPer;
    int ktn = min(ktPer, ktTot - kt0);
    float* Cp = C + (long)blockIdx.z * sliceStride;

    int tx = tid & 15, ty = tid >> 4;              // microtile coords: n=tx*4, m=ty*8
    int arow = tid >> 2, acol = (tid & 3) << 2;    // A tile loader (rows arow, arow+64)
    int brow = tid >> 4, bcol = (tid & 15) << 2;   // B tile loader

    const float* Wp = W + (size_t)brow * ldw + n0 + bcol;
    int am0 = m0 + arow, am1 = m0 + arow + 64;

    unsigned long long acc[4][4];
    #pragma unroll
    for (int q = 0; q < 4; q++)
        #pragma unroll
        for (int j = 0; j < 4; j++) acc[q][j] = 0ull;

    float4 av0 = loadA<MODE>(A, lda, z, coeff, am0, (kt0 << 4) + acol);
    float4 av1 = loadA<MODE>(A, lda, z, coeff, am1, (kt0 << 4) + acol);
    float4 bv  = *(const float4*)(Wp + (size_t)(kt0 << 4) * ldw);

    As[0][acol + 0][arow] = av0.x;
    As[0][acol + 1][arow] = av0.y;
    As[0][acol + 2][arow] = av0.z;
    As[0][acol + 3][arow] = av0.w;
    As[0][acol + 0][arow + 64] = av1.x;
    As[0][acol + 1][arow + 64] = av1.y;
    As[0][acol + 2][arow + 64] = av1.z;
    As[0][acol + 3][arow + 64] = av1.w;
    *(float4*)&Bs[0][brow][bcol] = bv;
    __syncthreads();

    for (int t = 0; t < ktn; t++) {
        int buf = t & 1;
        bool more = (t + 1) < ktn;
        if (more) {
            int kk = (kt0 + t + 1) << 4;
            av0 = loadA<MODE>(A, lda, z, coeff, am0, kk + acol);
            av1 = loadA<MODE>(A, lda, z, coeff, am1, kk + acol);
            bv  = *(const float4*)(Wp + (size_t)kk * ldw);
        }
        #pragma unroll
        for (int k = 0; k < 16; k++) {
            ulonglong2 a01 = *(const ulonglong2*)&As[buf][k][ty << 3];
            ulonglong2 a23 = *(const ulonglong2*)&As[buf][k][(ty << 3) + 4];
            float4 b4 = *(const float4*)&Bs[buf][k][tx << 2];
            unsigned long long bd0 = dup2(b4.x);
            unsigned long long bd1 = dup2(b4.y);
            unsigned long long bd2 = dup2(b4.z);
            unsigned long long bd3 = dup2(b4.w);
            acc[0][0] = ff2(a01.x, bd0, acc[0][0]);
            acc[0][1] = ff2(a01.x, bd1, acc[0][1]);
            acc[0][2] = ff2(a01.x, bd2, acc[0][2]);
            acc[0][3] = ff2(a01.x, bd3, acc[0][3]);
            acc[1][0] = ff2(a01.y, bd0, acc[1][0]);
            acc[1][1] = ff2(a01.y, bd1, acc[1][1]);
            acc[1][2] = ff2(a01.y, bd2, acc[1][2]);
            acc[1][3] = ff2(a01.y, bd3, acc[1][3]);
            acc[2][0] = ff2(a23.x, bd0, acc[2][0]);
            acc[2][1] = ff2(a23.x, bd1, acc[2][1]);
            acc[2][2] = ff2(a23.x, bd2, acc[2][2]);
            acc[2][3] = ff2(a23.x, bd3, acc[2][3]);
            acc[3][0] = ff2(a23.y, bd0, acc[3][0]);
            acc[3][1] = ff2(a23.y, bd1, acc[3][1]);
            acc[3][2] = ff2(a23.y, bd2, acc[3][2]);
            acc[3][3] = ff2(a23.y, bd3, acc[3][3]);
        }
        if (more) {
            int nb = buf ^ 1;
            As[nb][acol + 0][arow] = av0.x;
            As[nb][acol + 1][arow] = av0.y;
            As[nb][acol + 2][arow] = av0.z;
            As[nb][acol + 3][arow] = av0.w;
            As[nb][acol + 0][arow + 64] = av1.x;
            As[nb][acol + 1][arow + 64] = av1.y;
            As[nb][acol + 2][arow + 64] = av1.z;
            As[nb][acol + 3][arow + 64] = av1.w;
            *(float4*)&Bs[nb][brow][bcol] = bv;
        }
        __syncthreads();
    }

    // unpack: acc[q][j] covers m rows ty*8+2q, ty*8+2q+1
    float cres[8][4];
    #pragma unroll
    for (int q = 0; q < 4; q++)
        #pragma unroll
        for (int j = 0; j < 4; j++) {
            float lo, hi;
            asm("mov.b64 {%0, %1}, %2;" : "=f"(lo), "=f"(hi) : "l"(acc[q][j]));
            cres[2 * q][j] = lo;
            cres[2 * q + 1][j] = hi;
        }

    int n = n0 + (tx << 2);
    float4 bsv = make_float4(0.f, 0.f, 0.f, 0.f);
    if (bias) bsv = *(const float4*)(bias + n);
    #pragma unroll
    for (int r = 0; r < 8; r++) {
        int m = m0 + (ty << 3) + r;
        float4 v;
        v.x = cres[r][0] + bsv.x;
        v.y = cres[r][1] + bsv.y;
        v.z = cres[r][2] + bsv.z;
        v.w = cres[r][3] + bsv.w;
        if (act) { v.x = elu1(v.x); v.y = elu1(v.y); v.z = elu1(v.z); v.w = elu1(v.w); }
        if (n < Nout) *(float4*)(Cp + (size_t)m * ldc + n) = v;
    }
}

// ---------------- split-K combine with epilogue ----------------
__global__ void combine(const float* __restrict__ part, int S, int ldp,
                        float* __restrict__ C, int ldc, int Nout,
                        const float* __restrict__ bias,
                        const float* __restrict__ coeff,
                        const float* __restrict__ ebias, int ebld,
                        int act)
{
    int idx = blockIdx.x * blockDim.x + threadIdx.x;
    if (idx >= B_ * Nout) return;
    int m = idx / Nout, n = idx % Nout;
    float v = 0.f;
    for (int s = 0; s < S; s++) v += part[(size_t)s * B_ * ldp + (size_t)m * ldp + n];
    if (bias) v += bias[n];
    if (ebias) {
        const float* cf = coeff + m * E_;
        float bm = 0.f;
        #pragma unroll
        for (int e = 0; e < E_; e++) bm = fmaf(cf[e], ebias[e * ebld + n], bm);
        v += bm;
    }
    if (act) v = elu1(v);
    C[(size_t)m * ldc + n] = v;
}

// ---------------- host launch ----------------
static inline void* sym(const void* s) { void* p = nullptr; cudaGetSymbolAddress(&p, s); return p; }

extern "C" void kernel_launch(void* const* d_in, const int* in_sizes, int n_in,
                              void* d_out, int out_size) {
    (void)in_sizes; (void)n_in; (void)out_size;
    const float* x     = (const float*)d_in[0];
    const float* c     = (const float*)d_in[1];
    const float* fc1_w = (const float*)d_in[2];
    const float* fc1_b = (const float*)d_in[3];
    const float* fc2_w = (const float*)d_in[4];
    const float* fc2_b = (const float*)d_in[5];
    const float* mu_w  = (const float*)d_in[6];
    const float* mu_b  = (const float*)d_in[7];
    const float* lv_w  = (const float*)d_in[8];
    const float* lv_b  = (const float*)d_in[9];
    const float* g0_w  = (const float*)d_in[10];
    const float* g0_b  = (const float*)d_in[11];
    const float* g1_w  = (const float*)d_in[12];
    const float* g1_b  = (const float*)d_in[13];
    const float* g2_w  = (const float*)d_in[14];
    const float* g2_b  = (const float*)d_in[15];
    const float* w0    = (const float*)d_in[16];
    const float* b0    = (const float*)d_in[17];
    const float* w1    = (const float*)d_in[18];
    const float* b1    = (const float*)d_in[19];
    const float* w2    = (const float*)d_in[20];
    const float* b2    = (const float*)d_in[21];

    float* out       = (float*)d_out;
    float* out_layer = out;
    float* out_mu    = out + B_ * F_;
    float* out_lv    = out + B_ * F_ + B_ * L_;

    float* enc   = (float*)sym(g_enc);
    float* h1    = (float*)sym(g_h1);
    float* h2    = (float*)sym(g_h2);
    float* mulv  = (float*)sym(g_mulv);
    float* z     = (float*)sym(g_z);
    float* zc    = (float*)sym(g_zc);
    float* g0o   = (float*)sym(g_g0o);
    float* g1o   = (float*)sym(g_g1o);
    float* coef  = (float*)sym(g_coef);
    float* d0    = (float*)sym(g_d0);
    float* d1    = (float*)sym(g_d1);
    float* part  = (float*)sym(g_part);
    float* wfc1  = (float*)sym(g_wfc1);
    float* wfc2  = (float*)sym(g_wfc2);
    float* wmulv = (float*)sym(g_wmulv);
    float* bmulv = (float*)sym(g_bmulv);
    float* wg0   = (float*)sym(g_wg0);
    float* wg1   = (float*)sym(g_wg1);
    float* w0p   = (float*)sym(g_w0p);
    float* w2p   = (float*)sym(g_w2p);

    const int T = 256;
    auto gr = [](int n) { return (n + 255) / 256; };

    pack_all<<<gr(PKTOT), T>>>(fc1_w, fc2_w, mu_w, mu_b, lv_w, lv_b, g0_w, g1_w, w0, w2,
                               wfc1, wfc2, wmulv, bmulv, wg0, wg1, w0p, w2p);
    zc_fill_c<<<gr(B_ * 272), T>>>(zc, c);

    // ---- encoder fc1: split-K 4 (9,9,9,7), grid 256 ----
    cat2<<<gr(B_ * KP_FC1), T>>>(enc, KP_FC1, x, 267, c, 267);
    gemm3<0><<<dim3(4, 16, 4), T>>>(enc, KP_FC1, nullptr, nullptr, wfc1, H_,
                                    part, H_, (long)B_ * H_, H_, 34, 9, nullptr, 0);
    combine<<<gr(B_ * H_), T>>>(part, 4, H_, h1, H_, H_, fc1_b, nullptr, nullptr, 0, 1);

    // ---- encoder fc2: split-K 4 (9,9,9,6) ----
    cat2<<<gr(B_ * KP_FC2), T>>>(enc, KP_FC2, x, 267, h1, 256);
    gemm3<0><<<dim3(4, 16, 4), T>>>(enc, KP_FC2, nullptr, nullptr, wfc2, H_,
                                    part, H_, (long)B_ * H_, H_, 33, 9, nullptr, 0);
    combine<<<gr(B_ * H_), T>>>(part, 4, H_, h2, H_, H_, fc2_b, nullptr, nullptr, 0, 1);

    // ---- mu/lv: split-K 6 (6,6,6,6,6,3) ----
    cat2<<<gr(B_ * KP_FC2), T>>>(enc, KP_FC2, x, 267, h2, 256);
    gemm3<0><<<dim3(1, 16, 6), T>>>(enc, KP_FC2, nullptr, nullptr, wmulv, 64,
                                    part, 64, (long)B_ * 64, 64, 33, 6, nullptr, 0);
    combine<<<gr(B_ * 64), T>>>(part, 6, 64, mulv, 64, 64, bmulv, nullptr, nullptr, 0, 0);

    // z (also fills zc[:, :32]), mu/logvar outputs
    z_eps_kernel<<<gr(B_ * L_), T>>>(z, zc, mulv, out_mu, out_lv);

    // ---- gate ----
    gemm3<0><<<dim3(1, 16, 4), T>>>(zc, KP_ZC, nullptr, nullptr, wg0, G_,
                                    part, G_, (long)B_ * G_, G_, 19, 5, nullptr, 0);
    combine<<<gr(B_ * G_), T>>>(part, 4, G_, g0o, G_, G_, g0_b, nullptr, nullptr, 0, 1);
    gemm3<0><<<dim3(1, 16, 1), T>>>(g0o, G_, nullptr, nullptr, wg1, G_,
                                    g1o, G_, 0, G_, 4, 4, g1_b, 1);
    gate_final<<<gr(B_ * 32), T>>>(g1o, g2_w, g2_b, coef);

    // ---- decoder (split-K 8 exact, A built on-the-fly) ----
    gemm3<1><<<dim3(4, 16, 8), T>>>(zc, KP_ZC, nullptr, coef, w0p, H_,
                                    part, H_, (long)B_ * H_, H_, 152, 19, nullptr, 0);
    combine<<<gr(B_ * H_), T>>>(part, 8, H_, d0, H_, H_, nullptr, coef, b0, 256, 1);

    gemm3<2><<<dim3(4, 16, 8), T>>>(d0, H_, z, coef, w1, H_,
                                    part, H_, (long)B_ * H_, H_, 144, 18, nullptr, 0);
    combine<<<gr(B_ * H_), T>>>(part, 8, H_, d1, H_, H_, nullptr, coef, b1, 256, 1);

    gemm3<2><<<dim3(5, 16, 8), T>>>(d1, H_, z, coef, w2p, NP_W2,
                                    part, NP_W2, (long)B_ * NP_W2, NP_W2, 144, 18, nullptr, 0);
    combine<<<gr(B_ * 267), T>>>(part, 8, NP_W2, out_layer, 267, 267, nullptr, coef, b2, 267, 0);
}

// round 8
// speedup vs baseline: 2.7610x; 1.3034x over previous
#include <cuda_runtime.h>
#include <cuda_bf16.h>
#include <cstdint>

// ---------------- problem dims ----------------
#define B_   2048
#define F_   267
#define L_   32
#define H_   256
#define E_   8
#define G_   64

#define KP_FC1 544            // 534 -> 544 (34 tiles)
#define KP_FC2 528            // 523 -> 528 (33 tiles)
#define KP_ZC  304            // 299 -> 304
#define IN1_   288            // 32 + 256
#define NP_W2  320            // 267 -> 320

#define SPLIT_MAX 8

// tensor-path tiling (k-chunks of 64)
#define KT_L0 38              // 2432 / 64
#define KT_L12 36             // 2304 / 64
#define NT_L01 4              // 256 / 64
#define NT_L2 5               // 320 / 64
#define WT0_SZ (NT_L01*KT_L0*4096)
#define WT1_SZ (NT_L01*KT_L12*4096)
#define WT2_SZ (NT_L2*KT_L12*4096)

// ---------------- device scratch ----------------
__device__ __align__(16) float g_enc  [B_*KP_FC1];
__device__ __align__(16) float g_h1   [B_*H_];
__device__ __align__(16) float g_h2   [B_*H_];
__device__ __align__(16) float g_mulv [B_*64];
__device__ __align__(16) float g_z    [B_*L_];
__device__ __align__(16) float g_zc   [B_*KP_ZC];
__device__ __align__(16) float g_g0o  [B_*G_];
__device__ __align__(16) float g_g1o  [B_*G_];
__device__ __align__(16) float g_coef [B_*E_];
__device__ __align__(16) float g_d0   [B_*H_];
__device__ __align__(16) float g_d1   [B_*H_];
__device__ __align__(16) float g_part [SPLIT_MAX*B_*NP_W2];
// packed weights (FFMA path)
__device__ __align__(16) float g_wfc1 [KP_FC1*H_];
__device__ __align__(16) float g_wfc2 [KP_FC2*H_];
__device__ __align__(16) float g_wmulv[KP_FC2*64];
__device__ __align__(16) float g_bmulv[64];
__device__ __align__(16) float g_wg0  [KP_ZC*G_];
__device__ __align__(16) float g_wg1  [G_*G_];
// tensor-path weights: W^T bf16 hi/lo, tiles [ntile][ktile][64n][64k] (plain layout)
__device__ __align__(16) __nv_bfloat16 g_wt0h[WT0_SZ];
__device__ __align__(16) __nv_bfloat16 g_wt0l[WT0_SZ];
__device__ __align__(16) __nv_bfloat16 g_wt1h[WT1_SZ];
__device__ __align__(16) __nv_bfloat16 g_wt1l[WT1_SZ];
__device__ __align__(16) __nv_bfloat16 g_wt2h[WT2_SZ];
__device__ __align__(16) __nv_bfloat16 g_wt2l[WT2_SZ];

__device__ __forceinline__ float elu1(float v) { return v > 0.f ? v : expm1f(v); }

// ---------------- f32x2 helpers (FFMA path) ----------------
__device__ __forceinline__ unsigned long long ff2(unsigned long long a,
                                                  unsigned long long b,
                                                  unsigned long long c) {
    unsigned long long d;
    asm("fma.rn.f32x2 %0, %1, %2, %3;" : "=l"(d) : "l"(a), "l"(b), "l"(c));
    return d;
}
__device__ __forceinline__ unsigned long long dup2(float x) {
    unsigned long long d;
    asm("mov.b64 %0, {%1, %1};" : "=l"(d) : "f"(x));
    return d;
}

// ---------------- mma.sync helpers (plain sm_80+ ISA; assembles for sm_103) ----------------
__device__ __forceinline__ uint32_t smem_u32(const void* p) {
    uint32_t a;
    asm("{ .reg .u64 t; cvta.to.shared.u64 t, %1; cvt.u32.u64 %0, t; }" : "=r"(a) : "l"(p));
    return a;
}
__device__ __forceinline__ void ldsm_x4(uint32_t* r, uint32_t addr) {
    asm volatile("ldmatrix.sync.aligned.m8n8.x4.shared.b16 {%0,%1,%2,%3}, [%4];"
                 : "=r"(r[0]), "=r"(r[1]), "=r"(r[2]), "=r"(r[3]) : "r"(addr));
}
__device__ __forceinline__ void mma16816(float* c, const uint32_t* a, const uint32_t* b) {
    asm volatile("mma.sync.aligned.m16n8k16.row.col.f32.bf16.bf16.f32 "
                 "{%0,%1,%2,%3}, {%4,%5,%6,%7}, {%8,%9}, {%0,%1,%2,%3};"
                 : "+f"(c[0]), "+f"(c[1]), "+f"(c[2]), "+f"(c[3])
                 : "r"(a[0]), "r"(a[1]), "r"(a[2]), "r"(a[3]), "r"(b[0]), "r"(b[1]));
}

// ---------------- mega-pack (FFMA weights) ----------------
#define PK0 (KP_FC1*H_)
#define PK1 (KP_FC2*H_)
#define PK2 (KP_FC2*64)
#define PK3 64
#define PK4 (KP_ZC*G_)
#define PK5 (G_*G_)
#define PKTOT (PK0+PK1+PK2+PK3+PK4+PK5)

__global__ void pack_all(const float* __restrict__ fc1_w, const float* __restrict__ fc2_w,
                         const float* __restrict__ mu_w, const float* __restrict__ mu_b,
                         const float* __restrict__ lv_w, const float* __restrict__ lv_b,
                         const float* __restrict__ g0_w, const float* __restrict__ g1_w,
                         float* __restrict__ wfc1, float* __restrict__ wfc2,
                         float* __restrict__ wmulv, float* __restrict__ bmulv,
                         float* __restrict__ wg0, float* __restrict__ wg1) {
    int idx = blockIdx.x * blockDim.x + threadIdx.x;
    if (idx >= PKTOT) return;
    if (idx < PK0) {
        int k = idx / H_, n = idx % H_;
        wfc1[idx] = (k < 534) ? fc1_w[n * 534 + k] : 0.f;
        return;
    } idx -= PK0;
    if (idx < PK1) {
        int k = idx / H_, n = idx % H_;
        wfc2[idx] = (k < 523) ? fc2_w[n * 523 + k] : 0.f;
        return;
    } idx -= PK1;
    if (idx < PK2) {
        int k = idx / 64, n = idx % 64;
        float v = 0.f;
        if (k < 523) v = (n < 32) ? mu_w[n * 523 + k] : lv_w[(n - 32) * 523 + k];
        wmulv[idx] = v;
        return;
    } idx -= PK2;
    if (idx < PK3) {
        bmulv[idx] = (idx < 32) ? mu_b[idx] : lv_b[idx - 32];
        return;
    } idx -= PK3;
    if (idx < PK4) {
        int k = idx / G_, n = idx % G_;
        wg0[idx] = (k < 299) ? g0_w[n * 299 + k] : 0.f;
        return;
    } idx -= PK4;
    {
        int k = idx / G_, n = idx % G_;
        wg1[idx] = g1_w[n * G_ + k];
    }
}

// ---------------- tensor weight pack: W^T bf16 hi/lo, plain [64n][64k] tiles ----------------
__global__ void tpack(const float* __restrict__ w0, const float* __restrict__ w1,
                      const float* __restrict__ w2,
                      __nv_bfloat16* __restrict__ wt0h, __nv_bfloat16* __restrict__ wt0l,
                      __nv_bfloat16* __restrict__ wt1h, __nv_bfloat16* __restrict__ wt1l,
                      __nv_bfloat16* __restrict__ wt2h, __nv_bfloat16* __restrict__ wt2l) {
    int idx = blockIdx.x * blockDim.x + threadIdx.x;
    int layer, KT;
    __nv_bfloat16 *dh, *dl;
    if (idx < WT0_SZ) { layer = 0; KT = KT_L0; dh = wt0h; dl = wt0l; }
    else if (idx < WT0_SZ + WT1_SZ) { idx -= WT0_SZ; layer = 1; KT = KT_L12; dh = wt1h; dl = wt1l; }
    else if (idx < WT0_SZ + WT1_SZ + WT2_SZ) { idx -= WT0_SZ + WT1_SZ; layer = 2; KT = KT_L12; dh = wt2h; dl = wt2l; }
    else return;
    int tile = idx >> 12, u = idx & 4095;
    int ntile = tile / KT, kt = tile % KT;
    int nrow = u >> 6, kc = u & 63;
    int n = ntile * 64 + nrow;
    int kg = kt * 64 + kc;
    float w = 0.f;
    if (layer == 0) {
        int e = kg / KP_ZC, i = kg - e * KP_ZC;
        if (i < 299) w = w0[((size_t)(e * 299 + i)) * 256 + n];
    } else if (layer == 1) {
        w = w1[(size_t)kg * 256 + n];
    } else {
        if (n < 267) w = w2[(size_t)kg * 267 + n];
    }
    __nv_bfloat16 hi = __float2bfloat16(w);
    __nv_bfloat16 lo = __float2bfloat16(w - __bfloat162float(hi));
    size_t dst = ((size_t)tile << 12) + u;
    dh[dst] = hi;
    dl[dst] = lo;
}

// ---------------- concat / fill kernels ----------------
__global__ void cat2(float* __restrict__ dst, int Kp,
                     const float* __restrict__ s1, int l1,
                     const float* __restrict__ s2, int l2) {
    int idx = blockIdx.x * blockDim.x + threadIdx.x;
    if (idx >= B_ * Kp) return;
    int b = idx / Kp, k = idx % Kp;
    float v = 0.f;
    if (k < l1)           v = s1[b * l1 + k];
    else if (k < l1 + l2) v = s2[b * l2 + (k - l1)];
    dst[idx] = v;
}

__global__ void zc_fill_c(float* __restrict__ zc, const float* __restrict__ c) {
    int idx = blockIdx.x * blockDim.x + threadIdx.x;
    if (idx >= B_ * 272) return;
    int b = idx / 272, k = 32 + idx % 272;
    zc[b * KP_ZC + k] = (k < 299) ? c[b * 267 + (k - 32)] : 0.f;
}

// ---------------- threefry (partitionable) + XLA erfinv ----------------
__device__ __forceinline__ uint32_t rotl32(uint32_t v, int d) { return (v << d) | (v >> (32 - d)); }
__device__ __forceinline__ void tf4(uint32_t& x0, uint32_t& x1, int r0, int r1, int r2, int r3) {
    x0 += x1; x1 = rotl32(x1, r0); x1 ^= x0;
    x0 += x1; x1 = rotl32(x1, r1); x1 ^= x0;
    x0 += x1; x1 = rotl32(x1, r2); x1 ^= x0;
    x0 += x1; x1 = rotl32(x1, r3); x1 ^= x0;
}
__device__ __forceinline__ void threefry2x32(uint32_t k0, uint32_t k1, uint32_t& x0, uint32_t& x1) {
    uint32_t k2 = k0 ^ k1 ^ 0x1BD11BDAu;
    x0 += k0; x1 += k1;
    tf4(x0, x1, 13, 15, 26, 6);  x0 += k1; x1 += k2 + 1u;
    tf4(x0, x1, 17, 29, 16, 24); x0 += k2; x1 += k0 + 2u;
    tf4(x0, x1, 13, 15, 26, 6);  x0 += k0; x1 += k1 + 3u;
    tf4(x0, x1, 17, 29, 16, 24); x0 += k1; x1 += k2 + 4u;
    tf4(x0, x1, 13, 15, 26, 6);  x0 += k2; x1 += k0 + 5u;
}
__device__ __forceinline__ float erfinv_xla(float x) {
    float w = -log1pf(-x * x);
    float p;
    if (w < 5.0f) {
        w -= 2.5f;
        p = 2.81022636e-08f;
        p = fmaf(p, w, 3.43273939e-07f);
        p = fmaf(p, w, -3.5233877e-06f);
        p = fmaf(p, w, -4.39150654e-06f);
        p = fmaf(p, w, 0.00021858087f);
        p = fmaf(p, w, -0.00125372503f);
        p = fmaf(p, w, -0.00417768164f);
        p = fmaf(p, w, 0.246640727f);
        p = fmaf(p, w, 1.50140941f);
    } else {
        w = sqrtf(w) - 3.0f;
        p = -0.000200214257f;
        p = fmaf(p, w, 0.000100950558f);
        p = fmaf(p, w, 0.00134934322f);
        p = fmaf(p, w, -0.00367342844f);
        p = fmaf(p, w, 0.00573950773f);
        p = fmaf(p, w, -0.0076224613f);
        p = fmaf(p, w, 0.00943887047f);
        p = fmaf(p, w, 1.00167406f);
        p = fmaf(p, w, 2.83297682f);
    }
    return p * x;
}

__global__ void z_eps_kernel(float* __restrict__ zout, float* __restrict__ zc,
                             const float* __restrict__ mulv,
                             float* __restrict__ out_mu, float* __restrict__ out_lv) {
    int i = blockIdx.x * blockDim.x + threadIdx.x;
    if (i >= B_ * L_) return;
    uint32_t x0 = 0u, x1 = (uint32_t)i;
    threefry2x32(0u, 42u, x0, x1);
    uint32_t bits = x0 ^ x1;
    float f = __uint_as_float((bits >> 9) | 0x3f800000u) - 1.0f;
    const float lo = -0.99999994f;
    float u = fmaxf(lo, fmaf(f, 2.0f, lo));
    float eps = 1.41421354f * erfinv_xla(u);
    int b = i >> 5, l = i & 31;
    float mu = mulv[b * 64 + l];
    float lv = mulv[b * 64 + 32 + l];
    float zv = fmaf(eps, expf(0.5f * lv), mu);
    zout[i] = zv;
    zc[b * KP_ZC + l] = zv;
    out_mu[i] = mu;
    out_lv[i] = lv;
}

// ---------------- gate final (g2 + softmax) ----------------
__global__ void gate_final(const float* __restrict__ g1o, const float* __restrict__ g2w,
                           const float* __restrict__ g2b, float* __restrict__ coeff) {
    int gtid = blockIdx.x * blockDim.x + threadIdx.x;
    int row = gtid >> 5, lane = gtid & 31;
    if (row >= B_) return;
    float logit = 0.f;
    if (lane < E_) {
        logit = g2b[lane];
        const float* r = g1o + row * G_;
        const float* w = g2w + lane * G_;
        #pragma unroll 8
        for (int k = 0; k < G_; k++) logit = fmaf(r[k], w[k], logit);
    }
    float m = logit;
    for (int d = 4; d > 0; d >>= 1) m = fmaxf(m, __shfl_xor_sync(0xffffffffu, m, d));
    float ex = (lane < E_) ? expf(logit - m) : 0.f;
    float s = ex;
    for (int d = 4; d > 0; d >>= 1) s += __shfl_xor_sync(0xffffffffu, s, d);
    if (lane < E_) coeff[row * E_ + lane] = ex / s;
}

// ---------------- FFMA GEMM (encoder + gate): BM=128, BN=64, 8x4 f32x2 ----------------
__global__ void __launch_bounds__(256) gemm3(
    const float* __restrict__ A, int lda,
    const float* __restrict__ W, int ldw,
    float* __restrict__ C, int ldc, long sliceStride, int Nout,
    int ktTot, int ktPer,
    const float* __restrict__ bias, int act)
{
    __shared__ __align__(16) float As[2][16][132];
    __shared__ __align__(16) float Bs[2][16][68];

    int tid = threadIdx.x;
    int m0 = blockIdx.y * 128;
    int n0 = blockIdx.x * 64;
    int kt0 = blockIdx.z * ktPer;
    int ktn = min(ktPer, ktTot - kt0);
    float* Cp = C + (long)blockIdx.z * sliceStride;

    int tx = tid & 15, ty = tid >> 4;
    int arow = tid >> 2, acol = (tid & 3) << 2;
    int brow = tid >> 4, bcol = (tid & 15) << 2;

    const float* Wp = W + (size_t)brow * ldw + n0 + bcol;
    int am0 = m0 + arow, am1 = m0 + arow + 64;

    unsigned long long acc[4][4];
    #pragma unroll
    for (int q = 0; q < 4; q++)
        #pragma unroll
        for (int j = 0; j < 4; j++) acc[q][j] = 0ull;

    float4 av0 = *(const float4*)(A + (size_t)am0 * lda + (kt0 << 4) + acol);
    float4 av1 = *(const float4*)(A + (size_t)am1 * lda + (kt0 << 4) + acol);
    float4 bv  = *(const float4*)(Wp + (size_t)(kt0 << 4) * ldw);

    As[0][acol + 0][arow] = av0.x;
    As[0][acol + 1][arow] = av0.y;
    As[0][acol + 2][arow] = av0.z;
    As[0][acol + 3][arow] = av0.w;
    As[0][acol + 0][arow + 64] = av1.x;
    As[0][acol + 1][arow + 64] = av1.y;
    As[0][acol + 2][arow + 64] = av1.z;
    As[0][acol + 3][arow + 64] = av1.w;
    *(float4*)&Bs[0][brow][bcol] = bv;
    __syncthreads();

    for (int t = 0; t < ktn; t++) {
        int buf = t & 1;
        bool more = (t + 1) < ktn;
        if (more) {
            int kk = (kt0 + t + 1) << 4;
            av0 = *(const float4*)(A + (size_t)am0 * lda + kk + acol);
            av1 = *(const float4*)(A + (size_t)am1 * lda + kk + acol);
            bv  = *(const float4*)(Wp + (size_t)kk * ldw);
        }
        #pragma unroll
        for (int k = 0; k < 16; k++) {
            ulonglong2 a01 = *(const ulonglong2*)&As[buf][k][ty << 3];
            ulonglong2 a23 = *(const ulonglong2*)&As[buf][k][(ty << 3) + 4];
            float4 b4 = *(const float4*)&Bs[buf][k][tx << 2];
            unsigned long long bd0 = dup2(b4.x);
            unsigned long long bd1 = dup2(b4.y);
            unsigned long long bd2 = dup2(b4.z);
            unsigned long long bd3 = dup2(b4.w);
            acc[0][0] = ff2(a01.x, bd0, acc[0][0]);
            acc[0][1] = ff2(a01.x, bd1, acc[0][1]);
            acc[0][2] = ff2(a01.x, bd2, acc[0][2]);
            acc[0][3] = ff2(a01.x, bd3, acc[0][3]);
            acc[1][0] = ff2(a01.y, bd0, acc[1][0]);
            acc[1][1] = ff2(a01.y, bd1, acc[1][1]);
            acc[1][2] = ff2(a01.y, bd2, acc[1][2]);
            acc[1][3] = ff2(a01.y, bd3, acc[1][3]);
            acc[2][0] = ff2(a23.x, bd0, acc[2][0]);
            acc[2][1] = ff2(a23.x, bd1, acc[2][1]);
            acc[2][2] = ff2(a23.x, bd2, acc[2][2]);
            acc[2][3] = ff2(a23.x, bd3, acc[2][3]);
            acc[3][0] = ff2(a23.y, bd0, acc[3][0]);
            acc[3][1] = ff2(a23.y, bd1, acc[3][1]);
            acc[3][2] = ff2(a23.y, bd2, acc[3][2]);
            acc[3][3] = ff2(a23.y, bd3, acc[3][3]);
        }
        if (more) {
            int nb = buf ^ 1;
            As[nb][acol + 0][arow] = av0.x;
            As[nb][acol + 1][arow] = av0.y;
            As[nb][acol + 2][arow] = av0.z;
            As[nb][acol + 3][arow] = av0.w;
            As[nb][acol + 0][arow + 64] = av1.x;
            As[nb][acol + 1][arow + 64] = av1.y;
            As[nb][acol + 2][arow + 64] = av1.z;
            As[nb][acol + 3][arow + 64] = av1.w;
            *(float4*)&Bs[nb][brow][bcol] = bv;
        }
        __syncthreads();
    }

    float cres[8][4];
    #pragma unroll
    for (int q = 0; q < 4; q++)
        #pragma unroll
        for (int j = 0; j < 4; j++) {
            float lo, hi;
            asm("mov.b64 {%0, %1}, %2;" : "=f"(lo), "=f"(hi) : "l"(acc[q][j]));
            cres[2 * q][j] = lo;
            cres[2 * q + 1][j] = hi;
        }

    int n = n0 + (tx << 2);
    float4 bsv = make_float4(0.f, 0.f, 0.f, 0.f);
    if (bias) bsv = *(const float4*)(bias + n);
    #pragma unroll
    for (int r = 0; r < 8; r++) {
        int m = m0 + (ty << 3) + r;
        float4 v;
        v.x = cres[r][0] + bsv.x;
        v.y = cres[r][1] + bsv.y;
        v.z = cres[r][2] + bsv.z;
        v.w = cres[r][3] + bsv.w;
        if (act) { v.x = elu1(v.x); v.y = elu1(v.y); v.z = elu1(v.z); v.w = elu1(v.w); }
        if (n < Nout) *(float4*)(Cp + (size_t)m * ldc + n) = v;
    }
}

// ---------------- mma.sync decoder GEMM ----------------
// smem stage: Ah(128x72 bf16) Al Bh(64x72) Bl; stride 72 bf16 = 144 B.
#define LDS_AB 144
#define TS_A 18432
#define TS_B 9216
#define TSTAGE (2*TS_A + 2*TS_B)      // 55296
#define TSM_TOTAL (2*TSTAGE)          // 110592

template <int MODE>   // 1: src=zc (KP_ZC); 2: src=d + z (IN1_)
__global__ void __launch_bounds__(256) tgemm(
    const float* __restrict__ src,
    const float* __restrict__ z,
    const float* __restrict__ coeff,
    const __nv_bfloat16* __restrict__ wth,
    const __nv_bfloat16* __restrict__ wtl,
    float* __restrict__ C, int ldc, long sliceStride,
    int ktTot, int ktPer, int KT)
{
    extern __shared__ __align__(16) char smem[];
    uint32_t sb = smem_u32(smem);
    int tid = threadIdx.x;
    int wid = tid >> 5, lane = tid & 31;
    int wm = wid >> 1, wn = wid & 1;
    int m0 = blockIdx.y * 128;
    int ntile = blockIdx.x, n0 = ntile * 64;
    int kt0 = blockIdx.z * ktPer;
    int ktn = min(ktPer, ktTot - kt0);
    float* Cp = C + (long)blockIdx.z * sliceStride;

    float acc[2][4][4];
    #pragma unroll
    for (int mt = 0; mt < 2; mt++)
        #pragma unroll
        for (int nt = 0; nt < 4; nt++)
            #pragma unroll
            for (int j = 0; j < 4; j++) acc[mt][nt][j] = 0.f;

    // ---- fill stage `buf` with k-chunk kt ----
    auto fill = [&](int kt, int buf) {
        char* st = smem + buf * TSTAGE;
        #pragma unroll
        for (int gq = 0; gq < 4; gq++) {
            int g = tid + gq * 256;
            int row = g >> 3, c8 = g & 7;
            int m = m0 + row;
            int kg = (kt << 6) + (c8 << 3);
            float4 f0, f1;
            float cf;
            if (MODE == 1) {
                int e = kg / KP_ZC, i = kg - e * KP_ZC;
                cf = coeff[m * E_ + e];
                f0 = *(const float4*)(src + (size_t)m * KP_ZC + i);
                f1 = *(const float4*)(src + (size_t)m * KP_ZC + i + 4);
            } else {
                int e = kg / IN1_, i = kg - e * IN1_;
                cf = coeff[m * E_ + e];
                if (i < L_) {
                    f0 = *(const float4*)(z + (size_t)m * L_ + i);
                    f1 = *(const float4*)(z + (size_t)m * L_ + i + 4);
                } else {
                    f0 = *(const float4*)(src + (size_t)m * H_ + (i - L_));
                    f1 = *(const float4*)(src + (size_t)m * H_ + (i - L_) + 4);
                }
            }
            float v[8] = { cf * f0.x, cf * f0.y, cf * f0.z, cf * f0.w,
                           cf * f1.x, cf * f1.y, cf * f1.z, cf * f1.w };
            union { __nv_bfloat16 b[8]; uint4 u; } hv, lv;
            #pragma unroll
            for (int j = 0; j < 8; j++) {
                __nv_bfloat16 h = __float2bfloat16(v[j]);
                hv.b[j] = h;
                lv.b[j] = __float2bfloat16(v[j] - __bfloat162float(h));
            }
            *(uint4*)(st + row * LDS_AB + c8 * 16) = hv.u;
            *(uint4*)(st + TS_A + row * LDS_AB + c8 * 16) = lv.u;
        }
        const char* th = (const char*)(wth + ((size_t)(ntile * KT + kt) << 12));
        const char* tl = (const char*)(wtl + ((size_t)(ntile * KT + kt) << 12));
        #pragma unroll
        for (int gq = 0; gq < 2; gq++) {
            int g = tid + gq * 256;
            int n = g >> 3, seg = g & 7;
            *(uint4*)(st + 2 * TS_A + n * LDS_AB + seg * 16) = *(const uint4*)(th + n * 128 + seg * 16);
            *(uint4*)(st + 2 * TS_A + TS_B + n * LDS_AB + seg * 16) = *(const uint4*)(tl + n * 128 + seg * 16);
        }
    };

    fill(kt0, 0);
    __syncthreads();

    for (int t = 0; t < ktn; t++) {
        int buf = t & 1;
        if (t + 1 < ktn) fill(kt0 + t + 1, buf ^ 1);

        uint32_t sA = sb + buf * TSTAGE;
        uint32_t sB = sA + 2 * TS_A;
        int arow = wm * 32 + (lane & 15);
        int bn = wn * 32 + ((lane >> 4) << 3) + (lane & 7);
        int bkl = ((lane >> 3) & 1) << 3;
        #pragma unroll
        for (int ks = 0; ks < 4; ks++) {
            uint32_t ah0[4], ah1[4], al0[4], al1[4];
            uint32_t bh0[4], bh1[4], bl0[4], bl1[4];
            uint32_t aAdr = sA + arow * LDS_AB + (ks * 16 + (lane >> 4) * 8) * 2;
            ldsm_x4(ah0, aAdr);
            ldsm_x4(ah1, aAdr + 16 * LDS_AB);
            ldsm_x4(al0, aAdr + TS_A);
            ldsm_x4(al1, aAdr + TS_A + 16 * LDS_AB);
            uint32_t bAdr = sB + bn * LDS_AB + (ks * 16 + bkl) * 2;
            ldsm_x4(bh0, bAdr);
            ldsm_x4(bh1, bAdr + 16 * LDS_AB);
            ldsm_x4(bl0, bAdr + TS_B);
            ldsm_x4(bl1, bAdr + TS_B + 16 * LDS_AB);

            // AhBh
            mma16816(acc[0][0], ah0, bh0);     mma16816(acc[0][1], ah0, bh0 + 2);
            mma16816(acc[0][2], ah0, bh1);     mma16816(acc[0][3], ah0, bh1 + 2);
            mma16816(acc[1][0], ah1, bh0);     mma16816(acc[1][1], ah1, bh0 + 2);
            mma16816(acc[1][2], ah1, bh1);     mma16816(acc[1][3], ah1, bh1 + 2);
            // AhBl
            mma16816(acc[0][0], ah0, bl0);     mma16816(acc[0][1], ah0, bl0 + 2);
            mma16816(acc[0][2], ah0, bl1);     mma16816(acc[0][3], ah0, bl1 + 2);
            mma16816(acc[1][0], ah1, bl0);     mma16816(acc[1][1], ah1, bl0 + 2);
            mma16816(acc[1][2], ah1, bl1);     mma16816(acc[1][3], ah1, bl1 + 2);
            // AlBh
            mma16816(acc[0][0], al0, bh0);     mma16816(acc[0][1], al0, bh0 + 2);
            mma16816(acc[0][2], al0, bh1);     mma16816(acc[0][3], al0, bh1 + 2);
            mma16816(acc[1][0], al1, bh0);     mma16816(acc[1][1], al1, bh0 + 2);
            mma16816(acc[1][2], al1, bh1);     mma16816(acc[1][3], al1, bh1 + 2);
        }
        __syncthreads();
    }

    // epilogue: write raw partials (combine adds bias/ELU)
    #pragma unroll
    for (int mt = 0; mt < 2; mt++)
        #pragma unroll
        for (int nt = 0; nt < 4; nt++) {
            int m = m0 + wm * 32 + mt * 16 + (lane >> 2);
            int n = n0 + wn * 32 + nt * 8 + ((lane & 3) << 1);
            *(float2*)(Cp + (size_t)m * ldc + n) = make_float2(acc[mt][nt][0], acc[mt][nt][1]);
            *(float2*)(Cp + (size_t)(m + 8) * ldc + n) = make_float2(acc[mt][nt][2], acc[mt][nt][3]);
        }
}

// ---------------- split-K combine with epilogue ----------------
__global__ void combine(const float* __restrict__ part, int S, int ldp,
                        float* __restrict__ C, int ldc, int Nout,
                        const float* __restrict__ bias,
                        const float* __restrict__ coeff,
                        const float* __restrict__ ebias, int ebld,
                        int act)
{
    int idx = blockIdx.x * blockDim.x + threadIdx.x;
    if (idx >= B_ * Nout) return;
    int m = idx / Nout, n = idx % Nout;
    float v = 0.f;
    for (int s = 0; s < S; s++) v += part[(size_t)s * B_ * ldp + (size_t)m * ldp + n];
    if (bias) v += bias[n];
    if (ebias) {
        const float* cf = coeff + m * E_;
        float bm = 0.f;
        #pragma unroll
        for (int e = 0; e < E_; e++) bm = fmaf(cf[e], ebias[e * ebld + n], bm);
        v += bm;
    }
    if (act) v = elu1(v);
    C[(size_t)m * ldc + n] = v;
}

// ---------------- host launch ----------------
static inline void* sym(const void* s) { void* p = nullptr; cudaGetSymbolAddress(&p, s); return p; }

extern "C" void kernel_launch(void* const* d_in, const int* in_sizes, int n_in,
                              void* d_out, int out_size) {
    (void)in_sizes; (void)n_in; (void)out_size;
    const float* x     = (const float*)d_in[0];
    const float* c     = (const float*)d_in[1];
    const float* fc1_w = (const float*)d_in[2];
    const float* fc1_b = (const float*)d_in[3];
    const float* fc2_w = (const float*)d_in[4];
    const float* fc2_b = (const float*)d_in[5];
    const float* mu_w  = (const float*)d_in[6];
    const float* mu_b  = (const float*)d_in[7];
    const float* lv_w  = (const float*)d_in[8];
    const float* lv_b  = (const float*)d_in[9];
    const float* g0_w  = (const float*)d_in[10];
    const float* g0_b  = (const float*)d_in[11];
    const float* g1_w  = (const float*)d_in[12];
    const float* g1_b  = (const float*)d_in[13];
    const float* g2_w  = (const float*)d_in[14];
    const float* g2_b  = (const float*)d_in[15];
    const float* w0    = (const float*)d_in[16];
    const float* b0    = (const float*)d_in[17];
    const float* w1    = (const float*)d_in[18];
    const float* b1    = (const float*)d_in[19];
    const float* w2    = (const float*)d_in[20];
    const float* b2    = (const float*)d_in[21];

    float* out       = (float*)d_out;
    float* out_layer = out;
    float* out_mu    = out + B_ * F_;
    float* out_lv    = out + B_ * F_ + B_ * L_;

    float* enc   = (float*)sym(g_enc);
    float* h1    = (float*)sym(g_h1);
    float* h2    = (float*)sym(g_h2);
    float* mulv  = (float*)sym(g_mulv);
    float* z     = (float*)sym(g_z);
    float* zc    = (float*)sym(g_zc);
    float* g0o   = (float*)sym(g_g0o);
    float* g1o   = (float*)sym(g_g1o);
    float* coef  = (float*)sym(g_coef);
    float* d0    = (float*)sym(g_d0);
    float* d1    = (float*)sym(g_d1);
    float* part  = (float*)sym(g_part);
    float* wfc1  = (float*)sym(g_wfc1);
    float* wfc2  = (float*)sym(g_wfc2);
    float* wmulv = (float*)sym(g_wmulv);
    float* bmulv = (float*)sym(g_bmulv);
    float* wg0   = (float*)sym(g_wg0);
    float* wg1   = (float*)sym(g_wg1);
    __nv_bfloat16* wt0h = (__nv_bfloat16*)sym(g_wt0h);
    __nv_bfloat16* wt0l = (__nv_bfloat16*)sym(g_wt0l);
    __nv_bfloat16* wt1h = (__nv_bfloat16*)sym(g_wt1h);
    __nv_bfloat16* wt1l = (__nv_bfloat16*)sym(g_wt1l);
    __nv_bfloat16* wt2h = (__nv_bfloat16*)sym(g_wt2h);
    __nv_bfloat16* wt2l = (__nv_bfloat16*)sym(g_wt2l);

    cudaFuncSetAttribute(tgemm<1>, cudaFuncAttributeMaxDynamicSharedMemorySize, TSM_TOTAL);
    cudaFuncSetAttribute(tgemm<2>, cudaFuncAttributeMaxDynamicSharedMemorySize, TSM_TOTAL);

    const int T = 256;
    auto gr = [](int n) { return (n + 255) / 256; };

    pack_all<<<gr(PKTOT), T>>>(fc1_w, fc2_w, mu_w, mu_b, lv_w, lv_b, g0_w, g1_w,
                               wfc1, wfc2, wmulv, bmulv, wg0, wg1);
    tpack<<<gr(WT0_SZ + WT1_SZ + WT2_SZ), T>>>(w0, w1, w2, wt0h, wt0l, wt1h, wt1l, wt2h, wt2l);
    zc_fill_c<<<gr(B_ * 272), T>>>(zc, c);

    // ---- encoder fc1: split-K 4 ----
    cat2<<<gr(B_ * KP_FC1), T>>>(enc, KP_FC1, x, 267, c, 267);
    gemm3<<<dim3(4, 16, 4), T>>>(enc, KP_FC1, wfc1, H_,
                                 part, H_, (long)B_ * H_, H_, 34, 9, nullptr, 0);
    combine<<<gr(B_ * H_), T>>>(part, 4, H_, h1, H_, H_, fc1_b, nullptr, nullptr, 0, 1);

    // ---- encoder fc2: split-K 4 ----
    cat2<<<gr(B_ * KP_FC2), T>>>(enc, KP_FC2, x, 267, h1, 256);
    gemm3<<<dim3(4, 16, 4), T>>>(enc, KP_FC2, wfc2, H_,
                                 part, H_, (long)B_ * H_, H_, 33, 9, nullptr, 0);
    combine<<<gr(B_ * H_), T>>>(part, 4, H_, h2, H_, H_, fc2_b, nullptr, nullptr, 0, 1);

    // ---- mu/lv: split-K 6 ----
    cat2<<<gr(B_ * KP_FC2), T>>>(enc, KP_FC2, x, 267, h2, 256);
    gemm3<<<dim3(1, 16, 6), T>>>(enc, KP_FC2, wmulv, 64,
                                 part, 64, (long)B_ * 64, 64, 33, 6, nullptr, 0);
    combine<<<gr(B_ * 64), T>>>(part, 6, 64, mulv, 64, 64, bmulv, nullptr, nullptr, 0, 0);

    // z (also fills zc[:, :32]), mu/logvar outputs
    z_eps_kernel<<<gr(B_ * L_), T>>>(z, zc, mulv, out_mu, out_lv);

    // ---- gate ----
    gemm3<<<dim3(1, 16, 4), T>>>(zc, KP_ZC, wg0, G_,
                                 part, G_, (long)B_ * G_, G_, 19, 5, nullptr, 0);
    combine<<<gr(B_ * G_), T>>>(part, 4, G_, g0o, G_, G_, g0_b, nullptr, nullptr, 0, 1);
    gemm3<<<dim3(1, 16, 1), T>>>(g0o, G_, wg1, G_,
                                 g1o, G_, 0, G_, 4, 4, g1_b, 1);
    gate_final<<<gr(B_ * 32), T>>>(g1o, g2_w, g2_b, coef);

    // ---- decoder: mma.sync bf16 hi/lo, split-K 4 ----
    tgemm<1><<<dim3(NT_L01, 16, 4), T, TSM_TOTAL>>>(zc, nullptr, coef, wt0h, wt0l,
                                                    part, 256, (long)B_ * 256, KT_L0, 10, KT_L0);
    combine<<<gr(B_ * H_), T>>>(part, 4, 256, d0, H_, H_, nullptr, coef, b0, 256, 1);

    tgemm<2><<<dim3(NT_L01, 16, 4), T, TSM_TOTAL>>>(d0, z, coef, wt1h, wt1l,
                                                    part, 256, (long)B_ * 256, KT_L12, 9, KT_L12);
    combine<<<gr(B_ * H_), T>>>(part, 4, 256, d1, H_, H_, nullptr, coef, b1, 256, 1);

    tgemm<2><<<dim3(NT_L2, 16, 4), T, TSM_TOTAL>>>(d1, z, coef, wt2h, wt2l,
                                                   part, NP_W2, (long)B_ * NP_W2, KT_L12, 9, KT_L12);
    combine<<<gr(B_ * 267), T>>>(part, 4, NP_W2, out_layer, 267, 267, nullptr, coef, b2, 267, 0);
}

// round 9
// speedup vs baseline: 3.0680x; 1.1112x over previous
#include <cuda_runtime.h>
#include <cuda_bf16.h>
#include <cstdint>

// ---------------- problem dims ----------------
#define B_   2048
#define F_   267
#define L_   32
#define H_   256
#define E_   8
#define G_   64

#define KP_ENC 576            // encoder K pad: 534/523 -> 576 (9 chunks of 64)
#define KP_ZC  304            // 299 -> 304 (gate FFMA path)
#define IN1_   288            // 32 + 256
#define NP_W2  320            // 267 -> 320

#define SPLIT_MAX 9

// tensor-path tiling (k-chunks of 64)
#define KT_ENC 9
#define KT_L0 38
#define KT_L12 36
#define NT_L01 4
#define NT_L2 5
#define WTE1_SZ (4*KT_ENC*4096)
#define WTE2_SZ (4*KT_ENC*4096)
#define WTMV_SZ (1*KT_ENC*4096)
#define WT0_SZ (NT_L01*KT_L0*4096)
#define WT1_SZ (NT_L01*KT_L12*4096)
#define WT2_SZ (NT_L2*KT_L12*4096)

// ---------------- device scratch ----------------
__device__ __align__(16) float g_enc  [B_*KP_ENC];
__device__ __align__(16) float g_h1   [B_*H_];
__device__ __align__(16) float g_h2   [B_*H_];
__device__ __align__(16) float g_z    [B_*L_];
__device__ __align__(16) float g_zc   [B_*KP_ZC];
__device__ __align__(16) float g_g0o  [B_*G_];
__device__ __align__(16) float g_g1o  [B_*G_];
__device__ __align__(16) float g_coef [B_*E_];
__device__ __align__(16) float g_d0   [B_*H_];
__device__ __align__(16) float g_d1   [B_*H_];
__device__ __align__(16) float g_part [SPLIT_MAX*B_*NP_W2];
// FFMA-path weights (gate only)
__device__ __align__(16) float g_bmulv[64];
__device__ __align__(16) float g_wg0  [KP_ZC*G_];
__device__ __align__(16) float g_wg1  [G_*G_];
// tensor-path weights: bf16 hi/lo, tiles [ntile][ktile][64n][64k]
__device__ __align__(16) __nv_bfloat16 g_wte1h[WTE1_SZ];
__device__ __align__(16) __nv_bfloat16 g_wte1l[WTE1_SZ];
__device__ __align__(16) __nv_bfloat16 g_wte2h[WTE2_SZ];
__device__ __align__(16) __nv_bfloat16 g_wte2l[WTE2_SZ];
__device__ __align__(16) __nv_bfloat16 g_wtmvh[WTMV_SZ];
__device__ __align__(16) __nv_bfloat16 g_wtmvl[WTMV_SZ];
__device__ __align__(16) __nv_bfloat16 g_wt0h[WT0_SZ];
__device__ __align__(16) __nv_bfloat16 g_wt0l[WT0_SZ];
__device__ __align__(16) __nv_bfloat16 g_wt1h[WT1_SZ];
__device__ __align__(16) __nv_bfloat16 g_wt1l[WT1_SZ];
__device__ __align__(16) __nv_bfloat16 g_wt2h[WT2_SZ];
__device__ __align__(16) __nv_bfloat16 g_wt2l[WT2_SZ];

__device__ __forceinline__ float elu1(float v) { return v > 0.f ? v : expm1f(v); }

// ---------------- f32x2 helpers (FFMA gate path) ----------------
__device__ __forceinline__ unsigned long long ff2(unsigned long long a,
                                                  unsigned long long b,
                                                  unsigned long long c) {
    unsigned long long d;
    asm("fma.rn.f32x2 %0, %1, %2, %3;" : "=l"(d) : "l"(a), "l"(b), "l"(c));
    return d;
}
__device__ __forceinline__ unsigned long long dup2(float x) {
    unsigned long long d;
    asm("mov.b64 %0, {%1, %1};" : "=l"(d) : "f"(x));
    return d;
}

// ---------------- mma.sync helpers ----------------
__device__ __forceinline__ uint32_t smem_u32(const void* p) {
    uint32_t a;
    asm("{ .reg .u64 t; cvta.to.shared.u64 t, %1; cvt.u32.u64 %0, t; }" : "=r"(a) : "l"(p));
    return a;
}
__device__ __forceinline__ void ldsm_x4(uint32_t* r, uint32_t addr) {
    asm volatile("ldmatrix.sync.aligned.m8n8.x4.shared.b16 {%0,%1,%2,%3}, [%4];"
                 : "=r"(r[0]), "=r"(r[1]), "=r"(r[2]), "=r"(r[3]) : "r"(addr));
}
__device__ __forceinline__ void mma16816(float* c, const uint32_t* a, const uint32_t* b) {
    asm volatile("mma.sync.aligned.m16n8k16.row.col.f32.bf16.bf16.f32 "
                 "{%0,%1,%2,%3}, {%4,%5,%6,%7}, {%8,%9}, {%0,%1,%2,%3};"
                 : "+f"(c[0]), "+f"(c[1]), "+f"(c[2]), "+f"(c[3])
                 : "r"(a[0]), "r"(a[1]), "r"(a[2]), "r"(a[3]), "r"(b[0]), "r"(b[1]));
}

// ---------------- small pack (gate weights + mulv bias) ----------------
#define PK3 64
#define PK4 (KP_ZC*G_)
#define PK5 (G_*G_)
#define PKTOT (PK3+PK4+PK5)

__global__ void pack_all(const float* __restrict__ mu_b, const float* __restrict__ lv_b,
                         const float* __restrict__ g0_w, const float* __restrict__ g1_w,
                         float* __restrict__ bmulv, float* __restrict__ wg0,
                         float* __restrict__ wg1) {
    int idx = blockIdx.x * blockDim.x + threadIdx.x;
    if (idx >= PKTOT) return;
    if (idx < PK3) {
        bmulv[idx] = (idx < 32) ? mu_b[idx] : lv_b[idx - 32];
        return;
    } idx -= PK3;
    if (idx < PK4) {
        int k = idx / G_, n = idx % G_;
        wg0[idx] = (k < 299) ? g0_w[n * 299 + k] : 0.f;
        return;
    } idx -= PK4;
    {
        int k = idx / G_, n = idx % G_;
        wg1[idx] = g1_w[n * G_ + k];
    }
}

// ---------------- tensor weight pack: bf16 hi/lo, [64n][64k] tiles ----------------
__global__ void tpack(const float* __restrict__ fc1_w, const float* __restrict__ fc2_w,
                      const float* __restrict__ mu_w, const float* __restrict__ lv_w,
                      const float* __restrict__ w0, const float* __restrict__ w1,
                      const float* __restrict__ w2,
                      __nv_bfloat16* __restrict__ we1h, __nv_bfloat16* __restrict__ we1l,
                      __nv_bfloat16* __restrict__ we2h, __nv_bfloat16* __restrict__ we2l,
                      __nv_bfloat16* __restrict__ wmvh, __nv_bfloat16* __restrict__ wmvl,
                      __nv_bfloat16* __restrict__ wt0h, __nv_bfloat16* __restrict__ wt0l,
                      __nv_bfloat16* __restrict__ wt1h, __nv_bfloat16* __restrict__ wt1l,
                      __nv_bfloat16* __restrict__ wt2h, __nv_bfloat16* __restrict__ wt2l) {
    int idx = blockIdx.x * blockDim.x + threadIdx.x;
    int layer, KT;
    __nv_bfloat16 *dh, *dl;
    if (idx < WTE1_SZ) { layer = 0; KT = KT_ENC; dh = we1h; dl = we1l; }
    else if (idx < WTE1_SZ + WTE2_SZ) { idx -= WTE1_SZ; layer = 1; KT = KT_ENC; dh = we2h; dl = we2l; }
    else if (idx < WTE1_SZ + WTE2_SZ + WTMV_SZ) { idx -= WTE1_SZ + WTE2_SZ; layer = 2; KT = KT_ENC; dh = wmvh; dl = wmvl; }
    else if (idx < WTE1_SZ + WTE2_SZ + WTMV_SZ + WT0_SZ) { idx -= WTE1_SZ + WTE2_SZ + WTMV_SZ; layer = 3; KT = KT_L0; dh = wt0h; dl = wt0l; }
    else if (idx < WTE1_SZ + WTE2_SZ + WTMV_SZ + WT0_SZ + WT1_SZ) { idx -= WTE1_SZ + WTE2_SZ + WTMV_SZ + WT0_SZ; layer = 4; KT = KT_L12; dh = wt1h; dl = wt1l; }
    else if (idx < WTE1_SZ + WTE2_SZ + WTMV_SZ + WT0_SZ + WT1_SZ + WT2_SZ) { idx -= WTE1_SZ + WTE2_SZ + WTMV_SZ + WT0_SZ + WT1_SZ; layer = 5; KT = KT_L12; dh = wt2h; dl = wt2l; }
    else return;
    int tile = idx >> 12, u = idx & 4095;
    int ntile = tile / KT, kt = tile % KT;
    int nrow = u >> 6, kc = u & 63;
    int n = ntile * 64 + nrow;
    int kg = kt * 64 + kc;
    float w = 0.f;
    if (layer == 0) {                       // fc1_w [256,534]
        if (kg < 534) w = fc1_w[(size_t)n * 534 + kg];
    } else if (layer == 1) {                // fc2_w [256,523]
        if (kg < 523) w = fc2_w[(size_t)n * 523 + kg];
    } else if (layer == 2) {                // mu/lv [32,523] each
        if (kg < 523) w = (n < 32) ? mu_w[(size_t)n * 523 + kg]
                                   : lv_w[(size_t)(n - 32) * 523 + kg];
    } else if (layer == 3) {                // w0 [8,299,256]
        int e = kg / KP_ZC, i = kg - e * KP_ZC;
        if (i < 299) w = w0[((size_t)(e * 299 + i)) * 256 + n];
    } else if (layer == 4) {                // w1 [2304,256]
        w = w1[(size_t)kg * 256 + n];
    } else {                                // w2 [2304,267]
        if (n < 267) w = w2[(size_t)kg * 267 + n];
    }
    __nv_bfloat16 hi = __float2bfloat16(w);
    __nv_bfloat16 lo = __float2bfloat16(w - __bfloat162float(hi));
    size_t dst = ((size_t)tile << 12) + u;
    dh[dst] = hi;
    dl[dst] = lo;
}

// ---------------- concat / fill kernels ----------------
__global__ void cat2(float* __restrict__ dst, int Kp,
                     const float* __restrict__ s1, int l1,
                     const float* __restrict__ s2, int l2) {
    int idx = blockIdx.x * blockDim.x + threadIdx.x;
    if (idx >= B_ * Kp) return;
    int b = idx / Kp, k = idx % Kp;
    float v = 0.f;
    if (k < l1)           v = s1[b * l1 + k];
    else if (k < l1 + l2) v = s2[b * l2 + (k - l1)];
    dst[idx] = v;
}

__global__ void zc_fill_c(float* __restrict__ zc, const float* __restrict__ c) {
    int idx = blockIdx.x * blockDim.x + threadIdx.x;
    if (idx >= B_ * 272) return;
    int b = idx / 272, k = 32 + idx % 272;
    zc[b * KP_ZC + k] = (k < 299) ? c[b * 267 + (k - 32)] : 0.f;
}

// ---------------- threefry (partitionable) + XLA erfinv ----------------
__device__ __forceinline__ uint32_t rotl32(uint32_t v, int d) { return (v << d) | (v >> (32 - d)); }
__device__ __forceinline__ void tf4(uint32_t& x0, uint32_t& x1, int r0, int r1, int r2, int r3) {
    x0 += x1; x1 = rotl32(x1, r0); x1 ^= x0;
    x0 += x1; x1 = rotl32(x1, r1); x1 ^= x0;
    x0 += x1; x1 = rotl32(x1, r2); x1 ^= x0;
    x0 += x1; x1 = rotl32(x1, r3); x1 ^= x0;
}
__device__ __forceinline__ void threefry2x32(uint32_t k0, uint32_t k1, uint32_t& x0, uint32_t& x1) {
    uint32_t k2 = k0 ^ k1 ^ 0x1BD11BDAu;
    x0 += k0; x1 += k1;
    tf4(x0, x1, 13, 15, 26, 6);  x0 += k1; x1 += k2 + 1u;
    tf4(x0, x1, 17, 29, 16, 24); x0 += k2; x1 += k0 + 2u;
    tf4(x0, x1, 13, 15, 26, 6);  x0 += k0; x1 += k1 + 3u;
    tf4(x0, x1, 17, 29, 16, 24); x0 += k1; x1 += k2 + 4u;
    tf4(x0, x1, 13, 15, 26, 6);  x0 += k2; x1 += k0 + 5u;
}
__device__ __forceinline__ float erfinv_xla(float x) {
    float w = -log1pf(-x * x);
    float p;
    if (w < 5.0f) {
        w -= 2.5f;
        p = 2.81022636e-08f;
        p = fmaf(p, w, 3.43273939e-07f);
        p = fmaf(p, w, -3.5233877e-06f);
        p = fmaf(p, w, -4.39150654e-06f);
        p = fmaf(p, w, 0.00021858087f);
        p = fmaf(p, w, -0.00125372503f);
        p = fmaf(p, w, -0.00417768164f);
        p = fmaf(p, w, 0.246640727f);
        p = fmaf(p, w, 1.50140941f);
    } else {
        w = sqrtf(w) - 3.0f;
        p = -0.000200214257f;
        p = fmaf(p, w, 0.000100950558f);
        p = fmaf(p, w, 0.00134934322f);
        p = fmaf(p, w, -0.00367342844f);
        p = fmaf(p, w, 0.00573950773f);
        p = fmaf(p, w, -0.0076224613f);
        p = fmaf(p, w, 0.00943887047f);
        p = fmaf(p, w, 1.00167406f);
        p = fmaf(p, w, 2.83297682f);
    }
    return p * x;
}

// fused: combine mu/lv split-K partials + bias, then z = mu + eps*exp(lv/2)
__global__ void combine_zeps(const float* __restrict__ part, int S,
                             const float* __restrict__ bmulv,
                             float* __restrict__ zout, float* __restrict__ zc,
                             float* __restrict__ out_mu, float* __restrict__ out_lv) {
    int i = blockIdx.x * blockDim.x + threadIdx.x;
    if (i >= B_ * L_) return;
    int b = i >> 5, l = i & 31;
    float mu = bmulv[l], lv = bmulv[32 + l];
    for (int s = 0; s < S; s++) {
        const float* p = part + (size_t)s * B_ * 64 + (size_t)b * 64;
        mu += p[l];
        lv += p[32 + l];
    }
    uint32_t x0 = 0u, x1 = (uint32_t)i;
    threefry2x32(0u, 42u, x0, x1);
    uint32_t bits = x0 ^ x1;
    float f = __uint_as_float((bits >> 9) | 0x3f800000u) - 1.0f;
    const float lo = -0.99999994f;
    float u = fmaxf(lo, fmaf(f, 2.0f, lo));
    float eps = 1.41421354f * erfinv_xla(u);
    float zv = fmaf(eps, expf(0.5f * lv), mu);
    zout[i] = zv;
    zc[b * KP_ZC + l] = zv;
    out_mu[i] = mu;
    out_lv[i] = lv;
}

// ---------------- gate final (g2 + softmax) ----------------
__global__ void gate_final(const float* __restrict__ g1o, const float* __restrict__ g2w,
                           const float* __restrict__ g2b, float* __restrict__ coeff) {
    int gtid = blockIdx.x * blockDim.x + threadIdx.x;
    int row = gtid >> 5, lane = gtid & 31;
    if (row >= B_) return;
    float logit = 0.f;
    if (lane < E_) {
        logit = g2b[lane];
        const float* r = g1o + row * G_;
        const float* w = g2w + lane * G_;
        #pragma unroll 8
        for (int k = 0; k < G_; k++) logit = fmaf(r[k], w[k], logit);
    }
    float m = logit;
    for (int d = 4; d > 0; d >>= 1) m = fmaxf(m, __shfl_xor_sync(0xffffffffu, m, d));
    float ex = (lane < E_) ? expf(logit - m) : 0.f;
    float s = ex;
    for (int d = 4; d > 0; d >>= 1) s += __shfl_xor_sync(0xffffffffu, s, d);
    if (lane < E_) coeff[row * E_ + lane] = ex / s;
}

// ---------------- FFMA GEMM (gate only): BM=128, BN=64, 8x4 f32x2 ----------------
__global__ void __launch_bounds__(256) gemm3(
    const float* __restrict__ A, int lda,
    const float* __restrict__ W, int ldw,
    float* __restrict__ C, int ldc, long sliceStride, int Nout,
    int ktTot, int ktPer,
    const float* __restrict__ bias, int act)
{
    __shared__ __align__(16) float As[2][16][132];
    __shared__ __align__(16) float Bs[2][16][68];

    int tid = threadIdx.x;
    int m0 = blockIdx.y * 128;
    int n0 = blockIdx.x * 64;
    int kt0 = blockIdx.z * ktPer;
    int ktn = min(ktPer, ktTot - kt0);
    float* Cp = C + (long)blockIdx.z * sliceStride;

    int tx = tid & 15, ty = tid >> 4;
    int arow = tid >> 2, acol = (tid & 3) << 2;
    int brow = tid >> 4, bcol = (tid & 15) << 2;

    const float* Wp = W + (size_t)brow * ldw + n0 + bcol;
    int am0 = m0 + arow, am1 = m0 + arow + 64;

    unsigned long long acc[4][4];
    #pragma unroll
    for (int q = 0; q < 4; q++)
        #pragma unroll
        for (int j = 0; j < 4; j++) acc[q][j] = 0ull;

    float4 av0 = *(const float4*)(A + (size_t)am0 * lda + (kt0 << 4) + acol);
    float4 av1 = *(const float4*)(A + (size_t)am1 * lda + (kt0 << 4) + acol);
    float4 bv  = *(const float4*)(Wp + (size_t)(kt0 << 4) * ldw);

    As[0][acol + 0][arow] = av0.x;
    As[0][acol + 1][arow] = av0.y;
    As[0][acol + 2][arow] = av0.z;
    As[0][acol + 3][arow] = av0.w;
    As[0][acol + 0][arow + 64] = av1.x;
    As[0][acol + 1][arow + 64] = av1.y;
    As[0][acol + 2][arow + 64] = av1.z;
    As[0][acol + 3][arow + 64] = av1.w;
    *(float4*)&Bs[0][brow][bcol] = bv;
    __syncthreads();

    for (int t = 0; t < ktn; t++) {
        int buf = t & 1;
        bool more = (t + 1) < ktn;
        if (more) {
            int kk = (kt0 + t + 1) << 4;
            av0 = *(const float4*)(A + (size_t)am0 * lda + kk + acol);
            av1 = *(const float4*)(A + (size_t)am1 * lda + kk + acol);
            bv  = *(const float4*)(Wp + (size_t)kk * ldw);
        }
        #pragma unroll
        for (int k = 0; k < 16; k++) {
            ulonglong2 a01 = *(const ulonglong2*)&As[buf][k][ty << 3];
            ulonglong2 a23 = *(const ulonglong2*)&As[buf][k][(ty << 3) + 4];
            float4 b4 = *(const float4*)&Bs[buf][k][tx << 2];
            unsigned long long bd0 = dup2(b4.x);
            unsigned long long bd1 = dup2(b4.y);
            unsigned long long bd2 = dup2(b4.z);
            unsigned long long bd3 = dup2(b4.w);
            acc[0][0] = ff2(a01.x, bd0, acc[0][0]);
            acc[0][1] = ff2(a01.x, bd1, acc[0][1]);
            acc[0][2] = ff2(a01.x, bd2, acc[0][2]);
            acc[0][3] = ff2(a01.x, bd3, acc[0][3]);
            acc[1][0] = ff2(a01.y, bd0, acc[1][0]);
            acc[1][1] = ff2(a01.y, bd1, acc[1][1]);
            acc[1][2] = ff2(a01.y, bd2, acc[1][2]);
            acc[1][3] = ff2(a01.y, bd3, acc[1][3]);
            acc[2][0] = ff2(a23.x, bd0, acc[2][0]);
            acc[2][1] = ff2(a23.x, bd1, acc[2][1]);
            acc[2][2] = ff2(a23.x, bd2, acc[2][2]);
            acc[2][3] = ff2(a23.x, bd3, acc[2][3]);
            acc[3][0] = ff2(a23.y, bd0, acc[3][0]);
            acc[3][1] = ff2(a23.y, bd1, acc[3][1]);
            acc[3][2] = ff2(a23.y, bd2, acc[3][2]);
            acc[3][3] = ff2(a23.y, bd3, acc[3][3]);
        }
        if (more) {
            int nb = buf ^ 1;
            As[nb][acol + 0][arow] = av0.x;
            As[nb][acol + 1][arow] = av0.y;
            As[nb][acol + 2][arow] = av0.z;
            As[nb][acol + 3][arow] = av0.w;
            As[nb][acol + 0][arow + 64] = av1.x;
            As[nb][acol + 1][arow + 64] = av1.y;
            As[nb][acol + 2][arow + 64] = av1.z;
            As[nb][acol + 3][arow + 64] = av1.w;
            *(float4*)&Bs[nb][brow][bcol] = bv;
        }
        __syncthreads();
    }

    float cres[8][4];
    #pragma unroll
    for (int q = 0; q < 4; q++)
        #pragma unroll
        for (int j = 0; j < 4; j++) {
            float lo, hi;
            asm("mov.b64 {%0, %1}, %2;" : "=f"(lo), "=f"(hi) : "l"(acc[q][j]));
            cres[2 * q][j] = lo;
            cres[2 * q + 1][j] = hi;
        }

    int n = n0 + (tx << 2);
    float4 bsv = make_float4(0.f, 0.f, 0.f, 0.f);
    if (bias) bsv = *(const float4*)(bias + n);
    #pragma unroll
    for (int r = 0; r < 8; r++) {
        int m = m0 + (ty << 3) + r;
        float4 v;
        v.x = cres[r][0] + bsv.x;
        v.y = cres[r][1] + bsv.y;
        v.z = cres[r][2] + bsv.z;
        v.w = cres[r][3] + bsv.w;
        if (act) { v.x = elu1(v.x); v.y = elu1(v.y); v.z = elu1(v.z); v.w = elu1(v.w); }
        if (n < Nout) *(float4*)(Cp + (size_t)m * ldc + n) = v;
    }
}

// ---------------- mma.sync GEMM (encoder + decoder) ----------------
// smem stage: Ah(128x72 bf16) Al Bh(64x72) Bl; stride 72 bf16 = 144 B.
#define LDS_AB 144
#define TS_A 18432
#define TS_B 9216
#define TSTAGE (2*TS_A + 2*TS_B)      // 55296
#define TSM_TOTAL (2*TSTAGE)          // 110592

template <int MODE>   // 0: plain A (lda); 1: coeff*zc (KP_ZC); 2: coeff*(z|d) (IN1_)
__global__ void __launch_bounds__(256) tgemm(
    const float* __restrict__ src, int lda,
    const float* __restrict__ z,
    const float* __restrict__ coeff,
    const __nv_bfloat16* __restrict__ wth,
    const __nv_bfloat16* __restrict__ wtl,
    float* __restrict__ C, int ldc, long sliceStride,
    int ktTot, int ktPer, int KT)
{
    extern __shared__ __align__(16) char smem[];
    uint32_t sb = smem_u32(smem);
    int tid = threadIdx.x;
    int wid = tid >> 5, lane = tid & 31;
    int wm = wid >> 1, wn = wid & 1;
    int m0 = blockIdx.y * 128;
    int ntile = blockIdx.x, n0 = ntile * 64;
    int kt0 = blockIdx.z * ktPer;
    int ktn = min(ktPer, ktTot - kt0);
    float* Cp = C + (long)blockIdx.z * sliceStride;

    float acc[2][4][4];
    #pragma unroll
    for (int mt = 0; mt < 2; mt++)
        #pragma unroll
        for (int nt = 0; nt < 4; nt++)
            #pragma unroll
            for (int j = 0; j < 4; j++) acc[mt][nt][j] = 0.f;

    auto fill = [&](int kt, int buf) {
        char* st = smem + buf * TSTAGE;
        #pragma unroll
        for (int gq = 0; gq < 4; gq++) {
            int g = tid + gq * 256;
            int row = g >> 3, c8 = g & 7;
            int m = m0 + row;
            int kg = (kt << 6) + (c8 << 3);
            float4 f0, f1;
            float cf = 1.f;
            if (MODE == 0) {
                f0 = *(const float4*)(src + (size_t)m * lda + kg);
                f1 = *(const float4*)(src + (size_t)m * lda + kg + 4);
            } else if (MODE == 1) {
                int e = kg / KP_ZC, i = kg - e * KP_ZC;
                cf = coeff[m * E_ + e];
                f0 = *(const float4*)(src + (size_t)m * KP_ZC + i);
                f1 = *(const float4*)(src + (size_t)m * KP_ZC + i + 4);
            } else {
                int e = kg / IN1_, i = kg - e * IN1_;
                cf = coeff[m * E_ + e];
                if (i < L_) {
                    f0 = *(const float4*)(z + (size_t)m * L_ + i);
                    f1 = *(const float4*)(z + (size_t)m * L_ + i + 4);
                } else {
                    f0 = *(const float4*)(src + (size_t)m * H_ + (i - L_));
                    f1 = *(const float4*)(src + (size_t)m * H_ + (i - L_) + 4);
                }
            }
            float v[8] = { cf * f0.x, cf * f0.y, cf * f0.z, cf * f0.w,
                           cf * f1.x, cf * f1.y, cf * f1.z, cf * f1.w };
            union { __nv_bfloat16 b[8]; uint4 u; } hv, lv;
            #pragma unroll
            for (int j = 0; j < 8; j++) {
                __nv_bfloat16 h = __float2bfloat16(v[j]);
                hv.b[j] = h;
                lv.b[j] = __float2bfloat16(v[j] - __bfloat162float(h));
            }
            *(uint4*)(st + row * LDS_AB + c8 * 16) = hv.u;
            *(uint4*)(st + TS_A + row * LDS_AB + c8 * 16) = lv.u;
        }
        const char* th = (const char*)(wth + ((size_t)(ntile * KT + kt) << 12));
        const char* tl = (const char*)(wtl + ((size_t)(ntile * KT + kt) << 12));
        #pragma unroll
        for (int gq = 0; gq < 2; gq++) {
            int g = tid + gq * 256;
            int n = g >> 3, seg = g & 7;
            *(uint4*)(st + 2 * TS_A + n * LDS_AB + seg * 16) = *(const uint4*)(th + n * 128 + seg * 16);
            *(uint4*)(st + 2 * TS_A + TS_B + n * LDS_AB + seg * 16) = *(const uint4*)(tl + n * 128 + seg * 16);
        }
    };

    fill(kt0, 0);
    __syncthreads();

    for (int t = 0; t < ktn; t++) {
        int buf = t & 1;
        if (t + 1 < ktn) fill(kt0 + t + 1, buf ^ 1);

        uint32_t sA = sb + buf * TSTAGE;
        uint32_t sB = sA + 2 * TS_A;
        int arow = wm * 32 + (lane & 15);
        int bn = wn * 32 + ((lane >> 4) << 3) + (lane & 7);
        int bkl = ((lane >> 3) & 1) << 3;
        #pragma unroll
        for (int ks = 0; ks < 4; ks++) {
            uint32_t ah0[4], ah1[4], al0[4], al1[4];
            uint32_t bh0[4], bh1[4], bl0[4], bl1[4];
            uint32_t aAdr = sA + arow * LDS_AB + (ks * 16 + (lane >> 4) * 8) * 2;
            ldsm_x4(ah0, aAdr);
            ldsm_x4(ah1, aAdr + 16 * LDS_AB);
            ldsm_x4(al0, aAdr + TS_A);
            ldsm_x4(al1, aAdr + TS_A + 16 * LDS_AB);
            uint32_t bAdr = sB + bn * LDS_AB + (ks * 16 + bkl) * 2;
            ldsm_x4(bh0, bAdr);
            ldsm_x4(bh1, bAdr + 16 * LDS_AB);
            ldsm_x4(bl0, bAdr + TS_B);
            ldsm_x4(bl1, bAdr + TS_B + 16 * LDS_AB);

            mma16816(acc[0][0], ah0, bh0);     mma16816(acc[0][1], ah0, bh0 + 2);
            mma16816(acc[0][2], ah0, bh1);     mma16816(acc[0][3], ah0, bh1 + 2);
            mma16816(acc[1][0], ah1, bh0);     mma16816(acc[1][1], ah1, bh0 + 2);
            mma16816(acc[1][2], ah1, bh1);     mma16816(acc[1][3], ah1, bh1 + 2);

            mma16816(acc[0][0], ah0, bl0);     mma16816(acc[0][1], ah0, bl0 + 2);
            mma16816(acc[0][2], ah0, bl1);     mma16816(acc[0][3], ah0, bl1 + 2);
            mma16816(acc[1][0], ah1, bl0);     mma16816(acc[1][1], ah1, bl0 + 2);
            mma16816(acc[1][2], ah1, bl1);     mma16816(acc[1][3], ah1, bl1 + 2);

            mma16816(acc[0][0], al0, bh0);     mma16816(acc[0][1], al0, bh0 + 2);
            mma16816(acc[0][2], al0, bh1);     mma16816(acc[0][3], al0, bh1 + 2);
            mma16816(acc[1][0], al1, bh0);     mma16816(acc[1][1], al1, bh0 + 2);
            mma16816(acc[1][2], al1, bh1);     mma16816(acc[1][3], al1, bh1 + 2);
        }
        __syncthreads();
    }

    #pragma unroll
    for (int mt = 0; mt < 2; mt++)
        #pragma unroll
        for (int nt = 0; nt < 4; nt++) {
            int m = m0 + wm * 32 + mt * 16 + (lane >> 2);
            int n = n0 + wn * 32 + nt * 8 + ((lane & 3) << 1);
            *(float2*)(Cp + (size_t)m * ldc + n) = make_float2(acc[mt][nt][0], acc[mt][nt][1]);
            *(float2*)(Cp + (size_t)(m + 8) * ldc + n) = make_float2(acc[mt][nt][2], acc[mt][nt][3]);
        }
}

// ---------------- split-K combine with epilogue ----------------
__global__ void combine(const float* __restrict__ part, int S, int ldp,
                        float* __restrict__ C, int ldc, int Nout,
                        const float* __restrict__ bias,
                        const float* __restrict__ coeff,
                        const float* __restrict__ ebias, int ebld,
                        int act)
{
    int idx = blockIdx.x * blockDim.x + threadIdx.x;
    if (idx >= B_ * Nout) return;
    int m = idx / Nout, n = idx % Nout;
    float v = 0.f;
    for (int s = 0; s < S; s++) v += part[(size_t)s * B_ * ldp + (size_t)m * ldp + n];
    if (bias) v += bias[n];
    if (ebias) {
        const float* cf = coeff + m * E_;
        float bm = 0.f;
        #pragma unroll
        for (int e = 0; e < E_; e++) bm = fmaf(cf[e], ebias[e * ebld + n], bm);
        v += bm;
    }
    if (act) v = elu1(v);
    C[(size_t)m * ldc + n] = v;
}

// ---------------- host launch ----------------
static inline void* sym(const void* s) { void* p = nullptr; cudaGetSymbolAddress(&p, s); return p; }

extern "C" void kernel_launch(void* const* d_in, const int* in_sizes, int n_in,
                              void* d_out, int out_size) {
    (void)in_sizes; (void)n_in; (void)out_size;
    const float* x     = (const float*)d_in[0];
    const float* c     = (const float*)d_in[1];
    const float* fc1_w = (const float*)d_in[2];
    const float* fc1_b = (const float*)d_in[3];
    const float* fc2_w = (const float*)d_in[4];
    const float* fc2_b = (const float*)d_in[5];
    const float* mu_w  = (const float*)d_in[6];
    const float* mu_b  = (const float*)d_in[7];
    const float* lv_w  = (const float*)d_in[8];
    const float* lv_b  = (const float*)d_in[9];
    const float* g0_w  = (const float*)d_in[10];
    const float* g0_b  = (const float*)d_in[11];
    const float* g1_w  = (const float*)d_in[12];
    const float* g1_b  = (const float*)d_in[13];
    const float* g2_w  = (const float*)d_in[14];
    const float* g2_b  = (const float*)d_in[15];
    const float* w0    = (const float*)d_in[16];
    const float* b0    = (const float*)d_in[17];
    const float* w1    = (const float*)d_in[18];
    const float* b1    = (const float*)d_in[19];
    const float* w2    = (const float*)d_in[20];
    const float* b2    = (const float*)d_in[21];

    float* out       = (float*)d_out;
    float* out_layer = out;
    float* out_mu    = out + B_ * F_;
    float* out_lv    = out + B_ * F_ + B_ * L_;

    float* enc   = (float*)sym(g_enc);
    float* h1    = (float*)sym(g_h1);
    float* h2    = (float*)sym(g_h2);
    float* z     = (float*)sym(g_z);
    float* zc    = (float*)sym(g_zc);
    float* g0o   = (float*)sym(g_g0o);
    float* g1o   = (float*)sym(g_g1o);
    float* coef  = (float*)sym(g_coef);
    float* d0    = (float*)sym(g_d0);
    float* d1    = (float*)sym(g_d1);
    float* part  = (float*)sym(g_part);
    float* bmulv = (float*)sym(g_bmulv);
    float* wg0   = (float*)sym(g_wg0);
    float* wg1   = (float*)sym(g_wg1);
    __nv_bfloat16* we1h = (__nv_bfloat16*)sym(g_wte1h);
    __nv_bfloat16* we1l = (__nv_bfloat16*)sym(g_wte1l);
    __nv_bfloat16* we2h = (__nv_bfloat16*)sym(g_wte2h);
    __nv_bfloat16* we2l = (__nv_bfloat16*)sym(g_wte2l);
    __nv_bfloat16* wmvh = (__nv_bfloat16*)sym(g_wtmvh);
    __nv_bfloat16* wmvl = (__nv_bfloat16*)sym(g_wtmvl);
    __nv_bfloat16* wt0h = (__nv_bfloat16*)sym(g_wt0h);
    __nv_bfloat16* wt0l = (__nv_bfloat16*)sym(g_wt0l);
    __nv_bfloat16* wt1h = (__nv_bfloat16*)sym(g_wt1h);
    __nv_bfloat16* wt1l = (__nv_bfloat16*)sym(g_wt1l);
    __nv_bfloat16* wt2h = (__nv_bfloat16*)sym(g_wt2h);
    __nv_bfloat16* wt2l = (__nv_bfloat16*)sym(g_wt2l);

    cudaFuncSetAttribute(tgemm<0>, cudaFuncAttributeMaxDynamicSharedMemorySize, TSM_TOTAL);
    cudaFuncSetAttribute(tgemm<1>, cudaFuncAttributeMaxDynamicSharedMemorySize, TSM_TOTAL);
    cudaFuncSetAttribute(tgemm<2>, cudaFuncAttributeMaxDynamicSharedMemorySize, TSM_TOTAL);

    const int T = 256;
    auto gr = [](int n) { return (n + 255) / 256; };

    pack_all<<<gr(PKTOT), T>>>(mu_b, lv_b, g0_w, g1_w, bmulv, wg0, wg1);
    tpack<<<gr(WTE1_SZ + WTE2_SZ + WTMV_SZ + WT0_SZ + WT1_SZ + WT2_SZ), T>>>(
        fc1_w, fc2_w, mu_w, lv_w, w0, w1, w2,
        we1h, we1l, we2h, we2l, wmvh, wmvl, wt0h, wt0l, wt1h, wt1l, wt2h, wt2l);
    zc_fill_c<<<gr(B_ * 272), T>>>(zc, c);

    // ---- encoder fc1 (tensor, split-K 3) ----
    cat2<<<gr(B_ * KP_ENC), T>>>(enc, KP_ENC, x, 267, c, 267);
    tgemm<0><<<dim3(4, 16, 3), T, TSM_TOTAL>>>(enc, KP_ENC, nullptr, nullptr, we1h, we1l,
                                               part, 256, (long)B_ * 256, KT_ENC, 3, KT_ENC);
    combine<<<gr(B_ * H_), T>>>(part, 3, 256, h1, H_, H_, fc1_b, nullptr, nullptr, 0, 1);

    // ---- encoder fc2 (tensor, split-K 3) ----
    cat2<<<gr(B_ * KP_ENC), T>>>(enc, KP_ENC, x, 267, h1, 256);
    tgemm<0><<<dim3(4, 16, 3), T, TSM_TOTAL>>>(enc, KP_ENC, nullptr, nullptr, we2h, we2l,
                                               part, 256, (long)B_ * 256, KT_ENC, 3, KT_ENC);
    combine<<<gr(B_ * H_), T>>>(part, 3, 256, h2, H_, H_, fc2_b, nullptr, nullptr, 0, 1);

    // ---- mu/lv (tensor, split-K 9) + fused z sampling ----
    cat2<<<gr(B_ * KP_ENC), T>>>(enc, KP_ENC, x, 267, h2, 256);
    tgemm<0><<<dim3(1, 16, 9), T, TSM_TOTAL>>>(enc, KP_ENC, nullptr, nullptr, wmvh, wmvl,
                                               part, 64, (long)B_ * 64, KT_ENC, 1, KT_ENC);
    combine_zeps<<<gr(B_ * L_), T>>>(part, 9, bmulv, z, zc, out_mu, out_lv);

    // ---- gate (FFMA, tiny) ----
    gemm3<<<dim3(1, 16, 4), T>>>(zc, KP_ZC, wg0, G_,
                                 part, G_, (long)B_ * G_, G_, 19, 5, nullptr, 0);
    combine<<<gr(B_ * G_), T>>>(part, 4, G_, g0o, G_, G_, g0_b, nullptr, nullptr, 0, 1);
    gemm3<<<dim3(1, 16, 1), T>>>(g0o, G_, wg1, G_,
                                 g1o, G_, 0, G_, 4, 4, g1_b, 1);
    gate_final<<<gr(B_ * 32), T>>>(g1o, g2_w, g2_b, coef);

    // ---- decoder: mma.sync bf16 hi/lo, split-K 4 ----
    tgemm<1><<<dim3(NT_L01, 16, 4), T, TSM_TOTAL>>>(zc, 0, nullptr, coef, wt0h, wt0l,
                                                    part, 256, (long)B_ * 256, KT_L0, 10, KT_L0);
    combine<<<gr(B_ * H_), T>>>(part, 4, 256, d0, H_, H_, nullptr, coef, b0, 256, 1);

    tgemm<2><<<dim3(NT_L01, 16, 4), T, TSM_TOTAL>>>(d0, 0, z, coef, wt1h, wt1l,
                                                    part, 256, (long)B_ * 256, KT_L12, 9, KT_L12);
    combine<<<gr(B_ * H_), T>>>(part, 4, 256, d1, H_, H_, nullptr, coef, b1, 256, 1);

    tgemm<2><<<dim3(NT_L2, 16, 4), T, TSM_TOTAL>>>(d1, 0, z, coef, wt2h, wt2l,
                                                   part, NP_W2, (long)B_ * NP_W2, KT_L12, 9, KT_L12);
    combine<<<gr(B_ * 267), T>>>(part, 4, NP_W2, out_layer, 267, 267, nullptr, coef, b2, 267, 0);
}

// round 10
// speedup vs baseline: 3.1306x; 1.0204x over previous
#include <cuda_runtime.h>
#include <cuda_bf16.h>
#include <cstdint>

// ---------------- problem dims ----------------
#define B_   2048
#define F_   267
#define L_   32
#define H_   256
#define E_   8
#define G_   64

#define KP_ENC 576            // encoder K pad (9 chunks of 64)
#define KP_ZC  304            // 299 -> 304 (gate FFMA path)
#define IN1_   288            // 32 + 256
#define NP_W2  320            // 267 -> 320

#define SPLIT_MAX 9

// tensor-path tiling (k-chunks of 64)
#define KT_ENC 9
#define KT_L0 38
#define KT_L12 36
#define NT_L01 4
#define NT_L2 5
#define WTE1_SZ (4*KT_ENC*4096)
#define WTE2_SZ (4*KT_ENC*4096)
#define WTMV_SZ (1*KT_ENC*4096)
#define WT0_SZ (NT_L01*KT_L0*4096)
#define WT1_SZ (NT_L01*KT_L12*4096)
#define WT2_SZ (NT_L2*KT_L12*4096)

// ---------------- device scratch ----------------
__device__ __align__(16) float g_encA [B_*KP_ENC];     // [x | c | 0]
__device__ __align__(16) float g_encB [B_*KP_ENC];     // [x | h1/h2 | 0]
__device__ __align__(16) float g_z    [B_*L_];
__device__ __align__(16) float g_zc   [B_*KP_ZC];
__device__ __align__(16) float g_g0o  [B_*G_];
__device__ __align__(16) float g_g1o  [B_*G_];
__device__ __align__(16) float g_coef [B_*E_];
__device__ __align__(16) float g_d0   [B_*H_];
__device__ __align__(16) float g_d1   [B_*H_];
__device__ __align__(16) float g_part [SPLIT_MAX*B_*NP_W2];
// FFMA-path weights (gate only)
__device__ __align__(16) float g_bmulv[64];
__device__ __align__(16) float g_wg0  [KP_ZC*G_];
__device__ __align__(16) float g_wg1  [G_*G_];
// tensor-path weights: bf16 hi/lo, tiles [ntile][ktile][64n][64k]
__device__ __align__(16) __nv_bfloat16 g_wte1h[WTE1_SZ];
__device__ __align__(16) __nv_bfloat16 g_wte1l[WTE1_SZ];
__device__ __align__(16) __nv_bfloat16 g_wte2h[WTE2_SZ];
__device__ __align__(16) __nv_bfloat16 g_wte2l[WTE2_SZ];
__device__ __align__(16) __nv_bfloat16 g_wtmvh[WTMV_SZ];
__device__ __align__(16) __nv_bfloat16 g_wtmvl[WTMV_SZ];
__device__ __align__(16) __nv_bfloat16 g_wt0h[WT0_SZ];
__device__ __align__(16) __nv_bfloat16 g_wt0l[WT0_SZ];
__device__ __align__(16) __nv_bfloat16 g_wt1h[WT1_SZ];
__device__ __align__(16) __nv_bfloat16 g_wt1l[WT1_SZ];
__device__ __align__(16) __nv_bfloat16 g_wt2h[WT2_SZ];
__device__ __align__(16) __nv_bfloat16 g_wt2l[WT2_SZ];

__device__ __forceinline__ float elu1(float v) { return v > 0.f ? v : expm1f(v); }

// ---------------- f32x2 helpers (FFMA gate path) ----------------
__device__ __forceinline__ unsigned long long ff2(unsigned long long a,
                                                  unsigned long long b,
                                                  unsigned long long c) {
    unsigned long long d;
    asm("fma.rn.f32x2 %0, %1, %2, %3;" : "=l"(d) : "l"(a), "l"(b), "l"(c));
    return d;
}
__device__ __forceinline__ unsigned long long dup2(float x) {
    unsigned long long d;
    asm("mov.b64 %0, {%1, %1};" : "=l"(d) : "f"(x));
    return d;
}

// ---------------- mma.sync helpers ----------------
__device__ __forceinline__ uint32_t smem_u32(const void* p) {
    uint32_t a;
    asm("{ .reg .u64 t; cvta.to.shared.u64 t, %1; cvt.u32.u64 %0, t; }" : "=r"(a) : "l"(p));
    return a;
}
__device__ __forceinline__ void ldsm_x4(uint32_t* r, uint32_t addr) {
    asm volatile("ldmatrix.sync.aligned.m8n8.x4.shared.b16 {%0,%1,%2,%3}, [%4];"
                 : "=r"(r[0]), "=r"(r[1]), "=r"(r[2]), "=r"(r[3]) : "r"(addr));
}
__device__ __forceinline__ void mma16816(float* c, const uint32_t* a, const uint32_t* b) {
    asm volatile("mma.sync.aligned.m16n8k16.row.col.f32.bf16.bf16.f32 "
                 "{%0,%1,%2,%3}, {%4,%5,%6,%7}, {%8,%9}, {%0,%1,%2,%3};"
                 : "+f"(c[0]), "+f"(c[1]), "+f"(c[2]), "+f"(c[3])
                 : "r"(a[0]), "r"(a[1]), "r"(a[2]), "r"(a[3]), "r"(b[0]), "r"(b[1]));
}

// ---------------- small pack (gate weights + mulv bias) ----------------
#define PK3 64
#define PK4 (KP_ZC*G_)
#define PK5 (G_*G_)
#define PKTOT (PK3+PK4+PK5)

__global__ void pack_all(const float* __restrict__ mu_b, const float* __restrict__ lv_b,
                         const float* __restrict__ g0_w, const float* __restrict__ g1_w,
                         float* __restrict__ bmulv, float* __restrict__ wg0,
                         float* __restrict__ wg1) {
    int idx = blockIdx.x * blockDim.x + threadIdx.x;
    if (idx >= PKTOT) return;
    if (idx < PK3) {
        bmulv[idx] = (idx < 32) ? mu_b[idx] : lv_b[idx - 32];
        return;
    } idx -= PK3;
    if (idx < PK4) {
        int k = idx / G_, n = idx % G_;
        wg0[idx] = (k < 299) ? g0_w[n * 299 + k] : 0.f;
        return;
    } idx -= PK4;
    {
        int k = idx / G_, n = idx % G_;
        wg1[idx] = g1_w[n * G_ + k];
    }
}

// ---------------- tensor weight pack: bf16 hi/lo, [64n][64k] tiles ----------------
__global__ void tpack(const float* __restrict__ fc1_w, const float* __restrict__ fc2_w,
                      const float* __restrict__ mu_w, const float* __restrict__ lv_w,
                      const float* __restrict__ w0, const float* __restrict__ w1,
                      const float* __restrict__ w2,
                      __nv_bfloat16* __restrict__ we1h, __nv_bfloat16* __restrict__ we1l,
                      __nv_bfloat16* __restrict__ we2h, __nv_bfloat16* __restrict__ we2l,
                      __nv_bfloat16* __restrict__ wmvh, __nv_bfloat16* __restrict__ wmvl,
                      __nv_bfloat16* __restrict__ wt0h, __nv_bfloat16* __restrict__ wt0l,
                      __nv_bfloat16* __restrict__ wt1h, __nv_bfloat16* __restrict__ wt1l,
                      __nv_bfloat16* __restrict__ wt2h, __nv_bfloat16* __restrict__ wt2l) {
    int idx = blockIdx.x * blockDim.x + threadIdx.x;
    int layer, KT;
    __nv_bfloat16 *dh, *dl;
    if (idx < WTE1_SZ) { layer = 0; KT = KT_ENC; dh = we1h; dl = we1l; }
    else if (idx < WTE1_SZ + WTE2_SZ) { idx -= WTE1_SZ; layer = 1; KT = KT_ENC; dh = we2h; dl = we2l; }
    else if (idx < WTE1_SZ + WTE2_SZ + WTMV_SZ) { idx -= WTE1_SZ + WTE2_SZ; layer = 2; KT = KT_ENC; dh = wmvh; dl = wmvl; }
    else if (idx < WTE1_SZ + WTE2_SZ + WTMV_SZ + WT0_SZ) { idx -= WTE1_SZ + WTE2_SZ + WTMV_SZ; layer = 3; KT = KT_L0; dh = wt0h; dl = wt0l; }
    else if (idx < WTE1_SZ + WTE2_SZ + WTMV_SZ + WT0_SZ + WT1_SZ) { idx -= WTE1_SZ + WTE2_SZ + WTMV_SZ + WT0_SZ; layer = 4; KT = KT_L12; dh = wt1h; dl = wt1l; }
    else if (idx < WTE1_SZ + WTE2_SZ + WTMV_SZ + WT0_SZ + WT1_SZ + WT2_SZ) { idx -= WTE1_SZ + WTE2_SZ + WTMV_SZ + WT0_SZ + WT1_SZ; layer = 5; KT = KT_L12; dh = wt2h; dl = wt2l; }
    else return;
    int tile = idx >> 12, u = idx & 4095;
    int ntile = tile / KT, kt = tile % KT;
    int nrow = u >> 6, kc = u & 63;
    int n = ntile * 64 + nrow;
    int kg = kt * 64 + kc;
    float w = 0.f;
    if (layer == 0) {
        if (kg < 534) w = fc1_w[(size_t)n * 534 + kg];
    } else if (layer == 1) {
        if (kg < 523) w = fc2_w[(size_t)n * 523 + kg];
    } else if (layer == 2) {
        if (kg < 523) w = (n < 32) ? mu_w[(size_t)n * 523 + kg]
                                   : lv_w[(size_t)(n - 32) * 523 + kg];
    } else if (layer == 3) {
        int e = kg / KP_ZC, i = kg - e * KP_ZC;
        if (i < 299) w = w0[((size_t)(e * 299 + i)) * 256 + n];
    } else if (layer == 4) {
        w = w1[(size_t)kg * 256 + n];
    } else {
        if (n < 267) w = w2[(size_t)kg * 267 + n];
    }
    __nv_bfloat16 hi = __float2bfloat16(w);
    __nv_bfloat16 lo = __float2bfloat16(w - __bfloat162float(hi));
    size_t dst = ((size_t)tile << 12) + u;
    dh[dst] = hi;
    dl[dst] = lo;
}

// ---------------- fused input-prep kernel ----------------
// encA = [x | c | 0]; encB = [x | (h filled later) | 0]; zc[:,32:304] = c (pad 0)
#define PR0 (B_*KP_ENC)       // encA
#define PR1 (B_*320)          // encB cols 0..266 (x) and 523..575 (0): 320 cols worth
#define PR2 (B_*272)          // zc cols 32..303
__global__ void prep_inputs(const float* __restrict__ x, const float* __restrict__ c,
                            float* __restrict__ encA, float* __restrict__ encB,
                            float* __restrict__ zc) {
    int idx = blockIdx.x * blockDim.x + threadIdx.x;
    if (idx < PR0) {
        int b = idx / KP_ENC, k = idx % KP_ENC;
        float v = 0.f;
        if (k < 267)      v = x[b * 267 + k];
        else if (k < 534) v = c[b * 267 + (k - 267)];
        encA[idx] = v;
        return;
    } idx -= PR0;
    if (idx < PR1) {
        int b = idx / 320, j = idx % 320;
        int k = (j < 267) ? j : (523 + (j - 267));     // x cols or pad cols
        encB[b * KP_ENC + k] = (j < 267) ? x[b * 267 + j] : 0.f;
        return;
    } idx -= PR1;
    if (idx < PR2) {
        int b = idx / 272, k = 32 + idx % 272;
        zc[b * KP_ZC + k] = (k < 299) ? c[b * 267 + (k - 32)] : 0.f;
    }
}

// ---------------- threefry (partitionable) + XLA erfinv ----------------
__device__ __forceinline__ uint32_t rotl32(uint32_t v, int d) { return (v << d) | (v >> (32 - d)); }
__device__ __forceinline__ void tf4(uint32_t& x0, uint32_t& x1, int r0, int r1, int r2, int r3) {
    x0 += x1; x1 = rotl32(x1, r0); x1 ^= x0;
    x0 += x1; x1 = rotl32(x1, r1); x1 ^= x0;
    x0 += x1; x1 = rotl32(x1, r2); x1 ^= x0;
    x0 += x1; x1 = rotl32(x1, r3); x1 ^= x0;
}
__device__ __forceinline__ void threefry2x32(uint32_t k0, uint32_t k1, uint32_t& x0, uint32_t& x1) {
    uint32_t k2 = k0 ^ k1 ^ 0x1BD11BDAu;
    x0 += k0; x1 += k1;
    tf4(x0, x1, 13, 15, 26, 6);  x0 += k1; x1 += k2 + 1u;
    tf4(x0, x1, 17, 29, 16, 24); x0 += k2; x1 += k0 + 2u;
    tf4(x0, x1, 13, 15, 26, 6);  x0 += k0; x1 += k1 + 3u;
    tf4(x0, x1, 17, 29, 16, 24); x0 += k1; x1 += k2 + 4u;
    tf4(x0, x1, 13, 15, 26, 6);  x0 += k2; x1 += k0 + 5u;
}
__device__ __forceinline__ float erfinv_xla(float x) {
    float w = -log1pf(-x * x);
    float p;
    if (w < 5.0f) {
        w -= 2.5f;
        p = 2.81022636e-08f;
        p = fmaf(p, w, 3.43273939e-07f);
        p = fmaf(p, w, -3.5233877e-06f);
        p = fmaf(p, w, -4.39150654e-06f);
        p = fmaf(p, w, 0.00021858087f);
        p = fmaf(p, w, -0.00125372503f);
        p = fmaf(p, w, -0.00417768164f);
        p = fmaf(p, w, 0.246640727f);
        p = fmaf(p, w, 1.50140941f);
    } else {
        w = sqrtf(w) - 3.0f;
        p = -0.000200214257f;
        p = fmaf(p, w, 0.000100950558f);
        p = fmaf(p, w, 0.00134934322f);
        p = fmaf(p, w, -0.00367342844f);
        p = fmaf(p, w, 0.00573950773f);
        p = fmaf(p, w, -0.0076224613f);
        p = fmaf(p, w, 0.00943887047f);
        p = fmaf(p, w, 1.00167406f);
        p = fmaf(p, w, 2.83297682f);
    }
    return p * x;
}

// fused: combine mu/lv split-K partials + bias, then z = mu + eps*exp(lv/2)
__global__ void combine_zeps(const float* __restrict__ part, int S,
                             const float* __restrict__ bmulv,
                             float* __restrict__ zout, float* __restrict__ zc,
                             float* __restrict__ out_mu, float* __restrict__ out_lv) {
    int i = blockIdx.x * blockDim.x + threadIdx.x;
    if (i >= B_ * L_) return;
    int b = i >> 5, l = i & 31;
    float mu = bmulv[l], lv = bmulv[32 + l];
    for (int s = 0; s < S; s++) {
        const float* p = part + (size_t)s * B_ * 64 + (size_t)b * 64;
        mu += p[l];
        lv += p[32 + l];
    }
    uint32_t x0 = 0u, x1 = (uint32_t)i;
    threefry2x32(0u, 42u, x0, x1);
    uint32_t bits = x0 ^ x1;
    float f = __uint_as_float((bits >> 9) | 0x3f800000u) - 1.0f;
    const float lo = -0.99999994f;
    float u = fmaxf(lo, fmaf(f, 2.0f, lo));
    float eps = 1.41421354f * erfinv_xla(u);
    float zv = fmaf(eps, expf(0.5f * lv), mu);
    zout[i] = zv;
    zc[b * KP_ZC + l] = zv;
    out_mu[i] = mu;
    out_lv[i] = lv;
}

// ---------------- gate final (g2 + softmax) ----------------
__global__ void gate_final(const float* __restrict__ g1o, const float* __restrict__ g2w,
                           const float* __restrict__ g2b, float* __restrict__ coeff) {
    int gtid = blockIdx.x * blockDim.x + threadIdx.x;
    int row = gtid >> 5, lane = gtid & 31;
    if (row >= B_) return;
    float logit = 0.f;
    if (lane < E_) {
        logit = g2b[lane];
        const float* r = g1o + row * G_;
        const float* w = g2w + lane * G_;
        #pragma unroll 8
        for (int k = 0; k < G_; k++) logit = fmaf(r[k], w[k], logit);
    }
    float m = logit;
    for (int d = 4; d > 0; d >>= 1) m = fmaxf(m, __shfl_xor_sync(0xffffffffu, m, d));
    float ex = (lane < E_) ? expf(logit - m) : 0.f;
    float s = ex;
    for (int d = 4; d > 0; d >>= 1) s += __shfl_xor_sync(0xffffffffu, s, d);
    if (lane < E_) coeff[row * E_ + lane] = ex / s;
}

// ---------------- FFMA GEMM (gate only): BM=128, BN=64, 8x4 f32x2 ----------------
__global__ void __launch_bounds__(256) gemm3(
    const float* __restrict__ A, int lda,
    const float* __restrict__ W, int ldw,
    float* __restrict__ C, int ldc, long sliceStride, int Nout,
    int ktTot, int ktPer,
    const float* __restrict__ bias, int act)
{
    __shared__ __align__(16) float As[2][16][132];
    __shared__ __align__(16) float Bs[2][16][68];

    int tid = threadIdx.x;
    int m0 = blockIdx.y * 128;
    int n0 = blockIdx.x * 64;
    int kt0 = blockIdx.z * ktPer;
    int ktn = min(ktPer, ktTot - kt0);
    float* Cp = C + (long)blockIdx.z * sliceStride;

    int tx = tid & 15, ty = tid >> 4;
    int arow = tid >> 2, acol = (tid & 3) << 2;
    int brow = tid >> 4, bcol = (tid & 15) << 2;

    const float* Wp = W + (size_t)brow * ldw + n0 + bcol;
    int am0 = m0 + arow, am1 = m0 + arow + 64;

    unsigned long long acc[4][4];
    #pragma unroll
    for (int q = 0; q < 4; q++)
        #pragma unroll
        for (int j = 0; j < 4; j++) acc[q][j] = 0ull;

    float4 av0 = *(const float4*)(A + (size_t)am0 * lda + (kt0 << 4) + acol);
    float4 av1 = *(const float4*)(A + (size_t)am1 * lda + (kt0 << 4) + acol);
    float4 bv  = *(const float4*)(Wp + (size_t)(kt0 << 4) * ldw);

    As[0][acol + 0][arow] = av0.x;
    As[0][acol + 1][arow] = av0.y;
    As[0][acol + 2][arow] = av0.z;
    As[0][acol + 3][arow] = av0.w;
    As[0][acol + 0][arow + 64] = av1.x;
    As[0][acol + 1][arow + 64] = av1.y;
    As[0][acol + 2][arow + 64] = av1.z;
    As[0][acol + 3][arow + 64] = av1.w;
    *(float4*)&Bs[0][brow][bcol] = bv;
    __syncthreads();

    for (int t = 0; t < ktn; t++) {
        int buf = t & 1;
        bool more = (t + 1) < ktn;
        if (more) {
            int kk = (kt0 + t + 1) << 4;
            av0 = *(const float4*)(A + (size_t)am0 * lda + kk + acol);
            av1 = *(const float4*)(A + (size_t)am1 * lda + kk + acol);
            bv  = *(const float4*)(Wp + (size_t)kk * ldw);
        }
        #pragma unroll
        for (int k = 0; k < 16; k++) {
            ulonglong2 a01 = *(const ulonglong2*)&As[buf][k][ty << 3];
            ulonglong2 a23 = *(const ulonglong2*)&As[buf][k][(ty << 3) + 4];
            float4 b4 = *(const float4*)&Bs[buf][k][tx << 2];
            unsigned long long bd0 = dup2(b4.x);
            unsigned long long bd1 = dup2(b4.y);
            unsigned long long bd2 = dup2(b4.z);
            unsigned long long bd3 = dup2(b4.w);
            acc[0][0] = ff2(a01.x, bd0, acc[0][0]);
            acc[0][1] = ff2(a01.x, bd1, acc[0][1]);
            acc[0][2] = ff2(a01.x, bd2, acc[0][2]);
            acc[0][3] = ff2(a01.x, bd3, acc[0][3]);
            acc[1][0] = ff2(a01.y, bd0, acc[1][0]);
            acc[1][1] = ff2(a01.y, bd1, acc[1][1]);
            acc[1][2] = ff2(a01.y, bd2, acc[1][2]);
            acc[1][3] = ff2(a01.y, bd3, acc[1][3]);
            acc[2][0] = ff2(a23.x, bd0, acc[2][0]);
            acc[2][1] = ff2(a23.x, bd1, acc[2][1]);
            acc[2][2] = ff2(a23.x, bd2, acc[2][2]);
            acc[2][3] = ff2(a23.x, bd3, acc[2][3]);
            acc[3][0] = ff2(a23.y, bd0, acc[3][0]);
            acc[3][1] = ff2(a23.y, bd1, acc[3][1]);
            acc[3][2] = ff2(a23.y, bd2, acc[3][2]);
            acc[3][3] = ff2(a23.y, bd3, acc[3][3]);
        }
        if (more) {
            int nb = buf ^ 1;
            As[nb][acol + 0][arow] = av0.x;
            As[nb][acol + 1][arow] = av0.y;
            As[nb][acol + 2][arow] = av0.z;
            As[nb][acol + 3][arow] = av0.w;
            As[nb][acol + 0][arow + 64] = av1.x;
            As[nb][acol + 1][arow + 64] = av1.y;
            As[nb][acol + 2][arow + 64] = av1.z;
            As[nb][acol + 3][arow + 64] = av1.w;
            *(float4*)&Bs[nb][brow][bcol] = bv;
        }
        __syncthreads();
    }

    float cres[8][4];
    #pragma unroll
    for (int q = 0; q < 4; q++)
        #pragma unroll
        for (int j = 0; j < 4; j++) {
            float lo, hi;
            asm("mov.b64 {%0, %1}, %2;" : "=f"(lo), "=f"(hi) : "l"(acc[q][j]));
            cres[2 * q][j] = lo;
            cres[2 * q + 1][j] = hi;
        }

    int n = n0 + (tx << 2);
    float4 bsv = make_float4(0.f, 0.f, 0.f, 0.f);
    if (bias) bsv = *(const float4*)(bias + n);
    #pragma unroll
    for (int r = 0; r < 8; r++) {
        int m = m0 + (ty << 3) + r;
        float4 v;
        v.x = cres[r][0] + bsv.x;
        v.y = cres[r][1] + bsv.y;
        v.z = cres[r][2] + bsv.z;
        v.w = cres[r][3] + bsv.w;
        if (act) { v.x = elu1(v.x); v.y = elu1(v.y); v.z = elu1(v.z); v.w = elu1(v.w); }
        if (n < Nout) *(float4*)(Cp + (size_t)m * ldc + n) = v;
    }
}

// ---------------- mma.sync GEMM (encoder + decoder) ----------------
#define LDS_AB 144
#define TS_A 18432
#define TS_B 9216
#define TSTAGE (2*TS_A + 2*TS_B)      // 55296
#define TSM_TOTAL (2*TSTAGE)          // 110592

template <int MODE>   // 0: plain A (lda); 1: coeff*zc (KP_ZC); 2: coeff*(z|d) (IN1_)
__global__ void __launch_bounds__(256) tgemm(
    const float* __restrict__ src, int lda,
    const float* __restrict__ z,
    const float* __restrict__ coeff,
    const __nv_bfloat16* __restrict__ wth,
    const __nv_bfloat16* __restrict__ wtl,
    float* __restrict__ C, int ldc, long sliceStride,
    int ktTot, int ktPer, int KT)
{
    extern __shared__ __align__(16) char smem[];
    uint32_t sb = smem_u32(smem);
    int tid = threadIdx.x;
    int wid = tid >> 5, lane = tid & 31;
    int wm = wid >> 1, wn = wid & 1;
    int m0 = blockIdx.y * 128;
    int ntile = blockIdx.x, n0 = ntile * 64;
    int kt0 = blockIdx.z * ktPer;
    int ktn = min(ktPer, ktTot - kt0);
    float* Cp = C + (long)blockIdx.z * sliceStride;

    float acc[2][4][4];
    #pragma unroll
    for (int mt = 0; mt < 2; mt++)
        #pragma unroll
        for (int nt = 0; nt < 4; nt++)
            #pragma unroll
            for (int j = 0; j < 4; j++) acc[mt][nt][j] = 0.f;

    auto fill = [&](int kt, int buf) {
        char* st = smem + buf * TSTAGE;
        #pragma unroll
        for (int gq = 0; gq < 4; gq++) {
            int g = tid + gq * 256;
            int row = g >> 3, c8 = g & 7;
            int m = m0 + row;
            int kg = (kt << 6) + (c8 << 3);
            float4 f0, f1;
            float cf = 1.f;
            if (MODE == 0) {
                f0 = *(const float4*)(src + (size_t)m * lda + kg);
                f1 = *(const float4*)(src + (size_t)m * lda + kg + 4);
            } else if (MODE == 1) {
                int e = kg / KP_ZC, i = kg - e * KP_ZC;
                cf = coeff[m * E_ + e];
                f0 = *(const float4*)(src + (size_t)m * KP_ZC + i);
                f1 = *(const float4*)(src + (size_t)m * KP_ZC + i + 4);
            } else {
                int e = kg / IN1_, i = kg - e * IN1_;
                cf = coeff[m * E_ + e];
                if (i < L_) {
                    f0 = *(const float4*)(z + (size_t)m * L_ + i);
                    f1 = *(const float4*)(z + (size_t)m * L_ + i + 4);
                } else {
                    f0 = *(const float4*)(src + (size_t)m * H_ + (i - L_));
                    f1 = *(const float4*)(src + (size_t)m * H_ + (i - L_) + 4);
                }
            }
            float v[8] = { cf * f0.x, cf * f0.y, cf * f0.z, cf * f0.w,
                           cf * f1.x, cf * f1.y, cf * f1.z, cf * f1.w };
            union { __nv_bfloat16 b[8]; uint4 u; } hv, lv;
            #pragma unroll
            for (int j = 0; j < 8; j++) {
                __nv_bfloat16 h = __float2bfloat16(v[j]);
                hv.b[j] = h;
                lv.b[j] = __float2bfloat16(v[j] - __bfloat162float(h));
            }
            *(uint4*)(st + row * LDS_AB + c8 * 16) = hv.u;
            *(uint4*)(st + TS_A + row * LDS_AB + c8 * 16) = lv.u;
        }
        const char* th = (const char*)(wth + ((size_t)(ntile * KT + kt) << 12));
        const char* tl = (const char*)(wtl + ((size_t)(ntile * KT + kt) << 12));
        #pragma unroll
        for (int gq = 0; gq < 2; gq++) {
            int g = tid + gq * 256;
            int n = g >> 3, seg = g & 7;
            *(uint4*)(st + 2 * TS_A + n * LDS_AB + seg * 16) = *(const uint4*)(th + n * 128 + seg * 16);
            *(uint4*)(st + 2 * TS_A + TS_B + n * LDS_AB + seg * 16) = *(const uint4*)(tl + n * 128 + seg * 16);
        }
    };

    fill(kt0, 0);
    __syncthreads();

    for (int t = 0; t < ktn; t++) {
        int buf = t & 1;
        if (t + 1 < ktn) fill(kt0 + t + 1, buf ^ 1);

        uint32_t sA = sb + buf * TSTAGE;
        uint32_t sB = sA + 2 * TS_A;
        int arow = wm * 32 + (lane & 15);
        int bn = wn * 32 + ((lane >> 4) << 3) + (lane & 7);
        int bkl = ((lane >> 3) & 1) << 3;
        #pragma unroll
        for (int ks = 0; ks < 4; ks++) {
            uint32_t ah0[4], ah1[4], al0[4], al1[4];
            uint32_t bh0[4], bh1[4], bl0[4], bl1[4];
            uint32_t aAdr = sA + arow * LDS_AB + (ks * 16 + (lane >> 4) * 8) * 2;
            ldsm_x4(ah0, aAdr);
            ldsm_x4(ah1, aAdr + 16 * LDS_AB);
            ldsm_x4(al0, aAdr + TS_A);
            ldsm_x4(al1, aAdr + TS_A + 16 * LDS_AB);
            uint32_t bAdr = sB + bn * LDS_AB + (ks * 16 + bkl) * 2;
            ldsm_x4(bh0, bAdr);
            ldsm_x4(bh1, bAdr + 16 * LDS_AB);
            ldsm_x4(bl0, bAdr + TS_B);
            ldsm_x4(bl1, bAdr + TS_B + 16 * LDS_AB);

            mma16816(acc[0][0], ah0, bh0);     mma16816(acc[0][1], ah0, bh0 + 2);
            mma16816(acc[0][2], ah0, bh1);     mma16816(acc[0][3], ah0, bh1 + 2);
            mma16816(acc[1][0], ah1, bh0);     mma16816(acc[1][1], ah1, bh0 + 2);
            mma16816(acc[1][2], ah1, bh1);     mma16816(acc[1][3], ah1, bh1 + 2);

            mma16816(acc[0][0], ah0, bl0);     mma16816(acc[0][1], ah0, bl0 + 2);
            mma16816(acc[0][2], ah0, bl1);     mma16816(acc[0][3], ah0, bl1 + 2);
            mma16816(acc[1][0], ah1, bl0);     mma16816(acc[1][1], ah1, bl0 + 2);
            mma16816(acc[1][2], ah1, bl1);     mma16816(acc[1][3], ah1, bl1 + 2);

            mma16816(acc[0][0], al0, bh0);     mma16816(acc[0][1], al0, bh0 + 2);
            mma16816(acc[0][2], al0, bh1);     mma16816(acc[0][3], al0, bh1 + 2);
            mma16816(acc[1][0], al1, bh0);     mma16816(acc[1][1], al1, bh0 + 2);
            mma16816(acc[1][2], al1, bh1);     mma16816(acc[1][3], al1, bh1 + 2);
        }
        __syncthreads();
    }

    #pragma unroll
    for (int mt = 0; mt < 2; mt++)
        #pragma unroll
        for (int nt = 0; nt < 4; nt++) {
            int m = m0 + wm * 32 + mt * 16 + (lane >> 2);
            int n = n0 + wn * 32 + nt * 8 + ((lane & 3) << 1);
            *(float2*)(Cp + (size_t)m * ldc + n) = make_float2(acc[mt][nt][0], acc[mt][nt][1]);
            *(float2*)(Cp + (size_t)(m + 8) * ldc + n) = make_float2(acc[mt][nt][2], acc[mt][nt][3]);
        }
}

// ---------------- split-K combine with epilogue ----------------
// writes to C + (row-major ldc) at column offset coff (for encB in-place h writes)
__global__ void combine(const float* __restrict__ part, int S, int ldp,
                        float* __restrict__ C, int ldc, int Nout,
                        const float* __restrict__ bias,
                        const float* __restrict__ coeff,
                        const float* __restrict__ ebias, int ebld,
                        int act)
{
    int idx = blockIdx.x * blockDim.x + threadIdx.x;
    if (idx >= B_ * Nout) return;
    int m = idx / Nout, n = idx % Nout;
    float v = 0.f;
    for (int s = 0; s < S; s++) v += part[(size_t)s * B_ * ldp + (size_t)m * ldp + n];
    if (bias) v += bias[n];
    if (ebias) {
        const float* cf = coeff + m * E_;
        float bm = 0.f;
        #pragma unroll
        for (int e = 0; e < E_; e++) bm = fmaf(cf[e], ebias[e * ebld + n], bm);
        v += bm;
    }
    if (act) v = elu1(v);
    C[(size_t)m * ldc + n] = v;
}

// ---------------- host launch ----------------
static inline void* sym(const void* s) { void* p = nullptr; cudaGetSymbolAddress(&p, s); return p; }

extern "C" void kernel_launch(void* const* d_in, const int* in_sizes, int n_in,
                              void* d_out, int out_size) {
    (void)in_sizes; (void)n_in; (void)out_size;
    const float* x     = (const float*)d_in[0];
    const float* c     = (const float*)d_in[1];
    const float* fc1_w = (const float*)d_in[2];
    const float* fc1_b = (const float*)d_in[3];
    const float* fc2_w = (const float*)d_in[4];
    const float* fc2_b = (const float*)d_in[5];
    const float* mu_w  = (const float*)d_in[6];
    const float* mu_b  = (const float*)d_in[7];
    const float* lv_w  = (const float*)d_in[8];
    const float* lv_b  = (const float*)d_in[9];
    const float* g0_w  = (const float*)d_in[10];
    const float* g0_b  = (const float*)d_in[11];
    const float* g1_w  = (const float*)d_in[12];
    const float* g1_b  = (const float*)d_in[13];
    const float* g2_w  = (const float*)d_in[14];
    const float* g2_b  = (const float*)d_in[15];
    const float* w0    = (const float*)d_in[16];
    const float* b0    = (const float*)d_in[17];
    const float* w1    = (const float*)d_in[18];
    const float* b1    = (const float*)d_in[19];
    const float* w2    = (const float*)d_in[20];
    const float* b2    = (const float*)d_in[21];

    float* out       = (float*)d_out;
    float* out_layer = out;
    float* out_mu    = out + B_ * F_;
    float* out_lv    = out + B_ * F_ + B_ * L_;

    float* encA  = (float*)sym(g_encA);
    float* encB  = (float*)sym(g_encB);
    float* z     = (float*)sym(g_z);
    float* zc    = (float*)sym(g_zc);
    float* g0o   = (float*)sym(g_g0o);
    float* g1o   = (float*)sym(g_g1o);
    float* coef  = (float*)sym(g_coef);
    float* d0    = (float*)sym(g_d0);
    float* d1    = (float*)sym(g_d1);
    float* part  = (float*)sym(g_part);
    float* bmulv = (float*)sym(g_bmulv);
    float* wg0   = (float*)sym(g_wg0);
    float* wg1   = (float*)sym(g_wg1);
    __nv_bfloat16* we1h = (__nv_bfloat16*)sym(g_wte1h);
    __nv_bfloat16* we1l = (__nv_bfloat16*)sym(g_wte1l);
    __nv_bfloat16* we2h = (__nv_bfloat16*)sym(g_wte2h);
    __nv_bfloat16* we2l = (__nv_bfloat16*)sym(g_wte2l);
    __nv_bfloat16* wmvh = (__nv_bfloat16*)sym(g_wtmvh);
    __nv_bfloat16* wmvl = (__nv_bfloat16*)sym(g_wtmvl);
    __nv_bfloat16* wt0h = (__nv_bfloat16*)sym(g_wt0h);
    __nv_bfloat16* wt0l = (__nv_bfloat16*)sym(g_wt0l);
    __nv_bfloat16* wt1h = (__nv_bfloat16*)sym(g_wt1h);
    __nv_bfloat16* wt1l = (__nv_bfloat16*)sym(g_wt1l);
    __nv_bfloat16* wt2h = (__nv_bfloat16*)sym(g_wt2h);
    __nv_bfloat16* wt2l = (__nv_bfloat16*)sym(g_wt2l);

    cudaFuncSetAttribute(tgemm<0>, cudaFuncAttributeMaxDynamicSharedMemorySize, TSM_TOTAL);
    cudaFuncSetAttribute(tgemm<1>, cudaFuncAttributeMaxDynamicSharedMemorySize, TSM_TOTAL);
    cudaFuncSetAttribute(tgemm<2>, cudaFuncAttributeMaxDynamicSharedMemorySize, TSM_TOTAL);

    const int T = 256;
    auto gr = [](int n) { return (n + 255) / 256; };

    pack_all<<<gr(PKTOT), T>>>(mu_b, lv_b, g0_w, g1_w, bmulv, wg0, wg1);
    tpack<<<gr(WTE1_SZ + WTE2_SZ + WTMV_SZ + WT0_SZ + WT1_SZ + WT2_SZ), T>>>(
        fc1_w, fc2_w, mu_w, lv_w, w0, w1, w2,
        we1h, we1l, we2h, we2l, wmvh, wmvl, wt0h, wt0l, wt1h, wt1l, wt2h, wt2l);
    prep_inputs<<<gr(PR0 + PR1 + PR2), T>>>(x, c, encA, encB, zc);

    // ---- encoder fc1 (tensor, split-K 3); h1 written directly into encB[:,267:523] ----
    tgemm<0><<<dim3(4, 16, 3), T, TSM_TOTAL>>>(encA, KP_ENC, nullptr, nullptr, we1h, we1l,
                                               part, 256, (long)B_ * 256, KT_ENC, 3, KT_ENC);
    combine<<<gr(B_ * H_), T>>>(part, 3, 256, encB + 267, KP_ENC, H_, fc1_b, nullptr, nullptr, 0, 1);

    // ---- encoder fc2 (tensor, split-K 3); h2 overwrites the same slot ----
    tgemm<0><<<dim3(4, 16, 3), T, TSM_TOTAL>>>(encB, KP_ENC, nullptr, nullptr, we2h, we2l,
                                               part, 256, (long)B_ * 256, KT_ENC, 3, KT_ENC);
    combine<<<gr(B_ * H_), T>>>(part, 3, 256, encB + 267, KP_ENC, H_, fc2_b, nullptr, nullptr, 0, 1);

    // ---- mu/lv (tensor, split-K 9) + fused z sampling ----
    tgemm<0><<<dim3(1, 16, 9), T, TSM_TOTAL>>>(encB, KP_ENC, nullptr, nullptr, wmvh, wmvl,
                                               part, 64, (long)B_ * 64, KT_ENC, 1, KT_ENC);
    combine_zeps<<<gr(B_ * L_), T>>>(part, 9, bmulv, z, zc, out_mu, out_lv);

    // ---- gate (FFMA, tiny) ----
    gemm3<<<dim3(1, 16, 4), T>>>(zc, KP_ZC, wg0, G_,
                                 part, G_, (long)B_ * G_, G_, 19, 5, nullptr, 0);
    combine<<<gr(B_ * G_), T>>>(part, 4, G_, g0o, G_, G_, g0_b, nullptr, nullptr, 0, 1);
    gemm3<<<dim3(1, 16, 1), T>>>(g0o, G_, wg1, G_,
                                 g1o, G_, 0, G_, 4, 4, g1_b, 1);
    gate_final<<<gr(B_ * 32), T>>>(g1o, g2_w, g2_b, coef);

    // ---- decoder: mma.sync bf16 hi/lo, split-K 4 ----
    tgemm<1><<<dim3(NT_L01, 16, 4), T, TSM_TOTAL>>>(zc, 0, nullptr, coef, wt0h, wt0l,
                                                    part, 256, (long)B_ * 256, KT_L0, 10, KT_L0);
    combine<<<gr(B_ * H_), T>>>(part, 4, 256, d0, H_, H_, nullptr, coef, b0, 256, 1);

    tgemm<2><<<dim3(NT_L01, 16, 4), T, TSM_TOTAL>>>(d0, 0, z, coef, wt1h, wt1l,
                                                    part, 256, (long)B_ * 256, KT_L12, 9, KT_L12);
    combine<<<gr(B_ * H_), T>>>(part, 4, 256, d1, H_, H_, nullptr, coef, b1, 256, 1);

    tgemm<2><<<dim3(NT_L2, 16, 4), T, TSM_TOTAL>>>(d1, 0, z, coef, wt2h, wt2l,
                                                   part, NP_W2, (long)B_ * NP_W2, KT_L12, 9, KT_L12);
    combine<<<gr(B_ * 267), T>>>(part, 4, NP_W2, out_layer, 267, 267, nullptr, coef, b2, 267, 0);
}

// round 11
// speedup vs baseline: 3.5129x; 1.1221x over previous
#include <cuda_runtime.h>
#include <cuda_bf16.h>
#include <cstdint>

// ---------------- problem dims ----------------
#define B_   2048
#define F_   267
#define L_   32
#define H_   256
#define E_   8
#define G_   64

#define KP_ENC 576            // encoder K pad (9 chunks of 64)
#define KP_ZC  304            // 299 -> 304
#define IN1_   288            // 32 + 256
#define NP_W2  320            // 267 -> 320

#define SPLIT_MAX 9

// tensor-path tiling (k-chunks of 64)
#define KT_ENC 9
#define KT_L0 38
#define KT_L12 36
#define NT_L01 4
#define NT_L2 5
#define WTE1_SZ (4*KT_ENC*4096)
#define WTE2_SZ (4*KT_ENC*4096)
#define WTMV_SZ (1*KT_ENC*4096)
#define WT0_SZ (NT_L01*KT_L0*4096)
#define WT1_SZ (NT_L01*KT_L12*4096)
#define WT2_SZ (NT_L2*KT_L12*4096)

// ---------------- device scratch ----------------
__device__ __align__(16) __nv_bfloat16 g_encAh[B_*KP_ENC];
__device__ __align__(16) __nv_bfloat16 g_encAl[B_*KP_ENC];
__device__ __align__(16) __nv_bfloat16 g_encBh[B_*KP_ENC];
__device__ __align__(16) __nv_bfloat16 g_encBl[B_*KP_ENC];
__device__ __align__(16) float g_z    [B_*L_];
__device__ __align__(16) float g_zc   [B_*KP_ZC];
__device__ __align__(16) float g_g0o  [B_*G_];
__device__ __align__(16) float g_g1o  [B_*G_];
__device__ __align__(16) float g_coef [B_*E_];
__device__ __align__(16) float g_d0   [B_*H_];
__device__ __align__(16) float g_d1   [B_*H_];
__device__ __align__(16) float g_part [SPLIT_MAX*B_*NP_W2];
// FFMA-path weights (gate only)
__device__ __align__(16) float g_bmulv[64];
__device__ __align__(16) float g_wg0  [KP_ZC*G_];
__device__ __align__(16) float g_wg1  [G_*G_];
// tensor-path weights: bf16 hi/lo, tiles [ntile][ktile][64n][64k]
__device__ __align__(16) __nv_bfloat16 g_wte1h[WTE1_SZ];
__device__ __align__(16) __nv_bfloat16 g_wte1l[WTE1_SZ];
__device__ __align__(16) __nv_bfloat16 g_wte2h[WTE2_SZ];
__device__ __align__(16) __nv_bfloat16 g_wte2l[WTE2_SZ];
__device__ __align__(16) __nv_bfloat16 g_wtmvh[WTMV_SZ];
__device__ __align__(16) __nv_bfloat16 g_wtmvl[WTMV_SZ];
__device__ __align__(16) __nv_bfloat16 g_wt0h[WT0_SZ];
__device__ __align__(16) __nv_bfloat16 g_wt0l[WT0_SZ];
__device__ __align__(16) __nv_bfloat16 g_wt1h[WT1_SZ];
__device__ __align__(16) __nv_bfloat16 g_wt1l[WT1_SZ];
__device__ __align__(16) __nv_bfloat16 g_wt2h[WT2_SZ];
__device__ __align__(16) __nv_bfloat16 g_wt2l[WT2_SZ];

__device__ __forceinline__ float elu1(float v) { return v > 0.f ? v : expm1f(v); }
__device__ __forceinline__ void split_bf16(float v, __nv_bfloat16& h, __nv_bfloat16& l) {
    h = __float2bfloat16(v);
    l = __float2bfloat16(v - __bfloat162float(h));
}

// ---------------- f32x2 helpers (FFMA gate path) ----------------
__device__ __forceinline__ unsigned long long ff2(unsigned long long a,
                                                  unsigned long long b,
                                                  unsigned long long c) {
    unsigned long long d;
    asm("fma.rn.f32x2 %0, %1, %2, %3;" : "=l"(d) : "l"(a), "l"(b), "l"(c));
    return d;
}
__device__ __forceinline__ unsigned long long dup2(float x) {
    unsigned long long d;
    asm("mov.b64 %0, {%1, %1};" : "=l"(d) : "f"(x));
    return d;
}

// ---------------- mma.sync helpers ----------------
__device__ __forceinline__ uint32_t smem_u32(const void* p) {
    uint32_t a;
    asm("{ .reg .u64 t; cvta.to.shared.u64 t, %1; cvt.u32.u64 %0, t; }" : "=r"(a) : "l"(p));
    return a;
}
__device__ __forceinline__ void ldsm_x4(uint32_t* r, uint32_t addr) {
    asm volatile("ldmatrix.sync.aligned.m8n8.x4.shared.b16 {%0,%1,%2,%3}, [%4];"
                 : "=r"(r[0]), "=r"(r[1]), "=r"(r[2]), "=r"(r[3]) : "r"(addr));
}
__device__ __forceinline__ void mma16816(float* c, const uint32_t* a, const uint32_t* b) {
    asm volatile("mma.sync.aligned.m16n8k16.row.col.f32.bf16.bf16.f32 "
                 "{%0,%1,%2,%3}, {%4,%5,%6,%7}, {%8,%9}, {%0,%1,%2,%3};"
                 : "+f"(c[0]), "+f"(c[1]), "+f"(c[2]), "+f"(c[3])
                 : "r"(a[0]), "r"(a[1]), "r"(a[2]), "r"(a[3]), "r"(b[0]), "r"(b[1]));
}

// ---------------- small pack (gate weights + mulv bias) ----------------
#define PK3 64
#define PK4 (KP_ZC*G_)
#define PK5 (G_*G_)
#define PKTOT (PK3+PK4+PK5)

__global__ void pack_all(const float* __restrict__ mu_b, const float* __restrict__ lv_b,
                         const float* __restrict__ g0_w, const float* __restrict__ g1_w,
                         float* __restrict__ bmulv, float* __restrict__ wg0,
                         float* __restrict__ wg1) {
    int idx = blockIdx.x * blockDim.x + threadIdx.x;
    if (idx >= PKTOT) return;
    if (idx < PK3) {
        bmulv[idx] = (idx < 32) ? mu_b[idx] : lv_b[idx - 32];
        return;
    } idx -= PK3;
    if (idx < PK4) {
        int k = idx / G_, n = idx % G_;
        wg0[idx] = (k < 299) ? g0_w[n * 299 + k] : 0.f;
        return;
    } idx -= PK4;
    {
        int k = idx / G_, n = idx % G_;
        wg1[idx] = g1_w[n * G_ + k];
    }
}

// ---------------- tensor weight pack: bf16 hi/lo, [64n][64k] tiles ----------------
__global__ void tpack(const float* __restrict__ fc1_w, const float* __restrict__ fc2_w,
                      const float* __restrict__ mu_w, const float* __restrict__ lv_w,
                      const float* __restrict__ w0, const float* __restrict__ w1,
                      const float* __restrict__ w2,
                      __nv_bfloat16* __restrict__ we1h, __nv_bfloat16* __restrict__ we1l,
                      __nv_bfloat16* __restrict__ we2h, __nv_bfloat16* __restrict__ we2l,
                      __nv_bfloat16* __restrict__ wmvh, __nv_bfloat16* __restrict__ wmvl,
                      __nv_bfloat16* __restrict__ wt0h, __nv_bfloat16* __restrict__ wt0l,
                      __nv_bfloat16* __restrict__ wt1h, __nv_bfloat16* __restrict__ wt1l,
                      __nv_bfloat16* __restrict__ wt2h, __nv_bfloat16* __restrict__ wt2l) {
    int idx = blockIdx.x * blockDim.x + threadIdx.x;
    int layer, KT;
    __nv_bfloat16 *dh, *dl;
    if (idx < WTE1_SZ) { layer = 0; KT = KT_ENC; dh = we1h; dl = we1l; }
    else if (idx < WTE1_SZ + WTE2_SZ) { idx -= WTE1_SZ; layer = 1; KT = KT_ENC; dh = we2h; dl = we2l; }
    else if (idx < WTE1_SZ + WTE2_SZ + WTMV_SZ) { idx -= WTE1_SZ + WTE2_SZ; layer = 2; KT = KT_ENC; dh = wmvh; dl = wmvl; }
    else if (idx < WTE1_SZ + WTE2_SZ + WTMV_SZ + WT0_SZ) { idx -= WTE1_SZ + WTE2_SZ + WTMV_SZ; layer = 3; KT = KT_L0; dh = wt0h; dl = wt0l; }
    else if (idx < WTE1_SZ + WTE2_SZ + WTMV_SZ + WT0_SZ + WT1_SZ) { idx -= WTE1_SZ + WTE2_SZ + WTMV_SZ + WT0_SZ; layer = 4; KT = KT_L12; dh = wt1h; dl = wt1l; }
    else if (idx < WTE1_SZ + WTE2_SZ + WTMV_SZ + WT0_SZ + WT1_SZ + WT2_SZ) { idx -= WTE1_SZ + WTE2_SZ + WTMV_SZ + WT0_SZ + WT1_SZ; layer = 5; KT = KT_L12; dh = wt2h; dl = wt2l; }
    else return;
    int tile = idx >> 12, u = idx & 4095;
    int ntile = tile / KT, kt = tile % KT;
    int nrow = u >> 6, kc = u & 63;
    int n = ntile * 64 + nrow;
    int kg = kt * 64 + kc;
    float w = 0.f;
    if (layer == 0) {
        if (kg < 534) w = fc1_w[(size_t)n * 534 + kg];
    } else if (layer == 1) {
        if (kg < 523) w = fc2_w[(size_t)n * 523 + kg];
    } else if (layer == 2) {
        if (kg < 523) w = (n < 32) ? mu_w[(size_t)n * 523 + kg]
                                   : lv_w[(size_t)(n - 32) * 523 + kg];
    } else if (layer == 3) {
        int e = kg / KP_ZC, i = kg - e * KP_ZC;
        if (i < 299) w = w0[((size_t)(e * 299 + i)) * 256 + n];
    } else if (layer == 4) {
        w = w1[(size_t)kg * 256 + n];
    } else {
        if (n < 267) w = w2[(size_t)kg * 267 + n];
    }
    __nv_bfloat16 hi, lo;
    split_bf16(w, hi, lo);
    size_t dst = ((size_t)tile << 12) + u;
    dh[dst] = hi;
    dl[dst] = lo;
}

// ---------------- fused input-prep kernel (bf16 hi/lo encoder inputs) ----------------
#define PR0 (B_*KP_ENC)       // encA
#define PR1 (B_*320)          // encB x cols + pad cols
#define PR2 (B_*272)          // zc cols 32..303
__global__ void prep_inputs(const float* __restrict__ x, const float* __restrict__ c,
                            __nv_bfloat16* __restrict__ eAh, __nv_bfloat16* __restrict__ eAl,
                            __nv_bfloat16* __restrict__ eBh, __nv_bfloat16* __restrict__ eBl,
                            float* __restrict__ zc) {
    int idx = blockIdx.x * blockDim.x + threadIdx.x;
    if (idx < PR0) {
        int b = idx / KP_ENC, k = idx % KP_ENC;
        float v = 0.f;
        if (k < 267)      v = x[b * 267 + k];
        else if (k < 534) v = c[b * 267 + (k - 267)];
        __nv_bfloat16 h, l;
        split_bf16(v, h, l);
        eAh[idx] = h;
        eAl[idx] = l;
        return;
    } idx -= PR0;
    if (idx < PR1) {
        int b = idx / 320, j = idx % 320;
        int k = (j < 267) ? j : (523 + (j - 267));
        float v = (j < 267) ? x[b * 267 + j] : 0.f;
        __nv_bfloat16 h, l;
        split_bf16(v, h, l);
        eBh[b * KP_ENC + k] = h;
        eBl[b * KP_ENC + k] = l;
        return;
    } idx -= PR1;
    if (idx < PR2) {
        int b = idx / 272, k = 32 + idx % 272;
        zc[b * KP_ZC + k] = (k < 299) ? c[b * 267 + (k - 32)] : 0.f;
    }
}

// ---------------- threefry (partitionable) + XLA erfinv ----------------
__device__ __forceinline__ uint32_t rotl32(uint32_t v, int d) { return (v << d) | (v >> (32 - d)); }
__device__ __forceinline__ void tf4(uint32_t& x0, uint32_t& x1, int r0, int r1, int r2, int r3) {
    x0 += x1; x1 = rotl32(x1, r0); x1 ^= x0;
    x0 += x1; x1 = rotl32(x1, r1); x1 ^= x0;
    x0 += x1; x1 = rotl32(x1, r2); x1 ^= x0;
    x0 += x1; x1 = rotl32(x1, r3); x1 ^= x0;
}
__device__ __forceinline__ void threefry2x32(uint32_t k0, uint32_t k1, uint32_t& x0, uint32_t& x1) {
    uint32_t k2 = k0 ^ k1 ^ 0x1BD11BDAu;
    x0 += k0; x1 += k1;
    tf4(x0, x1, 13, 15, 26, 6);  x0 += k1; x1 += k2 + 1u;
    tf4(x0, x1, 17, 29, 16, 24); x0 += k2; x1 += k0 + 2u;
    tf4(x0, x1, 13, 15, 26, 6);  x0 += k0; x1 += k1 + 3u;
    tf4(x0, x1, 17, 29, 16, 24); x0 += k1; x1 += k2 + 4u;
    tf4(x0, x1, 13, 15, 26, 6);  x0 += k2; x1 += k0 + 5u;
}
__device__ __forceinline__ float erfinv_xla(float x) {
    float w = -log1pf(-x * x);
    float p;
    if (w < 5.0f) {
        w -= 2.5f;
        p = 2.81022636e-08f;
        p = fmaf(p, w, 3.43273939e-07f);
        p = fmaf(p, w, -3.5233877e-06f);
        p = fmaf(p, w, -4.39150654e-06f);
        p = fmaf(p, w, 0.00021858087f);
        p = fmaf(p, w, -0.00125372503f);
        p = fmaf(p, w, -0.00417768164f);
        p = fmaf(p, w, 0.246640727f);
        p = fmaf(p, w, 1.50140941f);
    } else {
        w = sqrtf(w) - 3.0f;
        p = -0.000200214257f;
        p = fmaf(p, w, 0.000100950558f);
        p = fmaf(p, w, 0.00134934322f);
        p = fmaf(p, w, -0.00367342844f);
        p = fmaf(p, w, 0.00573950773f);
        p = fmaf(p, w, -0.0076224613f);
        p = fmaf(p, w, 0.00943887047f);
        p = fmaf(p, w, 1.00167406f);
        p = fmaf(p, w, 2.83297682f);
    }
    return p * x;
}

// fused: combine mu/lv split-K partials + bias, then z = mu + eps*exp(lv/2)
__global__ void combine_zeps(const float* __restrict__ part, int S,
                             const float* __restrict__ bmulv,
                             float* __restrict__ zout, float* __restrict__ zc,
                             float* __restrict__ out_mu, float* __restrict__ out_lv) {
    int i = blockIdx.x * blockDim.x + threadIdx.x;
    if (i >= B_ * L_) return;
    int b = i >> 5, l = i & 31;
    float mu = bmulv[l], lv = bmulv[32 + l];
    for (int s = 0; s < S; s++) {
        const float* p = part + (size_t)s * B_ * 64 + (size_t)b * 64;
        mu += p[l];
        lv += p[32 + l];
    }
    uint32_t x0 = 0u, x1 = (uint32_t)i;
    threefry2x32(0u, 42u, x0, x1);
    uint32_t bits = x0 ^ x1;
    float f = __uint_as_float((bits >> 9) | 0x3f800000u) - 1.0f;
    const float lo = -0.99999994f;
    float u = fmaxf(lo, fmaf(f, 2.0f, lo));
    float eps = 1.41421354f * erfinv_xla(u);
    float zv = fmaf(eps, expf(0.5f * lv), mu);
    zout[i] = zv;
    zc[b * KP_ZC + l] = zv;
    out_mu[i] = mu;
    out_lv[i] = lv;
}

// ---------------- gate final (g2 + softmax) ----------------
__global__ void gate_final(const float* __restrict__ g1o, const float* __restrict__ g2w,
                           const float* __restrict__ g2b, float* __restrict__ coeff) {
    int gtid = blockIdx.x * blockDim.x + threadIdx.x;
    int row = gtid >> 5, lane = gtid & 31;
    if (row >= B_) return;
    float logit = 0.f;
    if (lane < E_) {
        logit = g2b[lane];
        const float* r = g1o + row * G_;
        const float* w = g2w + lane * G_;
        #pragma unroll 8
        for (int k = 0; k < G_; k++) logit = fmaf(r[k], w[k], logit);
    }
    float m = logit;
    for (int d = 4; d > 0; d >>= 1) m = fmaxf(m, __shfl_xor_sync(0xffffffffu, m, d));
    float ex = (lane < E_) ? expf(logit - m) : 0.f;
    float s = ex;
    for (int d = 4; d > 0; d >>= 1) s += __shfl_xor_sync(0xffffffffu, s, d);
    if (lane < E_) coeff[row * E_ + lane] = ex / s;
}

// ---------------- FFMA GEMM (gate only) ----------------
__global__ void __launch_bounds__(256) gemm3(
    const float* __restrict__ A, int lda,
    const float* __restrict__ W, int ldw,
    float* __restrict__ C, int ldc, long sliceStride, int Nout,
    int ktTot, int ktPer,
    const float* __restrict__ bias, int act)
{
    __shared__ __align__(16) float As[2][16][132];
    __shared__ __align__(16) float Bs[2][16][68];

    int tid = threadIdx.x;
    int m0 = blockIdx.y * 128;
    int n0 = blockIdx.x * 64;
    int kt0 = blockIdx.z * ktPer;
    int ktn = min(ktPer, ktTot - kt0);
    float* Cp = C + (long)blockIdx.z * sliceStride;

    int tx = tid & 15, ty = tid >> 4;
    int arow = tid >> 2, acol = (tid & 3) << 2;
    int brow = tid >> 4, bcol = (tid & 15) << 2;

    const float* Wp = W + (size_t)brow * ldw + n0 + bcol;
    int am0 = m0 + arow, am1 = m0 + arow + 64;

    unsigned long long acc[4][4];
    #pragma unroll
    for (int q = 0; q < 4; q++)
        #pragma unroll
        for (int j = 0; j < 4; j++) acc[q][j] = 0ull;

    float4 av0 = *(const float4*)(A + (size_t)am0 * lda + (kt0 << 4) + acol);
    float4 av1 = *(const float4*)(A + (size_t)am1 * lda + (kt0 << 4) + acol);
    float4 bv  = *(const float4*)(Wp + (size_t)(kt0 << 4) * ldw);

    As[0][acol + 0][arow] = av0.x;
    As[0][acol + 1][arow] = av0.y;
    As[0][acol + 2][arow] = av0.z;
    As[0][acol + 3][arow] = av0.w;
    As[0][acol + 0][arow + 64] = av1.x;
    As[0][acol + 1][arow + 64] = av1.y;
    As[0][acol + 2][arow + 64] = av1.z;
    As[0][acol + 3][arow + 64] = av1.w;
    *(float4*)&Bs[0][brow][bcol] = bv;
    __syncthreads();

    for (int t = 0; t < ktn; t++) {
        int buf = t & 1;
        bool more = (t + 1) < ktn;
        if (more) {
            int kk = (kt0 + t + 1) << 4;
            av0 = *(const float4*)(A + (size_t)am0 * lda + kk + acol);
            av1 = *(const float4*)(A + (size_t)am1 * lda + kk + acol);
            bv  = *(const float4*)(Wp + (size_t)kk * ldw);
        }
        #pragma unroll
        for (int k = 0; k < 16; k++) {
            ulonglong2 a01 = *(const ulonglong2*)&As[buf][k][ty << 3];
            ulonglong2 a23 = *(const ulonglong2*)&As[buf][k][(ty << 3) + 4];
            float4 b4 = *(const float4*)&Bs[buf][k][tx << 2];
            unsigned long long bd0 = dup2(b4.x);
            unsigned long long bd1 = dup2(b4.y);
            unsigned long long bd2 = dup2(b4.z);
            unsigned long long bd3 = dup2(b4.w);
            acc[0][0] = ff2(a01.x, bd0, acc[0][0]);
            acc[0][1] = ff2(a01.x, bd1, acc[0][1]);
            acc[0][2] = ff2(a01.x, bd2, acc[0][2]);
            acc[0][3] = ff2(a01.x, bd3, acc[0][3]);
            acc[1][0] = ff2(a01.y, bd0, acc[1][0]);
            acc[1][1] = ff2(a01.y, bd1, acc[1][1]);
            acc[1][2] = ff2(a01.y, bd2, acc[1][2]);
            acc[1][3] = ff2(a01.y, bd3, acc[1][3]);
            acc[2][0] = ff2(a23.x, bd0, acc[2][0]);
            acc[2][1] = ff2(a23.x, bd1, acc[2][1]);
            acc[2][2] = ff2(a23.x, bd2, acc[2][2]);
            acc[2][3] = ff2(a23.x, bd3, acc[2][3]);
            acc[3][0] = ff2(a23.y, bd0, acc[3][0]);
            acc[3][1] = ff2(a23.y, bd1, acc[3][1]);
            acc[3][2] = ff2(a23.y, bd2, acc[3][2]);
            acc[3][3] = ff2(a23.y, bd3, acc[3][3]);
        }
        if (more) {
            int nb = buf ^ 1;
            As[nb][acol + 0][arow] = av0.x;
            As[nb][acol + 1][arow] = av0.y;
            As[nb][acol + 2][arow] = av0.z;
            As[nb][acol + 3][arow] = av0.w;
            As[nb][acol + 0][arow + 64] = av1.x;
            As[nb][acol + 1][arow + 64] = av1.y;
            As[nb][acol + 2][arow + 64] = av1.z;
            As[nb][acol + 3][arow + 64] = av1.w;
            *(float4*)&Bs[nb][brow][bcol] = bv;
        }
        __syncthreads();
    }

    float cres[8][4];
    #pragma unroll
    for (int q = 0; q < 4; q++)
        #pragma unroll
        for (int j = 0; j < 4; j++) {
            float lo, hi;
            asm("mov.b64 {%0, %1}, %2;" : "=f"(lo), "=f"(hi) : "l"(acc[q][j]));
            cres[2 * q][j] = lo;
            cres[2 * q + 1][j] = hi;
        }

    int n = n0 + (tx << 2);
    float4 bsv = make_float4(0.f, 0.f, 0.f, 0.f);
    if (bias) bsv = *(const float4*)(bias + n);
    #pragma unroll
    for (int r = 0; r < 8; r++) {
        int m = m0 + (ty << 3) + r;
        float4 v;
        v.x = cres[r][0] + bsv.x;
        v.y = cres[r][1] + bsv.y;
        v.z = cres[r][2] + bsv.z;
        v.w = cres[r][3] + bsv.w;
        if (act) { v.x = elu1(v.x); v.y = elu1(v.y); v.z = elu1(v.z); v.w = elu1(v.w); }
        if (n < Nout) *(float4*)(Cp + (size_t)m * ldc + n) = v;
    }
}

// ---------------- mma.sync GEMM ----------------
#define LDS_AB 144
#define TS_A 18432
#define TS_B 9216
#define TSTAGE (2*TS_A + 2*TS_B)      // 55296
#define TSM_TOTAL (2*TSTAGE)          // 110592

// MODE 0: A from precomputed bf16 hi/lo (ah/al, stride lda)
// MODE 1: A = coeff * zc (f32 src, KP_ZC)
// MODE 2: A = coeff * (z|d) (f32 src + z, IN1_)
template <int MODE>
__global__ void __launch_bounds__(256) tgemm(
    const float* __restrict__ src, int lda,
    const __nv_bfloat16* __restrict__ ah, const __nv_bfloat16* __restrict__ al,
    const float* __restrict__ z,
    const float* __restrict__ coeff,
    const __nv_bfloat16* __restrict__ wth,
    const __nv_bfloat16* __restrict__ wtl,
    float* __restrict__ C, int ldc, long sliceStride,
    int ktTot, int ktPer, int KT)
{
    extern __shared__ __align__(16) char smem[];
    uint32_t sb = smem_u32(smem);
    int tid = threadIdx.x;
    int wid = tid >> 5, lane = tid & 31;
    int wm = wid >> 1, wn = wid & 1;
    int m0 = blockIdx.y * 128;
    int ntile = blockIdx.x, n0 = ntile * 64;
    int kt0 = blockIdx.z * ktPer;
    int ktn = min(ktPer, ktTot - kt0);
    float* Cp = C + (long)blockIdx.z * sliceStride;

    float acc[2][4][4];
    #pragma unroll
    for (int mt = 0; mt < 2; mt++)
        #pragma unroll
        for (int nt = 0; nt < 4; nt++)
            #pragma unroll
            for (int j = 0; j < 4; j++) acc[mt][nt][j] = 0.f;

    auto fill = [&](int kt, int buf) {
        char* st = smem + buf * TSTAGE;
        if (MODE == 0) {
            // pure copies: 2048 uint4 for A (hi+lo), 8 per thread
            #pragma unroll
            for (int gq = 0; gq < 8; gq++) {
                int g = tid + gq * 256;
                int sel = g >> 10;               // 0=hi, 1=lo
                int r = (g >> 3) & 127, seg = g & 7;
                const __nv_bfloat16* srcp = (sel ? al : ah) + (size_t)(m0 + r) * lda + (kt << 6) + (seg << 3);
                *(uint4*)(st + sel * TS_A + r * LDS_AB + seg * 16) = *(const uint4*)srcp;
            }
        } else {
            #pragma unroll
            for (int gq = 0; gq < 4; gq++) {
                int g = tid + gq * 256;
                int row = g >> 3, c8 = g & 7;
                int m = m0 + row;
                int kg = (kt << 6) + (c8 << 3);
                float4 f0, f1;
                float cf;
                if (MODE == 1) {
                    int e = kg / KP_ZC, i = kg - e * KP_ZC;
                    cf = coeff[m * E_ + e];
                    f0 = *(const float4*)(src + (size_t)m * KP_ZC + i);
                    f1 = *(const float4*)(src + (size_t)m * KP_ZC + i + 4);
                } else {
                    int e = kg / IN1_, i = kg - e * IN1_;
                    cf = coeff[m * E_ + e];
                    if (i < L_) {
                        f0 = *(const float4*)(z + (size_t)m * L_ + i);
                        f1 = *(const float4*)(z + (size_t)m * L_ + i + 4);
                    } else {
                        f0 = *(const float4*)(src + (size_t)m * H_ + (i - L_));
                        f1 = *(const float4*)(src + (size_t)m * H_ + (i - L_) + 4);
                    }
                }
                float v[8] = { cf * f0.x, cf * f0.y, cf * f0.z, cf * f0.w,
                               cf * f1.x, cf * f1.y, cf * f1.z, cf * f1.w };
                union { __nv_bfloat16 b[8]; uint4 u; } hv, lv;
                #pragma unroll
                for (int j = 0; j < 8; j++) split_bf16(v[j], hv.b[j], lv.b[j]);
                *(uint4*)(st + row * LDS_AB + c8 * 16) = hv.u;
                *(uint4*)(st + TS_A + row * LDS_AB + c8 * 16) = lv.u;
            }
        }
        const char* th = (const char*)(wth + ((size_t)(ntile * KT + kt) << 12));
        const char* tl = (const char*)(wtl + ((size_t)(ntile * KT + kt) << 12));
        #pragma unroll
        for (int gq = 0; gq < 2; gq++) {
            int g = tid + gq * 256;
            int n = g >> 3, seg = g & 7;
            *(uint4*)(st + 2 * TS_A + n * LDS_AB + seg * 16) = *(const uint4*)(th + n * 128 + seg * 16);
            *(uint4*)(st + 2 * TS_A + TS_B + n * LDS_AB + seg * 16) = *(const uint4*)(tl + n * 128 + seg * 16);
        }
    };

    fill(kt0, 0);
    __syncthreads();

    for (int t = 0; t < ktn; t++) {
        int buf = t & 1;
        if (t + 1 < ktn) fill(kt0 + t + 1, buf ^ 1);

        uint32_t sA = sb + buf * TSTAGE;
        uint32_t sB = sA + 2 * TS_A;
        int arow = wm * 32 + (lane & 15);
        int bn = wn * 32 + ((lane >> 4) << 3) + (lane & 7);
        int bkl = ((lane >> 3) & 1) << 3;
        #pragma unroll
        for (int ks = 0; ks < 4; ks++) {
            uint32_t ah0[4], ah1[4], al0[4], al1[4];
            uint32_t bh0[4], bh1[4], bl0[4], bl1[4];
            uint32_t aAdr = sA + arow * LDS_AB + (ks * 16 + (lane >> 4) * 8) * 2;
            ldsm_x4(ah0, aAdr);
            ldsm_x4(ah1, aAdr + 16 * LDS_AB);
            ldsm_x4(al0, aAdr + TS_A);
            ldsm_x4(al1, aAdr + TS_A + 16 * LDS_AB);
            uint32_t bAdr = sB + bn * LDS_AB + (ks * 16 + bkl) * 2;
            ldsm_x4(bh0, bAdr);
            ldsm_x4(bh1, bAdr + 16 * LDS_AB);
            ldsm_x4(bl0, bAdr + TS_B);
            ldsm_x4(bl1, bAdr + TS_B + 16 * LDS_AB);

            mma16816(acc[0][0], ah0, bh0);     mma16816(acc[0][1], ah0, bh0 + 2);
            mma16816(acc[0][2], ah0, bh1);     mma16816(acc[0][3], ah0, bh1 + 2);
            mma16816(acc[1][0], ah1, bh0);     mma16816(acc[1][1], ah1, bh0 + 2);
            mma16816(acc[1][2], ah1, bh1);     mma16816(acc[1][3], ah1, bh1 + 2);

            mma16816(acc[0][0], ah0, bl0);     mma16816(acc[0][1], ah0, bl0 + 2);
            mma16816(acc[0][2], ah0, bl1);     mma16816(acc[0][3], ah0, bl1 + 2);
            mma16816(acc[1][0], ah1, bl0);     mma16816(acc[1][1], ah1, bl0 + 2);
            mma16816(acc[1][2], ah1, bl1);     mma16816(acc[1][3], ah1, bl1 + 2);

            mma16816(acc[0][0], al0, bh0);     mma16816(acc[0][1], al0, bh0 + 2);
            mma16816(acc[0][2], al0, bh1);     mma16816(acc[0][3], al0, bh1 + 2);
            mma16816(acc[1][0], al1, bh0);     mma16816(acc[1][1], al1, bh0 + 2);
            mma16816(acc[1][2], al1, bh1);     mma16816(acc[1][3], al1, bh1 + 2);
        }
        __syncthreads();
    }

    #pragma unroll
    for (int mt = 0; mt < 2; mt++)
        #pragma unroll
        for (int nt = 0; nt < 4; nt++) {
            int m = m0 + wm * 32 + mt * 16 + (lane >> 2);
            int n = n0 + wn * 32 + nt * 8 + ((lane & 3) << 1);
            *(float2*)(Cp + (size_t)m * ldc + n) = make_float2(acc[mt][nt][0], acc[mt][nt][1]);
            *(float2*)(Cp + (size_t)(m + 8) * ldc + n) = make_float2(acc[mt][nt][2], acc[mt][nt][3]);
        }
}

// ---------------- split-K combines ----------------
__global__ void combine(const float* __restrict__ part, int S, int ldp,
                        float* __restrict__ C, int ldc, int Nout,
                        const float* __restrict__ bias,
                        const float* __restrict__ coeff,
                        const float* __restrict__ ebias, int ebld,
                        int act)
{
    int idx = blockIdx.x * blockDim.x + threadIdx.x;
    if (idx >= B_ * Nout) return;
    int m = idx / Nout, n = idx % Nout;
    float v = 0.f;
    for (int s = 0; s < S; s++) v += part[(size_t)s * B_ * ldp + (size_t)m * ldp + n];
    if (bias) v += bias[n];
    if (ebias) {
        const float* cf = coeff + m * E_;
        float bm = 0.f;
        #pragma unroll
        for (int e = 0; e < E_; e++) bm = fmaf(cf[e], ebias[e * ebld + n], bm);
        v += bm;
    }
    if (act) v = elu1(v);
    C[(size_t)m * ldc + n] = v;
}

// combine that writes ELU(h) as bf16 hi/lo into encB's h slot (cols 267..522)
__global__ void combine_h(const float* __restrict__ part, int S,
                          __nv_bfloat16* __restrict__ Ch, __nv_bfloat16* __restrict__ Cl,
                          const float* __restrict__ bias)
{
    int idx = blockIdx.x * blockDim.x + threadIdx.x;
    if (idx >= B_ * H_) return;
    int m = idx / H_, n = idx % H_;
    float v = bias[n];
    for (int s = 0; s < S; s++) v += part[(size_t)s * B_ * 256 + (size_t)m * 256 + n];
    v = elu1(v);
    __nv_bfloat16 h, l;
    split_bf16(v, h, l);
    size_t dst = (size_t)m * KP_ENC + 267 + n;
    Ch[dst] = h;
    Cl[dst] = l;
}

// ---------------- host launch ----------------
static inline void* sym(const void* s) { void* p = nullptr; cudaGetSymbolAddress(&p, s); return p; }

extern "C" void kernel_launch(void* const* d_in, const int* in_sizes, int n_in,
                              void* d_out, int out_size) {
    (void)in_sizes; (void)n_in; (void)out_size;
    const float* x     = (const float*)d_in[0];
    const float* c     = (const float*)d_in[1];
    const float* fc1_w = (const float*)d_in[2];
    const float* fc1_b = (const float*)d_in[3];
    const float* fc2_w = (const float*)d_in[4];
    const float* fc2_b = (const float*)d_in[5];
    const float* mu_w  = (const float*)d_in[6];
    const float* mu_b  = (const float*)d_in[7];
    const float* lv_w  = (const float*)d_in[8];
    const float* lv_b  = (const float*)d_in[9];
    const float* g0_w  = (const float*)d_in[10];
    const float* g0_b  = (const float*)d_in[11];
    const float* g1_w  = (const float*)d_in[12];
    const float* g1_b  = (const float*)d_in[13];
    const float* g2_w  = (const float*)d_in[14];
    const float* g2_b  = (const float*)d_in[15];
    const float* w0    = (const float*)d_in[16];
    const float* b0    = (const float*)d_in[17];
    const float* w1    = (const float*)d_in[18];
    const float* b1    = (const float*)d_in[19];
    const float* w2    = (const float*)d_in[20];
    const float* b2    = (const float*)d_in[21];

    float* out       = (float*)d_out;
    float* out_layer = out;
    float* out_mu    = out + B_ * F_;
    float* out_lv    = out + B_ * F_ + B_ * L_;

    __nv_bfloat16* eAh = (__nv_bfloat16*)sym(g_encAh);
    __nv_bfloat16* eAl = (__nv_bfloat16*)sym(g_encAl);
    __nv_bfloat16* eBh = (__nv_bfloat16*)sym(g_encBh);
    __nv_bfloat16* eBl = (__nv_bfloat16*)sym(g_encBl);
    float* z     = (float*)sym(g_z);
    float* zc    = (float*)sym(g_zc);
    float* g0o   = (float*)sym(g_g0o);
    float* g1o   = (float*)sym(g_g1o);
    float* coef  = (float*)sym(g_coef);
    float* d0    = (float*)sym(g_d0);
    float* d1    = (float*)sym(g_d1);
    float* part  = (float*)sym(g_part);
    float* bmulv = (float*)sym(g_bmulv);
    float* wg0   = (float*)sym(g_wg0);
    float* wg1   = (float*)sym(g_wg1);
    __nv_bfloat16* we1h = (__nv_bfloat16*)sym(g_wte1h);
    __nv_bfloat16* we1l = (__nv_bfloat16*)sym(g_wte1l);
    __nv_bfloat16* we2h = (__nv_bfloat16*)sym(g_wte2h);
    __nv_bfloat16* we2l = (__nv_bfloat16*)sym(g_wte2l);
    __nv_bfloat16* wmvh = (__nv_bfloat16*)sym(g_wtmvh);
    __nv_bfloat16* wmvl = (__nv_bfloat16*)sym(g_wtmvl);
    __nv_bfloat16* wt0h = (__nv_bfloat16*)sym(g_wt0h);
    __nv_bfloat16* wt0l = (__nv_bfloat16*)sym(g_wt0l);
    __nv_bfloat16* wt1h = (__nv_bfloat16*)sym(g_wt1h);
    __nv_bfloat16* wt1l = (__nv_bfloat16*)sym(g_wt1l);
    __nv_bfloat16* wt2h = (__nv_bfloat16*)sym(g_wt2h);
    __nv_bfloat16* wt2l = (__nv_bfloat16*)sym(g_wt2l);

    cudaFuncSetAttribute(tgemm<0>, cudaFuncAttributeMaxDynamicSharedMemorySize, TSM_TOTAL);
    cudaFuncSetAttribute(tgemm<1>, cudaFuncAttributeMaxDynamicSharedMemorySize, TSM_TOTAL);
    cudaFuncSetAttribute(tgemm<2>, cudaFuncAttributeMaxDynamicSharedMemorySize, TSM_TOTAL);

    const int T = 256;
    auto gr = [](int n) { return (n + 255) / 256; };

    pack_all<<<gr(PKTOT), T>>>(mu_b, lv_b, g0_w, g1_w, bmulv, wg0, wg1);
    tpack<<<gr(WTE1_SZ + WTE2_SZ + WTMV_SZ + WT0_SZ + WT1_SZ + WT2_SZ), T>>>(
        fc1_w, fc2_w, mu_w, lv_w, w0, w1, w2,
        we1h, we1l, we2h, we2l, wmvh, wmvl, wt0h, wt0l, wt1h, wt1l, wt2h, wt2l);
    prep_inputs<<<gr(PR0 + PR1 + PR2), T>>>(x, c, eAh, eAl, eBh, eBl, zc);

    // ---- encoder fc1 (tensor, split-K 5, grid 320); h1 -> encB bf16 hi/lo ----
    tgemm<0><<<dim3(4, 16, 5), T, TSM_TOTAL>>>(nullptr, KP_ENC, eAh, eAl, nullptr, nullptr,
                                               we1h, we1l, part, 256, (long)B_ * 256, KT_ENC, 2, KT_ENC);
    combine_h<<<gr(B_ * H_), T>>>(part, 5, eBh, eBl, fc1_b);

    // ---- encoder fc2 (tensor, split-K 5); h2 overwrites the slot ----
    tgemm<0><<<dim3(4, 16, 5), T, TSM_TOTAL>>>(nullptr, KP_ENC, eBh, eBl, nullptr, nullptr,
                                               we2h, we2l, part, 256, (long)B_ * 256, KT_ENC, 2, KT_ENC);
    combine_h<<<gr(B_ * H_), T>>>(part, 5, eBh, eBl, fc2_b);

    // ---- mu/lv (tensor, split-K 9) + fused z sampling ----
    tgemm<0><<<dim3(1, 16, 9), T, TSM_TOTAL>>>(nullptr, KP_ENC, eBh, eBl, nullptr, nullptr,
                                               wmvh, wmvl, part, 64, (long)B_ * 64, KT_ENC, 1, KT_ENC);
    combine_zeps<<<gr(B_ * L_), T>>>(part, 9, bmulv, z, zc, out_mu, out_lv);

    // ---- gate (FFMA, tiny) ----
    gemm3<<<dim3(1, 16, 4), T>>>(zc, KP_ZC, wg0, G_,
                                 part, G_, (long)B_ * G_, G_, 19, 5, nullptr, 0);
    combine<<<gr(B_ * G_), T>>>(part, 4, G_, g0o, G_, G_, g0_b, nullptr, nullptr, 0, 1);
    gemm3<<<dim3(1, 16, 1), T>>>(g0o, G_, wg1, G_,
                                 g1o, G_, 0, G_, 4, 4, g1_b, 1);
    gate_final<<<gr(B_ * 32), T>>>(g1o, g2_w, g2_b, coef);

    // ---- decoder: mma.sync bf16 hi/lo, split-K 8 ----
    tgemm<1><<<dim3(NT_L01, 16, 8), T, TSM_TOTAL>>>(zc, 0, nullptr, nullptr, nullptr, coef,
                                                    wt0h, wt0l, part, 256, (long)B_ * 256, KT_L0, 5, KT_L0);
    combine<<<gr(B_ * H_), T>>>(part, 8, 256, d0, H_, H_, nullptr, coef, b0, 256, 1);

    tgemm<2><<<dim3(NT_L01, 16, 8), T, TSM_TOTAL>>>(d0, 0, nullptr, nullptr, z, coef,
                                                    wt1h, wt1l, part, 256, (long)B_ * 256, KT_L12, 5, KT_L12);
    combine<<<gr(B_ * H_), T>>>(part, 8, 256, d1, H_, H_, nullptr, coef, b1, 256, 1);

    tgemm<2><<<dim3(NT_L2, 16, 8), T, TSM_TOTAL>>>(d1, 0, nullptr, nullptr, z, coef,
                                                   wt2h, wt2l, part, NP_W2, (long)B_ * NP_W2, KT_L12, 5, KT_L12);
    combine<<<gr(B_ * 267), T>>>(part, 8, NP_W2, out_layer, 267, 267, nullptr, coef, b2, 267, 0);
}

// round 12
// speedup vs baseline: 3.6244x; 1.0318x over previous
#include <cuda_runtime.h>
#include <cuda_bf16.h>
#include <cstdint>

// ---------------- problem dims ----------------
#define B_   2048
#define F_   267
#define L_   32
#define H_   256
#define E_   8
#define G_   64

#define KP_ENC 576            // encoder K pad (9 chunks of 64)
#define KP_ZC  304            // 299 -> 304
#define IN1_   288            // 32 + 256
#define NP_W2  320            // 267 -> 320

#define SPLIT_MAX 9

// tensor-path tiling (k-chunks of 64)
#define KT_ENC 9
#define KT_L0 38
#define KT_L12 36
#define NT_L01 4
#define NT_L2 5
#define WTE1_SZ (4*KT_ENC*4096)
#define WTE2_SZ (4*KT_ENC*4096)
#define WTMV_SZ (1*KT_ENC*4096)
#define WT0_SZ (NT_L01*KT_L0*4096)
#define WT1_SZ (NT_L01*KT_L12*4096)
#define WT2_SZ (NT_L2*KT_L12*4096)

// ---------------- device scratch ----------------
__device__ __align__(16) __nv_bfloat16 g_encAh[B_*KP_ENC];
__device__ __align__(16) __nv_bfloat16 g_encAl[B_*KP_ENC];
__device__ __align__(16) __nv_bfloat16 g_encBh[B_*KP_ENC];
__device__ __align__(16) __nv_bfloat16 g_encBl[B_*KP_ENC];
__device__ __align__(16) float g_z    [B_*L_];
__device__ __align__(16) float g_zc   [B_*KP_ZC];
__device__ __align__(16) float g_g0o  [B_*G_];
__device__ __align__(16) float g_g1o  [B_*G_];
__device__ __align__(16) float g_coef [B_*E_];
__device__ __align__(16) float g_d0   [B_*H_];
__device__ __align__(16) float g_d1   [B_*H_];
__device__ __align__(16) float g_part [SPLIT_MAX*B_*NP_W2];
// FFMA-path weights (gate only)
__device__ __align__(16) float g_bmulv[64];
__device__ __align__(16) float g_wg0  [KP_ZC*G_];
__device__ __align__(16) float g_wg1  [G_*G_];
// tensor-path weights: bf16 hi/lo, tiles [ntile][ktile][64n][64k]
__device__ __align__(16) __nv_bfloat16 g_wte1h[WTE1_SZ];
__device__ __align__(16) __nv_bfloat16 g_wte1l[WTE1_SZ];
__device__ __align__(16) __nv_bfloat16 g_wte2h[WTE2_SZ];
__device__ __align__(16) __nv_bfloat16 g_wte2l[WTE2_SZ];
__device__ __align__(16) __nv_bfloat16 g_wtmvh[WTMV_SZ];
__device__ __align__(16) __nv_bfloat16 g_wtmvl[WTMV_SZ];
__device__ __align__(16) __nv_bfloat16 g_wt0h[WT0_SZ];
__device__ __align__(16) __nv_bfloat16 g_wt0l[WT0_SZ];
__device__ __align__(16) __nv_bfloat16 g_wt1h[WT1_SZ];
__device__ __align__(16) __nv_bfloat16 g_wt1l[WT1_SZ];
__device__ __align__(16) __nv_bfloat16 g_wt2h[WT2_SZ];
__device__ __align__(16) __nv_bfloat16 g_wt2l[WT2_SZ];

__device__ __forceinline__ float elu1(float v) { return v > 0.f ? v : expm1f(v); }
__device__ __forceinline__ void split_bf16(float v, __nv_bfloat16& h, __nv_bfloat16& l) {
    h = __float2bfloat16(v);
    l = __float2bfloat16(v - __bfloat162float(h));
}

// ---------------- f32x2 helpers (FFMA gate path) ----------------
__device__ __forceinline__ unsigned long long ff2(unsigned long long a,
                                                  unsigned long long b,
                                                  unsigned long long c) {
    unsigned long long d;
    asm("fma.rn.f32x2 %0, %1, %2, %3;" : "=l"(d) : "l"(a), "l"(b), "l"(c));
    return d;
}
__device__ __forceinline__ unsigned long long dup2(float x) {
    unsigned long long d;
    asm("mov.b64 %0, {%1, %1};" : "=l"(d) : "f"(x));
    return d;
}

// ---------------- mma.sync + cp.async helpers ----------------
__device__ __forceinline__ uint32_t smem_u32(const void* p) {
    uint32_t a;
    asm("{ .reg .u64 t; cvta.to.shared.u64 t, %1; cvt.u32.u64 %0, t; }" : "=r"(a) : "l"(p));
    return a;
}
__device__ __forceinline__ void ldsm_x4(uint32_t* r, uint32_t addr) {
    asm volatile("ldmatrix.sync.aligned.m8n8.x4.shared.b16 {%0,%1,%2,%3}, [%4];"
                 : "=r"(r[0]), "=r"(r[1]), "=r"(r[2]), "=r"(r[3]) : "r"(addr));
}
__device__ __forceinline__ void mma16816(float* c, const uint32_t* a, const uint32_t* b) {
    asm volatile("mma.sync.aligned.m16n8k16.row.col.f32.bf16.bf16.f32 "
                 "{%0,%1,%2,%3}, {%4,%5,%6,%7}, {%8,%9}, {%0,%1,%2,%3};"
                 : "+f"(c[0]), "+f"(c[1]), "+f"(c[2]), "+f"(c[3])
                 : "r"(a[0]), "r"(a[1]), "r"(a[2]), "r"(a[3]), "r"(b[0]), "r"(b[1]));
}
__device__ __forceinline__ void cp16(uint32_t smem_dst, const void* gsrc) {
    asm volatile("cp.async.cg.shared.global [%0], [%1], 16;" :: "r"(smem_dst), "l"(gsrc));
}
#define CP_COMMIT() asm volatile("cp.async.commit_group;" ::: "memory")
#define CP_WAIT0()  asm volatile("cp.async.wait_group 0;" ::: "memory")

// ---------------- small pack (gate weights + mulv bias) ----------------
#define PK3 64
#define PK4 (KP_ZC*G_)
#define PK5 (G_*G_)
#define PKTOT (PK3+PK4+PK5)

__global__ void pack_all(const float* __restrict__ mu_b, const float* __restrict__ lv_b,
                         const float* __restrict__ g0_w, const float* __restrict__ g1_w,
                         float* __restrict__ bmulv, float* __restrict__ wg0,
                         float* __restrict__ wg1) {
    int idx = blockIdx.x * blockDim.x + threadIdx.x;
    if (idx >= PKTOT) return;
    if (idx < PK3) {
        bmulv[idx] = (idx < 32) ? mu_b[idx] : lv_b[idx - 32];
        return;
    } idx -= PK3;
    if (idx < PK4) {
        int k = idx / G_, n = idx % G_;
        wg0[idx] = (k < 299) ? g0_w[n * 299 + k] : 0.f;
        return;
    } idx -= PK4;
    {
        int k = idx / G_, n = idx % G_;
        wg1[idx] = g1_w[n * G_ + k];
    }
}

// ---------------- tensor weight pack ----------------
__global__ void tpack(const float* __restrict__ fc1_w, const float* __restrict__ fc2_w,
                      const float* __restrict__ mu_w, const float* __restrict__ lv_w,
                      const float* __restrict__ w0, const float* __restrict__ w1,
                      const float* __restrict__ w2,
                      __nv_bfloat16* __restrict__ we1h, __nv_bfloat16* __restrict__ we1l,
                      __nv_bfloat16* __restrict__ we2h, __nv_bfloat16* __restrict__ we2l,
                      __nv_bfloat16* __restrict__ wmvh, __nv_bfloat16* __restrict__ wmvl,
                      __nv_bfloat16* __restrict__ wt0h, __nv_bfloat16* __restrict__ wt0l,
                      __nv_bfloat16* __restrict__ wt1h, __nv_bfloat16* __restrict__ wt1l,
                      __nv_bfloat16* __restrict__ wt2h, __nv_bfloat16* __restrict__ wt2l) {
    int idx = blockIdx.x * blockDim.x + threadIdx.x;
    int layer, KT;
    __nv_bfloat16 *dh, *dl;
    if (idx < WTE1_SZ) { layer = 0; KT = KT_ENC; dh = we1h; dl = we1l; }
    else if (idx < WTE1_SZ + WTE2_SZ) { idx -= WTE1_SZ; layer = 1; KT = KT_ENC; dh = we2h; dl = we2l; }
    else if (idx < WTE1_SZ + WTE2_SZ + WTMV_SZ) { idx -= WTE1_SZ + WTE2_SZ; layer = 2; KT = KT_ENC; dh = wmvh; dl = wmvl; }
    else if (idx < WTE1_SZ + WTE2_SZ + WTMV_SZ + WT0_SZ) { idx -= WTE1_SZ + WTE2_SZ + WTMV_SZ; layer = 3; KT = KT_L0; dh = wt0h; dl = wt0l; }
    else if (idx < WTE1_SZ + WTE2_SZ + WTMV_SZ + WT0_SZ + WT1_SZ) { idx -= WTE1_SZ + WTE2_SZ + WTMV_SZ + WT0_SZ; layer = 4; KT = KT_L12; dh = wt1h; dl = wt1l; }
    else if (idx < WTE1_SZ + WTE2_SZ + WTMV_SZ + WT0_SZ + WT1_SZ + WT2_SZ) { idx -= WTE1_SZ + WTE2_SZ + WTMV_SZ + WT0_SZ + WT1_SZ; layer = 5; KT = KT_L12; dh = wt2h; dl = wt2l; }
    else return;
    int tile = idx >> 12, u = idx & 4095;
    int ntile = tile / KT, kt = tile % KT;
    int nrow = u >> 6, kc = u & 63;
    int n = ntile * 64 + nrow;
    int kg = kt * 64 + kc;
    float w = 0.f;
    if (layer == 0) {
        if (kg < 534) w = fc1_w[(size_t)n * 534 + kg];
    } else if (layer == 1) {
        if (kg < 523) w = fc2_w[(size_t)n * 523 + kg];
    } else if (layer == 2) {
        if (kg < 523) w = (n < 32) ? mu_w[(size_t)n * 523 + kg]
                                   : lv_w[(size_t)(n - 32) * 523 + kg];
    } else if (layer == 3) {
        int e = kg / KP_ZC, i = kg - e * KP_ZC;
        if (i < 299) w = w0[((size_t)(e * 299 + i)) * 256 + n];
    } else if (layer == 4) {
        w = w1[(size_t)kg * 256 + n];
    } else {
        if (n < 267) w = w2[(size_t)kg * 267 + n];
    }
    __nv_bfloat16 hi, lo;
    split_bf16(w, hi, lo);
    size_t dst = ((size_t)tile << 12) + u;
    dh[dst] = hi;
    dl[dst] = lo;
}

// ---------------- fused input-prep kernel ----------------
#define PR0 (B_*KP_ENC)
#define PR1 (B_*320)
#define PR2 (B_*272)
__global__ void prep_inputs(const float* __restrict__ x, const float* __restrict__ c,
                            __nv_bfloat16* __restrict__ eAh, __nv_bfloat16* __restrict__ eAl,
                            __nv_bfloat16* __restrict__ eBh, __nv_bfloat16* __restrict__ eBl,
                            float* __restrict__ zc) {
    int idx = blockIdx.x * blockDim.x + threadIdx.x;
    if (idx < PR0) {
        int b = idx / KP_ENC, k = idx % KP_ENC;
        float v = 0.f;
        if (k < 267)      v = x[b * 267 + k];
        else if (k < 534) v = c[b * 267 + (k - 267)];
        __nv_bfloat16 h, l;
        split_bf16(v, h, l);
        eAh[idx] = h;
        eAl[idx] = l;
        return;
    } idx -= PR0;
    if (idx < PR1) {
        int b = idx / 320, j = idx % 320;
        int k = (j < 267) ? j : (523 + (j - 267));
        float v = (j < 267) ? x[b * 267 + j] : 0.f;
        __nv_bfloat16 h, l;
        split_bf16(v, h, l);
        eBh[b * KP_ENC + k] = h;
        eBl[b * KP_ENC + k] = l;
        return;
    } idx -= PR1;
    if (idx < PR2) {
        int b = idx / 272, k = 32 + idx % 272;
        zc[b * KP_ZC + k] = (k < 299) ? c[b * 267 + (k - 32)] : 0.f;
    }
}

// ---------------- threefry (partitionable) + XLA erfinv ----------------
__device__ __forceinline__ uint32_t rotl32(uint32_t v, int d) { return (v << d) | (v >> (32 - d)); }
__device__ __forceinline__ void tf4(uint32_t& x0, uint32_t& x1, int r0, int r1, int r2, int r3) {
    x0 += x1; x1 = rotl32(x1, r0); x1 ^= x0;
    x0 += x1; x1 = rotl32(x1, r1); x1 ^= x0;
    x0 += x1; x1 = rotl32(x1, r2); x1 ^= x0;
    x0 += x1; x1 = rotl32(x1, r3); x1 ^= x0;
}
__device__ __forceinline__ void threefry2x32(uint32_t k0, uint32_t k1, uint32_t& x0, uint32_t& x1) {
    uint32_t k2 = k0 ^ k1 ^ 0x1BD11BDAu;
    x0 += k0; x1 += k1;
    tf4(x0, x1, 13, 15, 26, 6);  x0 += k1; x1 += k2 + 1u;
    tf4(x0, x1, 17, 29, 16, 24); x0 += k2; x1 += k0 + 2u;
    tf4(x0, x1, 13, 15, 26, 6);  x0 += k0; x1 += k1 + 3u;
    tf4(x0, x1, 17, 29, 16, 24); x0 += k1; x1 += k2 + 4u;
    tf4(x0, x1, 13, 15, 26, 6);  x0 += k2; x1 += k0 + 5u;
}
__device__ __forceinline__ float erfinv_xla(float x) {
    float w = -log1pf(-x * x);
    float p;
    if (w < 5.0f) {
        w -= 2.5f;
        p = 2.81022636e-08f;
        p = fmaf(p, w, 3.43273939e-07f);
        p = fmaf(p, w, -3.5233877e-06f);
        p = fmaf(p, w, -4.39150654e-06f);
        p = fmaf(p, w, 0.00021858087f);
        p = fmaf(p, w, -0.00125372503f);
        p = fmaf(p, w, -0.00417768164f);
        p = fmaf(p, w, 0.246640727f);
        p = fmaf(p, w, 1.50140941f);
    } else {
        w = sqrtf(w) - 3.0f;
        p = -0.000200214257f;
        p = fmaf(p, w, 0.000100950558f);
        p = fmaf(p, w, 0.00134934322f);
        p = fmaf(p, w, -0.00367342844f);
        p = fmaf(p, w, 0.00573950773f);
        p = fmaf(p, w, -0.0076224613f);
        p = fmaf(p, w, 0.00943887047f);
        p = fmaf(p, w, 1.00167406f);
        p = fmaf(p, w, 2.83297682f);
    }
    return p * x;
}

__global__ void combine_zeps(const float* __restrict__ part, int S,
                             const float* __restrict__ bmulv,
                             float* __restrict__ zout, float* __restrict__ zc,
                             float* __restrict__ out_mu, float* __restrict__ out_lv) {
    int i = blockIdx.x * blockDim.x + threadIdx.x;
    if (i >= B_ * L_) return;
    int b = i >> 5, l = i & 31;
    float mu = bmulv[l], lv = bmulv[32 + l];
    for (int s = 0; s < S; s++) {
        const float* p = part + (size_t)s * B_ * 64 + (size_t)b * 64;
        mu += p[l];
        lv += p[32 + l];
    }
    uint32_t x0 = 0u, x1 = (uint32_t)i;
    threefry2x32(0u, 42u, x0, x1);
    uint32_t bits = x0 ^ x1;
    float f = __uint_as_float((bits >> 9) | 0x3f800000u) - 1.0f;
    const float lo = -0.99999994f;
    float u = fmaxf(lo, fmaf(f, 2.0f, lo));
    float eps = 1.41421354f * erfinv_xla(u);
    float zv = fmaf(eps, expf(0.5f * lv), mu);
    zout[i] = zv;
    zc[b * KP_ZC + l] = zv;
    out_mu[i] = mu;
    out_lv[i] = lv;
}

// ---------------- gate final ----------------
__global__ void gate_final(const float* __restrict__ g1o, const float* __restrict__ g2w,
                           const float* __restrict__ g2b, float* __restrict__ coeff) {
    int gtid = blockIdx.x * blockDim.x + threadIdx.x;
    int row = gtid >> 5, lane = gtid & 31;
    if (row >= B_) return;
    float logit = 0.f;
    if (lane < E_) {
        logit = g2b[lane];
        const float* r = g1o + row * G_;
        const float* w = g2w + lane * G_;
        #pragma unroll 8
        for (int k = 0; k < G_; k++) logit = fmaf(r[k], w[k], logit);
    }
    float m = logit;
    for (int d = 4; d > 0; d >>= 1) m = fmaxf(m, __shfl_xor_sync(0xffffffffu, m, d));
    float ex = (lane < E_) ? expf(logit - m) : 0.f;
    float s = ex;
    for (int d = 4; d > 0; d >>= 1) s += __shfl_xor_sync(0xffffffffu, s, d);
    if (lane < E_) coeff[row * E_ + lane] = ex / s;
}

// ---------------- FFMA GEMM (gate only) ----------------
__global__ void __launch_bounds__(256) gemm3(
    const float* __restrict__ A, int lda,
    const float* __restrict__ W, int ldw,
    float* __restrict__ C, int ldc, long sliceStride, int Nout,
    int ktTot, int ktPer,
    const float* __restrict__ bias, int act)
{
    __shared__ __align__(16) float As[2][16][132];
    __shared__ __align__(16) float Bs[2][16][68];

    int tid = threadIdx.x;
    int m0 = blockIdx.y * 128;
    int n0 = blockIdx.x * 64;
    int kt0 = blockIdx.z * ktPer;
    int ktn = min(ktPer, ktTot - kt0);
    float* Cp = C + (long)blockIdx.z * sliceStride;

    int tx = tid & 15, ty = tid >> 4;
    int arow = tid >> 2, acol = (tid & 3) << 2;
    int brow = tid >> 4, bcol = (tid & 15) << 2;

    const float* Wp = W + (size_t)brow * ldw + n0 + bcol;
    int am0 = m0 + arow, am1 = m0 + arow + 64;

    unsigned long long acc[4][4];
    #pragma unroll
    for (int q = 0; q < 4; q++)
        #pragma unroll
        for (int j = 0; j < 4; j++) acc[q][j] = 0ull;

    float4 av0 = *(const float4*)(A + (size_t)am0 * lda + (kt0 << 4) + acol);
    float4 av1 = *(const float4*)(A + (size_t)am1 * lda + (kt0 << 4) + acol);
    float4 bv  = *(const float4*)(Wp + (size_t)(kt0 << 4) * ldw);

    As[0][acol + 0][arow] = av0.x;
    As[0][acol + 1][arow] = av0.y;
    As[0][acol + 2][arow] = av0.z;
    As[0][acol + 3][arow] = av0.w;
    As[0][acol + 0][arow + 64] = av1.x;
    As[0][acol + 1][arow + 64] = av1.y;
    As[0][acol + 2][arow + 64] = av1.z;
    As[0][acol + 3][arow + 64] = av1.w;
    *(float4*)&Bs[0][brow][bcol] = bv;
    __syncthreads();

    for (int t = 0; t < ktn; t++) {
        int buf = t & 1;
        bool more = (t + 1) < ktn;
        if (more) {
            int kk = (kt0 + t + 1) << 4;
            av0 = *(const float4*)(A + (size_t)am0 * lda + kk + acol);
            av1 = *(const float4*)(A + (size_t)am1 * lda + kk + acol);
            bv  = *(const float4*)(Wp + (size_t)kk * ldw);
        }
        #pragma unroll
        for (int k = 0; k < 16; k++) {
            ulonglong2 a01 = *(const ulonglong2*)&As[buf][k][ty << 3];
            ulonglong2 a23 = *(const ulonglong2*)&As[buf][k][(ty << 3) + 4];
            float4 b4 = *(const float4*)&Bs[buf][k][tx << 2];
            unsigned long long bd0 = dup2(b4.x);
            unsigned long long bd1 = dup2(b4.y);
            unsigned long long bd2 = dup2(b4.z);
            unsigned long long bd3 = dup2(b4.w);
            acc[0][0] = ff2(a01.x, bd0, acc[0][0]);
            acc[0][1] = ff2(a01.x, bd1, acc[0][1]);
            acc[0][2] = ff2(a01.x, bd2, acc[0][2]);
            acc[0][3] = ff2(a01.x, bd3, acc[0][3]);
            acc[1][0] = ff2(a01.y, bd0, acc[1][0]);
            acc[1][1] = ff2(a01.y, bd1, acc[1][1]);
            acc[1][2] = ff2(a01.y, bd2, acc[1][2]);
            acc[1][3] = ff2(a01.y, bd3, acc[1][3]);
            acc[2][0] = ff2(a23.x, bd0, acc[2][0]);
            acc[2][1] = ff2(a23.x, bd1, acc[2][1]);
            acc[2][2] = ff2(a23.x, bd2, acc[2][2]);
            acc[2][3] = ff2(a23.x, bd3, acc[2][3]);
            acc[3][0] = ff2(a23.y, bd0, acc[3][0]);
            acc[3][1] = ff2(a23.y, bd1, acc[3][1]);
            acc[3][2] = ff2(a23.y, bd2, acc[3][2]);
            acc[3][3] = ff2(a23.y, bd3, acc[3][3]);
        }
        if (more) {
            int nb = buf ^ 1;
            As[nb][acol + 0][arow] = av0.x;
            As[nb][acol + 1][arow] = av0.y;
            As[nb][acol + 2][arow] = av0.z;
            As[nb][acol + 3][arow] = av0.w;
            As[nb][acol + 0][arow + 64] = av1.x;
            As[nb][acol + 1][arow + 64] = av1.y;
            As[nb][acol + 2][arow + 64] = av1.z;
            As[nb][acol + 3][arow + 64] = av1.w;
            *(float4*)&Bs[nb][brow][bcol] = bv;
        }
        __syncthreads();
    }

    float cres[8][4];
    #pragma unroll
    for (int q = 0; q < 4; q++)
        #pragma unroll
        for (int j = 0; j < 4; j++) {
            float lo, hi;
            asm("mov.b64 {%0, %1}, %2;" : "=f"(lo), "=f"(hi) : "l"(acc[q][j]));
            cres[2 * q][j] = lo;
            cres[2 * q + 1][j] = hi;
        }

    int n = n0 + (tx << 2);
    float4 bsv = make_float4(0.f, 0.f, 0.f, 0.f);
    if (bias) bsv = *(const float4*)(bias + n);
    #pragma unroll
    for (int r = 0; r < 8; r++) {
        int m = m0 + (ty << 3) + r;
        float4 v;
        v.x = cres[r][0] + bsv.x;
        v.y = cres[r][1] + bsv.y;
        v.z = cres[r][2] + bsv.z;
        v.w = cres[r][3] + bsv.w;
        if (act) { v.x = elu1(v.x); v.y = elu1(v.y); v.z = elu1(v.z); v.w = elu1(v.w); }
        if (n < Nout) *(float4*)(Cp + (size_t)m * ldc + n) = v;
    }
}

// ---------------- mma.sync GEMM with cp.async fills ----------------
#define LDS_AB 144
#define TS_A 18432
#define TS_B 9216
#define TSTAGE (2*TS_A + 2*TS_B)      // 55296
#define TSM_TOTAL (2*TSTAGE)          // 110592

template <int MODE>
__global__ void __launch_bounds__(256) tgemm(
    const float* __restrict__ src, int lda,
    const __nv_bfloat16* __restrict__ ah, const __nv_bfloat16* __restrict__ al,
    const float* __restrict__ z,
    const float* __restrict__ coeff,
    const __nv_bfloat16* __restrict__ wth,
    const __nv_bfloat16* __restrict__ wtl,
    float* __restrict__ C, int ldc, long sliceStride,
    int ktTot, int ktPer, int KT)
{
    extern __shared__ __align__(16) char smem[];
    uint32_t sb = smem_u32(smem);
    int tid = threadIdx.x;
    int wid = tid >> 5, lane = tid & 31;
    int wm = wid >> 1, wn = wid & 1;
    int m0 = blockIdx.y * 128;
    int ntile = blockIdx.x, n0 = ntile * 64;
    int kt0 = blockIdx.z * ktPer;
    int ktn = min(ktPer, ktTot - kt0);
    float* Cp = C + (long)blockIdx.z * sliceStride;

    float acc[2][4][4];
    #pragma unroll
    for (int mt = 0; mt < 2; mt++)
        #pragma unroll
        for (int nt = 0; nt < 4; nt++)
            #pragma unroll
            for (int j = 0; j < 4; j++) acc[mt][nt][j] = 0.f;

    auto fill = [&](int kt, int buf) {
        uint32_t st = sb + buf * TSTAGE;
        if (MODE == 0) {
            // A hi/lo: pure 16B async copies (8 per thread)
            #pragma unroll
            for (int gq = 0; gq < 8; gq++) {
                int g = tid + gq * 256;
                int sel = g >> 10;
                int r = (g >> 3) & 127, seg = g & 7;
                const __nv_bfloat16* srcp = (sel ? al : ah) + (size_t)(m0 + r) * lda + (kt << 6) + (seg << 3);
                cp16(st + sel * TS_A + r * LDS_AB + seg * 16, srcp);
            }
        } else {
            char* stc = smem + buf * TSTAGE;
            #pragma unroll
            for (int gq = 0; gq < 4; gq++) {
                int g = tid + gq * 256;
                int row = g >> 3, c8 = g & 7;
                int m = m0 + row;
                int kg = (kt << 6) + (c8 << 3);
                float4 f0, f1;
                float cf;
                if (MODE == 1) {
                    int e = kg / KP_ZC, i = kg - e * KP_ZC;
                    cf = coeff[m * E_ + e];
                    f0 = *(const float4*)(src + (size_t)m * KP_ZC + i);
                    f1 = *(const float4*)(src + (size_t)m * KP_ZC + i + 4);
                } else {
                    int e = kg / IN1_, i = kg - e * IN1_;
                    cf = coeff[m * E_ + e];
                    if (i < L_) {
                        f0 = *(const float4*)(z + (size_t)m * L_ + i);
                        f1 = *(const float4*)(z + (size_t)m * L_ + i + 4);
                    } else {
                        f0 = *(const float4*)(src + (size_t)m * H_ + (i - L_));
                        f1 = *(const float4*)(src + (size_t)m * H_ + (i - L_) + 4);
                    }
                }
                float v[8] = { cf * f0.x, cf * f0.y, cf * f0.z, cf * f0.w,
                               cf * f1.x, cf * f1.y, cf * f1.z, cf * f1.w };
                union { __nv_bfloat16 b[8]; uint4 u; } hv, lv;
                #pragma unroll
                for (int j = 0; j < 8; j++) split_bf16(v[j], hv.b[j], lv.b[j]);
                *(uint4*)(stc + row * LDS_AB + c8 * 16) = hv.u;
                *(uint4*)(stc + TS_A + row * LDS_AB + c8 * 16) = lv.u;
            }
        }
        const __nv_bfloat16* th = wth + ((size_t)(ntile * KT + kt) << 12);
        const __nv_bfloat16* tl = wtl + ((size_t)(ntile * KT + kt) << 12);
        #pragma unroll
        for (int gq = 0; gq < 2; gq++) {
            int g = tid + gq * 256;
            int n = g >> 3, seg = g & 7;
            cp16(st + 2 * TS_A + n * LDS_AB + seg * 16, th + n * 64 + seg * 8);
            cp16(st + 2 * TS_A + TS_B + n * LDS_AB + seg * 16, tl + n * 64 + seg * 8);
        }
    };

    fill(kt0, 0);
    CP_COMMIT();
    CP_WAIT0();
    __syncthreads();

    for (int t = 0; t < ktn; t++) {
        int buf = t & 1;
        bool more = (t + 1) < ktn;
        if (more) {
            fill(kt0 + t + 1, buf ^ 1);
            CP_COMMIT();
        }

        uint32_t sA = sb + buf * TSTAGE;
        uint32_t sB = sA + 2 * TS_A;
        int arow = wm * 32 + (lane & 15);
        int bn = wn * 32 + ((lane >> 4) << 3) + (lane & 7);
        int bkl = ((lane >> 3) & 1) << 3;
        #pragma unroll
        for (int ks = 0; ks < 4; ks++) {
            uint32_t ah0[4], ah1[4], al0[4], al1[4];
            uint32_t bh0[4], bh1[4], bl0[4], bl1[4];
            uint32_t aAdr = sA + arow * LDS_AB + (ks * 16 + (lane >> 4) * 8) * 2;
            ldsm_x4(ah0, aAdr);
            ldsm_x4(ah1, aAdr + 16 * LDS_AB);
            ldsm_x4(al0, aAdr + TS_A);
            ldsm_x4(al1, aAdr + TS_A + 16 * LDS_AB);
            uint32_t bAdr = sB + bn * LDS_AB + (ks * 16 + bkl) * 2;
            ldsm_x4(bh0, bAdr);
            ldsm_x4(bh1, bAdr + 16 * LDS_AB);
            ldsm_x4(bl0, bAdr + TS_B);
            ldsm_x4(bl1, bAdr + TS_B + 16 * LDS_AB);

            mma16816(acc[0][0], ah0, bh0);     mma16816(acc[0][1], ah0, bh0 + 2);
            mma16816(acc[0][2], ah0, bh1);     mma16816(acc[0][3], ah0, bh1 + 2);
            mma16816(acc[1][0], ah1, bh0);     mma16816(acc[1][1], ah1, bh0 + 2);
            mma16816(acc[1][2], ah1, bh1);     mma16816(acc[1][3], ah1, bh1 + 2);

            mma16816(acc[0][0], ah0, bl0);     mma16816(acc[0][1], ah0, bl0 + 2);
            mma16816(acc[0][2], ah0, bl1);     mma16816(acc[0][3], ah0, bl1 + 2);
            mma16816(acc[1][0], ah1, bl0);     mma16816(acc[1][1], ah1, bl0 + 2);
            mma16816(acc[1][2], ah1, bl1);     mma16816(acc[1][3], ah1, bl1 + 2);

            mma16816(acc[0][0], al0, bh0);     mma16816(acc[0][1], al0, bh0 + 2);
            mma16816(acc[0][2], al0, bh1);     mma16816(acc[0][3], al0, bh1 + 2);
            mma16816(acc[1][0], al1, bh0);     mma16816(acc[1][1], al1, bh0 + 2);
            mma16816(acc[1][2], al1, bh1);     mma16816(acc[1][3], al1, bh1 + 2);
        }
        if (more) CP_WAIT0();
        __syncthreads();
    }

    #pragma unroll
    for (int mt = 0; mt < 2; mt++)
        #pragma unroll
        for (int nt = 0; nt < 4; nt++) {
            int m = m0 + wm * 32 + mt * 16 + (lane >> 2);
            int n = n0 + wn * 32 + nt * 8 + ((lane & 3) << 1);
            *(float2*)(Cp + (size_t)m * ldc + n) = make_float2(acc[mt][nt][0], acc[mt][nt][1]);
            *(float2*)(Cp + (size_t)(m + 8) * ldc + n) = make_float2(acc[mt][nt][2], acc[mt][nt][3]);
        }
}

// ---------------- split-K combines ----------------
__global__ void combine(const float* __restrict__ part, int S, int ldp,
                        float* __restrict__ C, int ldc, int Nout,
                        const float* __restrict__ bias,
                        const float* __restrict__ coeff,
                        const float* __restrict__ ebias, int ebld,
                        int act)
{
    int idx = blockIdx.x * blockDim.x + threadIdx.x;
    if (idx >= B_ * Nout) return;
    int m = idx / Nout, n = idx % Nout;
    float v = 0.f;
    for (int s = 0; s < S; s++) v += part[(size_t)s * B_ * ldp + (size_t)m * ldp + n];
    if (bias) v += bias[n];
    if (ebias) {
        const float* cf = coeff + m * E_;
        float bm = 0.f;
        #pragma unroll
        for (int e = 0; e < E_; e++) bm = fmaf(cf[e], ebias[e * ebld + n], bm);
        v += bm;
    }
    if (act) v = elu1(v);
    C[(size_t)m * ldc + n] = v;
}

__global__ void combine_h(const float* __restrict__ part, int S,
                          __nv_bfloat16* __restrict__ Ch, __nv_bfloat16* __restrict__ Cl,
                          const float* __restrict__ bias)
{
    int idx = blockIdx.x * blockDim.x + threadIdx.x;
    if (idx >= B_ * H_) return;
    int m = idx / H_, n = idx % H_;
    float v = bias[n];
    for (int s = 0; s < S; s++) v += part[(size_t)s * B_ * 256 + (size_t)m * 256 + n];
    v = elu1(v);
    __nv_bfloat16 h, l;
    split_bf16(v, h, l);
    size_t dst = (size_t)m * KP_ENC + 267 + n;
    Ch[dst] = h;
    Cl[dst] = l;
}

// ---------------- host launch ----------------
static inline void* sym(const void* s) { void* p = nullptr; cudaGetSymbolAddress(&p, s); return p; }

extern "C" void kernel_launch(void* const* d_in, const int* in_sizes, int n_in,
                              void* d_out, int out_size) {
    (void)in_sizes; (void)n_in; (void)out_size;
    const float* x     = (const float*)d_in[0];
    const float* c     = (const float*)d_in[1];
    const float* fc1_w = (const float*)d_in[2];
    const float* fc1_b = (const float*)d_in[3];
    const float* fc2_w = (const float*)d_in[4];
    const float* fc2_b = (const float*)d_in[5];
    const float* mu_w  = (const float*)d_in[6];
    const float* mu_b  = (const float*)d_in[7];
    const float* lv_w  = (const float*)d_in[8];
    const float* lv_b  = (const float*)d_in[9];
    const float* g0_w  = (const float*)d_in[10];
    const float* g0_b  = (const float*)d_in[11];
    const float* g1_w  = (const float*)d_in[12];
    const float* g1_b  = (const float*)d_in[13];
    const float* g2_w  = (const float*)d_in[14];
    const float* g2_b  = (const float*)d_in[15];
    const float* w0    = (const float*)d_in[16];
    const float* b0    = (const float*)d_in[17];
    const float* w1    = (const float*)d_in[18];
    const float* b1    = (const float*)d_in[19];
    const float* w2    = (const float*)d_in[20];
    const float* b2    = (const float*)d_in[21];

    float* out       = (float*)d_out;
    float* out_layer = out;
    float* out_mu    = out + B_ * F_;
    float* out_lv    = out + B_ * F_ + B_ * L_;

    __nv_bfloat16* eAh = (__nv_bfloat16*)sym(g_encAh);
    __nv_bfloat16* eAl = (__nv_bfloat16*)sym(g_encAl);
    __nv_bfloat16* eBh = (__nv_bfloat16*)sym(g_encBh);
    __nv_bfloat16* eBl = (__nv_bfloat16*)sym(g_encBl);
    float* z     = (float*)sym(g_z);
    float* zc    = (float*)sym(g_zc);
    float* g0o   = (float*)sym(g_g0o);
    float* g1o   = (float*)sym(g_g1o);
    float* coef  = (float*)sym(g_coef);
    float* d0    = (float*)sym(g_d0);
    float* d1    = (float*)sym(g_d1);
    float* part  = (float*)sym(g_part);
    float* bmulv = (float*)sym(g_bmulv);
    float* wg0   = (float*)sym(g_wg0);
    float* wg1   = (float*)sym(g_wg1);
    __nv_bfloat16* we1h = (__nv_bfloat16*)sym(g_wte1h);
    __nv_bfloat16* we1l = (__nv_bfloat16*)sym(g_wte1l);
    __nv_bfloat16* we2h = (__nv_bfloat16*)sym(g_wte2h);
    __nv_bfloat16* we2l = (__nv_bfloat16*)sym(g_wte2l);
    __nv_bfloat16* wmvh = (__nv_bfloat16*)sym(g_wtmvh);
    __nv_bfloat16* wmvl = (__nv_bfloat16*)sym(g_wtmvl);
    __nv_bfloat16* wt0h = (__nv_bfloat16*)sym(g_wt0h);
    __nv_bfloat16* wt0l = (__nv_bfloat16*)sym(g_wt0l);
    __nv_bfloat16* wt1h = (__nv_bfloat16*)sym(g_wt1h);
    __nv_bfloat16* wt1l = (__nv_bfloat16*)sym(g_wt1l);
    __nv_bfloat16* wt2h = (__nv_bfloat16*)sym(g_wt2h);
    __nv_bfloat16* wt2l = (__nv_bfloat16*)sym(g_wt2l);

    cudaFuncSetAttribute(tgemm<0>, cudaFuncAttributeMaxDynamicSharedMemorySize, TSM_TOTAL);
    cudaFuncSetAttribute(tgemm<1>, cudaFuncAttributeMaxDynamicSharedMemorySize, TSM_TOTAL);
    cudaFuncSetAttribute(tgemm<2>, cudaFuncAttributeMaxDynamicSharedMemorySize, TSM_TOTAL);
    cudaFuncSetAttribute(tgemm<0>, cudaFuncAttributePreferredSharedMemoryCarveout, 100);
    cudaFuncSetAttribute(tgemm<1>, cudaFuncAttributePreferredSharedMemoryCarveout, 100);
    cudaFuncSetAttribute(tgemm<2>, cudaFuncAttributePreferredSharedMemoryCarveout, 100);

    const int T = 256;
    auto gr = [](int n) { return (n + 255) / 256; };

    pack_all<<<gr(PKTOT), T>>>(mu_b, lv_b, g0_w, g1_w, bmulv, wg0, wg1);
    tpack<<<gr(WTE1_SZ + WTE2_SZ + WTMV_SZ + WT0_SZ + WT1_SZ + WT2_SZ), T>>>(
        fc1_w, fc2_w, mu_w, lv_w, w0, w1, w2,
        we1h, we1l, we2h, we2l, wmvh, wmvl, wt0h, wt0l, wt1h, wt1l, wt2h, wt2l);
    prep_inputs<<<gr(PR0 + PR1 + PR2), T>>>(x, c, eAh, eAl, eBh, eBl, zc);

    // ---- encoder fc1 (tensor, split-K 5); h1 -> encB bf16 hi/lo ----
    tgemm<0><<<dim3(4, 16, 5), T, TSM_TOTAL>>>(nullptr, KP_ENC, eAh, eAl, nullptr, nullptr,
                                               we1h, we1l, part, 256, (long)B_ * 256, KT_ENC, 2, KT_ENC);
    combine_h<<<gr(B_ * H_), T>>>(part, 5, eBh, eBl, fc1_b);

    // ---- encoder fc2 (tensor, split-K 5) ----
    tgemm<0><<<dim3(4, 16, 5), T, TSM_TOTAL>>>(nullptr, KP_ENC, eBh, eBl, nullptr, nullptr,
                                               we2h, we2l, part, 256, (long)B_ * 256, KT_ENC, 2, KT_ENC);
    combine_h<<<gr(B_ * H_), T>>>(part, 5, eBh, eBl, fc2_b);

    // ---- mu/lv (tensor, split-K 9) + fused z sampling ----
    tgemm<0><<<dim3(1, 16, 9), T, TSM_TOTAL>>>(nullptr, KP_ENC, eBh, eBl, nullptr, nullptr,
                                               wmvh, wmvl, part, 64, (long)B_ * 64, KT_ENC, 1, KT_ENC);
    combine_zeps<<<gr(B_ * L_), T>>>(part, 9, bmulv, z, zc, out_mu, out_lv);

    // ---- gate (FFMA, tiny) ----
    gemm3<<<dim3(1, 16, 4), T>>>(zc, KP_ZC, wg0, G_,
                                 part, G_, (long)B_ * G_, G_, 19, 5, nullptr, 0);
    combine<<<gr(B_ * G_), T>>>(part, 4, G_, g0o, G_, G_, g0_b, nullptr, nullptr, 0, 1);
    gemm3<<<dim3(1, 16, 1), T>>>(g0o, G_, wg1, G_,
                                 g1o, G_, 0, G_, 4, 4, g1_b, 1);
    gate_final<<<gr(B_ * 32), T>>>(g1o, g2_w, g2_b, coef);

    // ---- decoder: mma.sync bf16 hi/lo, split-K 8 ----
    tgemm<1><<<dim3(NT_L01, 16, 8), T, TSM_TOTAL>>>(zc, 0, nullptr, nullptr, nullptr, coef,
                                                    wt0h, wt0l, part, 256, (long)B_ * 256, KT_L0, 5, KT_L0);
    combine<<<gr(B_ * H_), T>>>(part, 8, 256, d0, H_, H_, nullptr, coef, b0, 256, 1);

    tgemm<2><<<dim3(NT_L01, 16, 8), T, TSM_TOTAL>>>(d0, 0, nullptr, nullptr, z, coef,
                                                    wt1h, wt1l, part, 256, (long)B_ * 256, KT_L12, 5, KT_L12);
    combine<<<gr(B_ * H_), T>>>(part, 8, 256, d1, H_, H_, nullptr, coef, b1, 256, 1);

    tgemm<2><<<dim3(NT_L2, 16, 8), T, TSM_TOTAL>>>(d1, 0, nullptr, nullptr, z, coef,
                                                   wt2h, wt2l, part, NP_W2, (long)B_ * NP_W2, KT_L12, 5, KT_L12);
    combine<<<gr(B_ * 267), T>>>(part, 8, NP_W2, out_layer, 267, 267, nullptr, coef, b2, 267, 0);
}